// round 1
// baseline (speedup 1.0000x reference)
#include <cuda_runtime.h>
#include <math.h>
#include <stdint.h>

// Problem constants
#define BB 2
#define SS 2048
#define HH 2048
#define NH 16
#define NKV 4
#define HD 128
#define GROUPS (NH / NKV)        // 4
#define M_TOT (BB * SS)          // 4096
#define QDIM (NH * HD)           // 2048
#define KVDIM (NKV * HD)         // 512

// Scratch (device globals: no allocations allowed)
__device__ float g_Q[M_TOT * QDIM];    // 33.5 MB
__device__ float g_K[M_TOT * KVDIM];   // 8.4 MB
__device__ float g_V[M_TOT * KVDIM];   // 8.4 MB
__device__ float g_A[M_TOT * QDIM];    // 33.5 MB (attention out, pre-Wo)
__device__ float g_cos[SS * 64];
__device__ float g_sin[SS * 64];

// ---------------------------------------------------------------------------
// Generic NT GEMM tile: Y[m][n] = sum_k X[m][k] * W[n][k]
// X: [*, 2048] row-major (ldx=2048), W: [*, 2048] row-major (ldw=2048)
// BM=BN=128, BK=16, 256 threads, 8x8 per thread.
// ---------------------------------------------------------------------------
__device__ __forceinline__ void gemm_tile_nt(const float* __restrict__ X,
                                             const float* __restrict__ W,
                                             float* __restrict__ Y,
                                             int m0, int n0, int ldy) {
    const int KDIM = 2048;
    __shared__ float As[16][132];
    __shared__ float Bs[16][132];

    int tid = threadIdx.x;
    int ty = tid >> 4;        // 0..15
    int tx = tid & 15;        // 0..15

    float acc[8][8];
#pragma unroll
    for (int i = 0; i < 8; i++)
#pragma unroll
        for (int j = 0; j < 8; j++) acc[i][j] = 0.f;

    for (int k0 = 0; k0 < KDIM; k0 += 16) {
        // Load A and B tiles (transposed into [k][row])
#pragma unroll
        for (int l = 0; l < 2; l++) {
            int idx = tid + l * 256;          // 0..511
            int row = idx >> 2;               // 0..127
            int c4 = (idx & 3) * 4;           // 0,4,8,12
            float4 va = *(const float4*)(X + (size_t)(m0 + row) * KDIM + k0 + c4);
            As[c4 + 0][row] = va.x;
            As[c4 + 1][row] = va.y;
            As[c4 + 2][row] = va.z;
            As[c4 + 3][row] = va.w;
            float4 vb = *(const float4*)(W + (size_t)(n0 + row) * KDIM + k0 + c4);
            Bs[c4 + 0][row] = vb.x;
            Bs[c4 + 1][row] = vb.y;
            Bs[c4 + 2][row] = vb.z;
            Bs[c4 + 3][row] = vb.w;
        }
        __syncthreads();

#pragma unroll
        for (int kk = 0; kk < 16; kk++) {
            float a[8], b[8];
            *(float4*)(a + 0) = *(const float4*)&As[kk][ty * 8 + 0];
            *(float4*)(a + 4) = *(const float4*)&As[kk][ty * 8 + 4];
            *(float4*)(b + 0) = *(const float4*)&Bs[kk][tx * 8 + 0];
            *(float4*)(b + 4) = *(const float4*)&Bs[kk][tx * 8 + 4];
#pragma unroll
            for (int i = 0; i < 8; i++)
#pragma unroll
                for (int j = 0; j < 8; j++) acc[i][j] = fmaf(a[i], b[j], acc[i][j]);
        }
        __syncthreads();
    }

    // Write 8x8 block
#pragma unroll
    for (int i = 0; i < 8; i++) {
        float* yrow = Y + (size_t)(m0 + ty * 8 + i) * ldy + n0 + tx * 8;
        float4 r0 = make_float4(acc[i][0], acc[i][1], acc[i][2], acc[i][3]);
        float4 r1 = make_float4(acc[i][4], acc[i][5], acc[i][6], acc[i][7]);
        *(float4*)(yrow + 0) = r0;
        *(float4*)(yrow + 4) = r1;
    }
}

// Fused QKV projection: grid (24, 32). bx 0..15 -> Q, 16..19 -> K, 20..23 -> V
__global__ __launch_bounds__(256) void qkv_gemm_kernel(const float* __restrict__ X,
                                                       const float* __restrict__ Wq,
                                                       const float* __restrict__ Wk,
                                                       const float* __restrict__ Wv) {
    int bx = blockIdx.x;
    int m0 = blockIdx.y * 128;
    const float* Wp;
    float* Yp;
    int n0, ldy;
    if (bx < 16) {
        Wp = Wq; Yp = g_Q; n0 = bx * 128; ldy = QDIM;
    } else if (bx < 20) {
        Wp = Wk; Yp = g_K; n0 = (bx - 16) * 128; ldy = KVDIM;
    } else {
        Wp = Wv; Yp = g_V; n0 = (bx - 20) * 128; ldy = KVDIM;
    }
    gemm_tile_nt(X, Wp, Yp, m0, n0, ldy);
}

// Output projection: grid (16, 32)
__global__ __launch_bounds__(256) void out_gemm_kernel(const float* __restrict__ Wo,
                                                       float* __restrict__ out) {
    gemm_tile_nt(g_A, Wo, out, blockIdx.y * 128, blockIdx.x * 128, HH);
}

// ---------------------------------------------------------------------------
// RoPE
// ---------------------------------------------------------------------------
__global__ void rope_table_kernel() {
    int idx = blockIdx.x * blockDim.x + threadIdx.x;
    if (idx >= SS * 64) return;
    int pos = idx >> 6;
    int i = idx & 63;
    double inv = pow(10000.0, -(double)i / 64.0);   // theta^{-2i/128}
    double ang = (double)pos * inv;
    double sd, cd;
    sincos(ang, &sd, &cd);
    g_cos[idx] = (float)cd;
    g_sin[idx] = (float)sd;
}

__global__ void rope_apply_kernel() {
    int idx = blockIdx.x * blockDim.x + threadIdx.x;
    const int qcount = M_TOT * NH * 64;
    const int kcount = M_TOT * NKV * 64;
    if (idx >= qcount + kcount) return;

    float* row;
    int pos, i;
    if (idx < qcount) {
        int m = idx / (NH * 64);
        int r = idx - m * (NH * 64);
        int h = r >> 6;
        i = r & 63;
        pos = m & (SS - 1);
        row = g_Q + (size_t)m * QDIM + h * HD;
    } else {
        int e = idx - qcount;
        int m = e / (NKV * 64);
        int r = e - m * (NKV * 64);
        int h = r >> 6;
        i = r & 63;
        pos = m & (SS - 1);
        row = g_K + (size_t)m * KVDIM + h * HD;
    }
    float c = g_cos[pos * 64 + i];
    float s = g_sin[pos * 64 + i];
    float x1 = row[i];
    float x2 = row[i + 64];
    row[i] = x1 * c - x2 * s;
    row[i + 64] = x2 * c + x1 * s;
}

// ---------------------------------------------------------------------------
// SIMT flash attention (causal, online softmax)
// grid (S/64, NH, B), 256 threads
// ---------------------------------------------------------------------------
#define BQ 64
#define BKV 64
#define LDT 132   // row stride for 128-wide tiles (pads, keeps 16B align)
#define LDSS 65   // row stride for 64-wide score tile
#define FLASH_SMEM_FLOATS (3 * 64 * LDT + 64 * LDSS + 3 * 64)

__global__ __launch_bounds__(256) void flash_kernel() {
    extern __shared__ float sm[];
    float* Qs = sm;
    float* Ks = Qs + 64 * LDT;
    float* Vs = Ks + 64 * LDT;
    float* Sc = Vs + 64 * LDT;
    float* m_s = Sc + 64 * LDSS;
    float* l_s = m_s + 64;
    float* corr_s = l_s + 64;

    int qt = blockIdx.x;
    int h = blockIdx.y;
    int b = blockIdx.z;
    int q0 = qt * BQ;
    int kh = h / GROUPS;

    int tid = threadIdx.x;
    int ty = tid >> 4, tx = tid & 15;

    // Load Q tile
    const float* Qg = g_Q + ((size_t)(b * SS + q0)) * QDIM + h * HD;
#pragma unroll
    for (int l = 0; l < 8; l++) {
        int idx = tid + l * 256;
        int r = idx >> 5;
        int c4 = (idx & 31) * 4;
        *(float4*)&Qs[r * LDT + c4] = *(const float4*)(Qg + (size_t)r * QDIM + c4);
    }
    if (tid < 64) { m_s[tid] = -1e30f; l_s[tid] = 0.f; }

    float Oa[4][8];
#pragma unroll
    for (int i = 0; i < 4; i++)
#pragma unroll
        for (int j = 0; j < 8; j++) Oa[i][j] = 0.f;

    const float scale = 0.08838834764831845f;  // 1/sqrt(128)
    int ntiles = q0 / BKV + 1;

    for (int t = 0; t < ntiles; t++) {
        int k0 = t * BKV;
        __syncthreads();  // prev iter done with Ks/Vs/Sc

        const float* Kg = g_K + ((size_t)(b * SS + k0)) * KVDIM + kh * HD;
        const float* Vg = g_V + ((size_t)(b * SS + k0)) * KVDIM + kh * HD;
#pragma unroll
        for (int l = 0; l < 8; l++) {
            int idx = tid + l * 256;
            int r = idx >> 5;
            int c4 = (idx & 31) * 4;
            *(float4*)&Ks[r * LDT + c4] = *(const float4*)(Kg + (size_t)r * KVDIM + c4);
            *(float4*)&Vs[r * LDT + c4] = *(const float4*)(Vg + (size_t)r * KVDIM + c4);
        }
        __syncthreads();

        // Scores: each thread 4x4 (rows ty*4.., cols tx*4..)
        float acc[4][4];
#pragma unroll
        for (int i = 0; i < 4; i++)
#pragma unroll
            for (int j = 0; j < 4; j++) acc[i][j] = 0.f;

        for (int d = 0; d < HD; d += 4) {
            float4 q[4], k[4];
#pragma unroll
            for (int i = 0; i < 4; i++) q[i] = *(const float4*)&Qs[(ty * 4 + i) * LDT + d];
#pragma unroll
            for (int j = 0; j < 4; j++) k[j] = *(const float4*)&Ks[(tx * 4 + j) * LDT + d];
#pragma unroll
            for (int i = 0; i < 4; i++)
#pragma unroll
                for (int j = 0; j < 4; j++) {
                    acc[i][j] = fmaf(q[i].x, k[j].x, acc[i][j]);
                    acc[i][j] = fmaf(q[i].y, k[j].y, acc[i][j]);
                    acc[i][j] = fmaf(q[i].z, k[j].z, acc[i][j]);
                    acc[i][j] = fmaf(q[i].w, k[j].w, acc[i][j]);
                }
        }
        bool diag = (t == ntiles - 1);
#pragma unroll
        for (int i = 0; i < 4; i++)
#pragma unroll
            for (int j = 0; j < 4; j++) {
                float v = acc[i][j] * scale;
                if (diag && (k0 + tx * 4 + j > q0 + ty * 4 + i)) v = -1e30f;
                Sc[(ty * 4 + i) * LDSS + tx * 4 + j] = v;
            }
        __syncthreads();

        // Online softmax stats: 4 threads per row
        {
            int row = tid >> 2, qd = tid & 3;
            int base = qd * 16;
            float mprev = m_s[row];
            float p[16];
            float tmax = -1e30f;
#pragma unroll
            for (int c = 0; c < 16; c++) {
                p[c] = Sc[row * LDSS + base + c];
                tmax = fmaxf(tmax, p[c]);
            }
            tmax = fmaxf(tmax, __shfl_xor_sync(0xffffffffu, tmax, 1));
            tmax = fmaxf(tmax, __shfl_xor_sync(0xffffffffu, tmax, 2));
            float newm = fmaxf(mprev, tmax);
            float lsum = 0.f;
#pragma unroll
            for (int c = 0; c < 16; c++) {
                p[c] = __expf(p[c] - newm);
                Sc[row * LDSS + base + c] = p[c];
                lsum += p[c];
            }
            lsum += __shfl_xor_sync(0xffffffffu, lsum, 1);
            lsum += __shfl_xor_sync(0xffffffffu, lsum, 2);
            if (qd == 0) {
                float corr = __expf(mprev - newm);
                corr_s[row] = corr;
                m_s[row] = newm;
                l_s[row] = l_s[row] * corr + lsum;
            }
        }
        __syncthreads();

        // O update: rows ty*4.., cols tx*8..
        float cf[4];
#pragma unroll
        for (int i = 0; i < 4; i++) cf[i] = corr_s[ty * 4 + i];
#pragma unroll
        for (int i = 0; i < 4; i++)
#pragma unroll
            for (int j = 0; j < 8; j++) Oa[i][j] *= cf[i];

        for (int c = 0; c < BKV; c++) {
            float s0 = Sc[(ty * 4 + 0) * LDSS + c];
            float s1 = Sc[(ty * 4 + 1) * LDSS + c];
            float s2 = Sc[(ty * 4 + 2) * LDSS + c];
            float s3 = Sc[(ty * 4 + 3) * LDSS + c];
            float4 va = *(const float4*)&Vs[c * LDT + tx * 8];
            float4 vb = *(const float4*)&Vs[c * LDT + tx * 8 + 4];
            float vv[8] = {va.x, va.y, va.z, va.w, vb.x, vb.y, vb.z, vb.w};
#pragma unroll
            for (int j = 0; j < 8; j++) {
                Oa[0][j] = fmaf(s0, vv[j], Oa[0][j]);
                Oa[1][j] = fmaf(s1, vv[j], Oa[1][j]);
                Oa[2][j] = fmaf(s2, vv[j], Oa[2][j]);
                Oa[3][j] = fmaf(s3, vv[j], Oa[3][j]);
            }
        }
    }
    __syncthreads();

    // Epilogue: normalize and write to g_A[m][h*128 + d]
#pragma unroll
    for (int i = 0; i < 4; i++) {
        float inv = 1.f / l_s[ty * 4 + i];
        int m = b * SS + q0 + ty * 4 + i;
        float* arow = g_A + (size_t)m * QDIM + h * HD + tx * 8;
        float4 r0 = make_float4(Oa[i][0] * inv, Oa[i][1] * inv, Oa[i][2] * inv, Oa[i][3] * inv);
        float4 r1 = make_float4(Oa[i][4] * inv, Oa[i][5] * inv, Oa[i][6] * inv, Oa[i][7] * inv);
        *(float4*)(arow + 0) = r0;
        *(float4*)(arow + 4) = r1;
    }
}

// ---------------------------------------------------------------------------
extern "C" void kernel_launch(void* const* d_in, const int* in_sizes, int n_in,
                              void* d_out, int out_size) {
    const float* X = (const float*)d_in[0];
    const float* Wq = (const float*)d_in[1];
    const float* Wk = (const float*)d_in[2];
    const float* Wv = (const float*)d_in[3];
    const float* Wo = (const float*)d_in[4];
    float* out = (float*)d_out;

    // 1. QKV projections
    qkv_gemm_kernel<<<dim3(24, 32), 256>>>(X, Wq, Wk, Wv);

    // 2. RoPE
    rope_table_kernel<<<(SS * 64 + 255) / 256, 256>>>();
    {
        int total = M_TOT * (NH + NKV) * 64;
        rope_apply_kernel<<<(total + 255) / 256, 256>>>();
    }

    // 3. Flash attention
    static int smem_set = 0;
    size_t smem_bytes = FLASH_SMEM_FLOATS * sizeof(float);
    cudaFuncSetAttribute(flash_kernel, cudaFuncAttributeMaxDynamicSharedMemorySize,
                         (int)smem_bytes);
    (void)smem_set;
    flash_kernel<<<dim3(SS / BQ, NH, BB), 256, smem_bytes>>>();

    // 4. Output projection
    out_gemm_kernel<<<dim3(16, 32), 256>>>(Wo, out);
}

// round 2
// speedup vs baseline: 1.4217x; 1.4217x over previous
#include <cuda_runtime.h>
#include <cuda_bf16.h>
#include <math.h>
#include <stdint.h>

// Problem constants
#define BB 2
#define SS 2048
#define HH 2048
#define NH 16
#define NKV 4
#define HD 128
#define GROUPS (NH / NKV)        // 4
#define M_TOT (BB * SS)          // 4096
#define QDIM (NH * HD)           // 2048
#define KVDIM (NKV * HD)         // 512
#define KDIM 2048                // GEMM reduction dim (all gemms)

// fp32 scratch
__device__ __align__(16) float g_Q[M_TOT * QDIM];
__device__ __align__(16) float g_K[M_TOT * KVDIM];
__device__ __align__(16) float g_V[M_TOT * KVDIM];
__device__ __align__(16) float g_A[M_TOT * QDIM];
__device__ float g_cos[SS * 64];
__device__ float g_sin[SS * 64];

// bf16 hi/lo split buffers
__device__ __align__(16) __nv_bfloat16 g_Xhi[M_TOT * KDIM], g_Xlo[M_TOT * KDIM];
__device__ __align__(16) __nv_bfloat16 g_Wqhi[QDIM * KDIM], g_Wqlo[QDIM * KDIM];
__device__ __align__(16) __nv_bfloat16 g_Wkhi[KVDIM * KDIM], g_Wklo[KVDIM * KDIM];
__device__ __align__(16) __nv_bfloat16 g_Wvhi[KVDIM * KDIM], g_Wvlo[KVDIM * KDIM];
__device__ __align__(16) __nv_bfloat16 g_Wohi[HH * KDIM], g_Wolo[HH * KDIM];
__device__ __align__(16) __nv_bfloat16 g_Ahi[M_TOT * KDIM], g_Alo[M_TOT * KDIM];

// ---------------------------------------------------------------------------
// Split fp32 -> bf16 hi + bf16 lo
// ---------------------------------------------------------------------------
__device__ __forceinline__ void split4(const float4 v, __nv_bfloat16* hi, __nv_bfloat16* lo) {
    float x[4] = {v.x, v.y, v.z, v.w};
#pragma unroll
    for (int i = 0; i < 4; i++) {
        __nv_bfloat16 h = __float2bfloat16(x[i]);
        float r = x[i] - __bfloat162float(h);
        hi[i] = h;
        lo[i] = __float2bfloat16(r);
    }
}

// Split all 5 inputs in one grid. Indices in float4 units.
#define N4_X  ((M_TOT * KDIM) / 4)     // 2097152
#define N4_WQ ((QDIM * KDIM) / 4)      // 1048576
#define N4_WKV ((KVDIM * KDIM) / 4)    // 262144
#define N4_WO ((HH * KDIM) / 4)        // 1048576
#define N4_TOTAL (N4_X + N4_WQ + 2 * N4_WKV + N4_WO)

__global__ void split_inputs_kernel(const float* __restrict__ X,
                                    const float* __restrict__ Wq,
                                    const float* __restrict__ Wk,
                                    const float* __restrict__ Wv,
                                    const float* __restrict__ Wo) {
    int i = blockIdx.x * blockDim.x + threadIdx.x;
    if (i >= N4_TOTAL) return;
    const float* src;
    __nv_bfloat16 *hi, *lo;
    int off;
    if (i < N4_X) {
        src = X; hi = g_Xhi; lo = g_Xlo; off = i;
    } else if (i < N4_X + N4_WQ) {
        src = Wq; hi = g_Wqhi; lo = g_Wqlo; off = i - N4_X;
    } else if (i < N4_X + N4_WQ + N4_WKV) {
        src = Wk; hi = g_Wkhi; lo = g_Wklo; off = i - N4_X - N4_WQ;
    } else if (i < N4_X + N4_WQ + 2 * N4_WKV) {
        src = Wv; hi = g_Wvhi; lo = g_Wvlo; off = i - N4_X - N4_WQ - N4_WKV;
    } else {
        src = Wo; hi = g_Wohi; lo = g_Wolo; off = i - N4_X - N4_WQ - 2 * N4_WKV;
    }
    float4 v = *(const float4*)(src + (size_t)off * 4);
    __nv_bfloat16 h[4], l[4];
    split4(v, h, l);
    *(__nv_bfloat162*)(hi + (size_t)off * 4 + 0) = __nv_bfloat162(h[0], h[1]);
    *(__nv_bfloat162*)(hi + (size_t)off * 4 + 2) = __nv_bfloat162(h[2], h[3]);
    *(__nv_bfloat162*)(lo + (size_t)off * 4 + 0) = __nv_bfloat162(l[0], l[1]);
    *(__nv_bfloat162*)(lo + (size_t)off * 4 + 2) = __nv_bfloat162(l[2], l[3]);
}

__global__ void split_A_kernel() {
    int i = blockIdx.x * blockDim.x + threadIdx.x;
    if (i >= N4_X) return;
    float4 v = *(const float4*)(g_A + (size_t)i * 4);
    __nv_bfloat16 h[4], l[4];
    split4(v, h, l);
    *(__nv_bfloat162*)(g_Ahi + (size_t)i * 4 + 0) = __nv_bfloat162(h[0], h[1]);
    *(__nv_bfloat162*)(g_Ahi + (size_t)i * 4 + 2) = __nv_bfloat162(h[2], h[3]);
    *(__nv_bfloat162*)(g_Alo + (size_t)i * 4 + 0) = __nv_bfloat162(l[0], l[1]);
    *(__nv_bfloat162*)(g_Alo + (size_t)i * 4 + 2) = __nv_bfloat162(l[2], l[3]);
}

// ---------------------------------------------------------------------------
// bf16-split tensor-core GEMM: Y[m][n] = sum_k A[m][k] * B[n][k]  (NT)
// A = Ahi+Alo, B = Bhi+Blo; acc += AhiBhi + AhiBlo + AloBhi (fp32 acc)
// Block 128x128x32, 256 threads (8 warps: 2m x 4n), 2-stage cp.async pipeline.
// ---------------------------------------------------------------------------
#define STAGE_BYTES 32768   // 4 buffers x 128x32 bf16 (8KB each)
#define GEMM_SMEM (2 * STAGE_BYTES)

__device__ __forceinline__ void cp16(uint32_t saddr, const void* gaddr) {
    asm volatile("cp.async.cg.shared.global [%0], [%1], 16;\n" ::"r"(saddr), "l"(gaddr));
}
__device__ __forceinline__ void ldsm4(uint32_t* r, uint32_t addr) {
    asm volatile("ldmatrix.sync.aligned.m8n8.x4.shared.b16 {%0,%1,%2,%3}, [%4];\n"
                 : "=r"(r[0]), "=r"(r[1]), "=r"(r[2]), "=r"(r[3]) : "r"(addr));
}
__device__ __forceinline__ void mma16816(float* c, const uint32_t* a, uint32_t b0, uint32_t b1) {
    asm volatile("mma.sync.aligned.m16n8k16.row.col.f32.bf16.bf16.f32 "
                 "{%0,%1,%2,%3}, {%4,%5,%6,%7}, {%8,%9}, {%0,%1,%2,%3};\n"
                 : "+f"(c[0]), "+f"(c[1]), "+f"(c[2]), "+f"(c[3])
                 : "r"(a[0]), "r"(a[1]), "r"(a[2]), "r"(a[3]), "r"(b0), "r"(b1));
}

// swizzled smem byte offset for (row 0..127, k halves 0..31), 16B chunks
__device__ __forceinline__ uint32_t sw_off(int row, int k) {
    int c = (k >> 3) ^ (row & 3);
    return (uint32_t)((row * 4 + c) << 4);
}

__device__ __forceinline__ void load_stage(uint32_t sbase, int stage,
                                           const __nv_bfloat16* __restrict__ Ahi,
                                           const __nv_bfloat16* __restrict__ Alo,
                                           const __nv_bfloat16* __restrict__ Bhi,
                                           const __nv_bfloat16* __restrict__ Blo,
                                           int m0, int n0, int k0, int tid) {
    uint32_t st = sbase + stage * STAGE_BYTES;
#pragma unroll
    for (int l = 0; l < 2; l++) {
        int idx = tid + l * 256;          // 0..511
        int row = idx >> 2;               // 0..127
        int c = idx & 3;                  // chunk 0..3
        uint32_t spos = sw_off(row, c * 8);
        size_t goffA = (size_t)(m0 + row) * KDIM + k0 + c * 8;
        size_t goffB = (size_t)(n0 + row) * KDIM + k0 + c * 8;
        cp16(st + spos, Ahi + goffA);
        cp16(st + 8192 + spos, Alo + goffA);
        cp16(st + 16384 + spos, Bhi + goffB);
        cp16(st + 24576 + spos, Blo + goffB);
    }
}

__device__ __forceinline__ void gemm_split_tile(const __nv_bfloat16* __restrict__ Ahi,
                                                const __nv_bfloat16* __restrict__ Alo,
                                                const __nv_bfloat16* __restrict__ Bhi,
                                                const __nv_bfloat16* __restrict__ Blo,
                                                float* __restrict__ Y,
                                                int m0, int n0, int ldy) {
    extern __shared__ char smem_raw[];
    uint32_t sbase = (uint32_t)__cvta_generic_to_shared(smem_raw);

    int tid = threadIdx.x;
    int lane = tid & 31;
    int wid = tid >> 5;
    int wm = wid & 1;    // 0..1
    int wn = wid >> 1;   // 0..3

    float acc[4][4][4];
#pragma unroll
    for (int i = 0; i < 4; i++)
#pragma unroll
        for (int j = 0; j < 4; j++)
#pragma unroll
            for (int r = 0; r < 4; r++) acc[i][j][r] = 0.f;

    load_stage(sbase, 0, Ahi, Alo, Bhi, Blo, m0, n0, 0, tid);
    asm volatile("cp.async.commit_group;\n");

    const int KT = KDIM / 32;   // 64
    int mid = lane >> 3, rin = lane & 7;

    for (int kt = 0; kt < KT; kt++) {
        int buf = kt & 1;
        if (kt + 1 < KT) {
            load_stage(sbase, buf ^ 1, Ahi, Alo, Bhi, Blo, m0, n0, (kt + 1) * 32, tid);
            asm volatile("cp.async.commit_group;\n");
            asm volatile("cp.async.wait_group 1;\n");
        } else {
            asm volatile("cp.async.wait_group 0;\n");
        }
        __syncthreads();

        uint32_t aHiB = sbase + buf * STAGE_BYTES;
        uint32_t aLoB = aHiB + 8192;
        uint32_t bHiB = aHiB + 16384;
        uint32_t bLoB = aHiB + 24576;

#pragma unroll
        for (int kk = 0; kk < 2; kk++) {
            uint32_t ah[4][4], al[4][4];
#pragma unroll
            for (int i = 0; i < 4; i++) {
                int m_l = wm * 64 + i * 16 + (mid & 1) * 8 + rin;
                int k_l = kk * 16 + (mid >> 1) * 8;
                uint32_t so = sw_off(m_l, k_l);
                ldsm4(ah[i], aHiB + so);
                ldsm4(al[i], aLoB + so);
            }
#pragma unroll
            for (int j2 = 0; j2 < 2; j2++) {
                uint32_t bh[4], bl[4];
                int n_l = wn * 32 + (j2 * 2 + (mid >> 1)) * 8 + rin;
                int k_l = kk * 16 + (mid & 1) * 8;
                uint32_t so = sw_off(n_l, k_l);
                ldsm4(bh, bHiB + so);
                ldsm4(bl, bLoB + so);
#pragma unroll
                for (int jj = 0; jj < 2; jj++) {
                    int j = j2 * 2 + jj;
                    uint32_t b0h = bh[jj * 2], b1h = bh[jj * 2 + 1];
                    uint32_t b0l = bl[jj * 2], b1l = bl[jj * 2 + 1];
#pragma unroll
                    for (int i = 0; i < 4; i++) {
                        mma16816(acc[i][j], ah[i], b0h, b1h);
                        mma16816(acc[i][j], ah[i], b0l, b1l);
                        mma16816(acc[i][j], al[i], b0h, b1h);
                    }
                }
            }
        }
        __syncthreads();
    }

    // Epilogue
#pragma unroll
    for (int i = 0; i < 4; i++) {
#pragma unroll
        for (int j = 0; j < 4; j++) {
            int r0 = m0 + wm * 64 + i * 16 + (lane >> 2);
            int cc = n0 + wn * 32 + j * 8 + (lane & 3) * 2;
            *(float2*)&Y[(size_t)r0 * ldy + cc] = make_float2(acc[i][j][0], acc[i][j][1]);
            *(float2*)&Y[(size_t)(r0 + 8) * ldy + cc] = make_float2(acc[i][j][2], acc[i][j][3]);
        }
    }
}

// Fused QKV projection: grid (24, 32). bx 0..15 -> Q, 16..19 -> K, 20..23 -> V
__global__ __launch_bounds__(256, 2) void qkv_gemm_kernel() {
    int bx = blockIdx.x;
    int m0 = blockIdx.y * 128;
    if (bx < 16)
        gemm_split_tile(g_Xhi, g_Xlo, g_Wqhi, g_Wqlo, g_Q, m0, bx * 128, QDIM);
    else if (bx < 20)
        gemm_split_tile(g_Xhi, g_Xlo, g_Wkhi, g_Wklo, g_K, m0, (bx - 16) * 128, KVDIM);
    else
        gemm_split_tile(g_Xhi, g_Xlo, g_Wvhi, g_Wvlo, g_V, m0, (bx - 20) * 128, KVDIM);
}

// Output projection: grid (16, 32)
__global__ __launch_bounds__(256, 2) void out_gemm_kernel(float* __restrict__ out) {
    gemm_split_tile(g_Ahi, g_Alo, g_Wohi, g_Wolo, out, blockIdx.y * 128, blockIdx.x * 128, HH);
}

// ---------------------------------------------------------------------------
// RoPE
// ---------------------------------------------------------------------------
__global__ void rope_table_kernel() {
    int idx = blockIdx.x * blockDim.x + threadIdx.x;
    if (idx >= SS * 64) return;
    int pos = idx >> 6;
    int i = idx & 63;
    double inv = pow(10000.0, -(double)i / 64.0);
    double ang = (double)pos * inv;
    double sd, cd;
    sincos(ang, &sd, &cd);
    g_cos[idx] = (float)cd;
    g_sin[idx] = (float)sd;
}

__global__ void rope_apply_kernel() {
    int idx = blockIdx.x * blockDim.x + threadIdx.x;
    const int qcount = M_TOT * NH * 64;
    const int kcount = M_TOT * NKV * 64;
    if (idx >= qcount + kcount) return;

    float* row;
    int pos, i;
    if (idx < qcount) {
        int m = idx / (NH * 64);
        int r = idx - m * (NH * 64);
        int h = r >> 6;
        i = r & 63;
        pos = m & (SS - 1);
        row = g_Q + (size_t)m * QDIM + h * HD;
    } else {
        int e = idx - qcount;
        int m = e / (NKV * 64);
        int r = e - m * (NKV * 64);
        int h = r >> 6;
        i = r & 63;
        pos = m & (SS - 1);
        row = g_K + (size_t)m * KVDIM + h * HD;
    }
    float c = g_cos[pos * 64 + i];
    float s = g_sin[pos * 64 + i];
    float x1 = row[i];
    float x2 = row[i + 64];
    row[i] = x1 * c - x2 * s;
    row[i + 64] = x2 * c + x1 * s;
}

// ---------------------------------------------------------------------------
// SIMT flash attention (causal, online softmax) — unchanged from round 1
// ---------------------------------------------------------------------------
#define BQ 64
#define BKV 64
#define LDT 132
#define LDSS 65
#define FLASH_SMEM_FLOATS (3 * 64 * LDT + 64 * LDSS + 3 * 64)

__global__ __launch_bounds__(256) void flash_kernel() {
    extern __shared__ float sm[];
    float* Qs = sm;
    float* Ks = Qs + 64 * LDT;
    float* Vs = Ks + 64 * LDT;
    float* Sc = Vs + 64 * LDT;
    float* m_s = Sc + 64 * LDSS;
    float* l_s = m_s + 64;
    float* corr_s = l_s + 64;

    int qt = blockIdx.x;
    int h = blockIdx.y;
    int b = blockIdx.z;
    int q0 = qt * BQ;
    int kh = h / GROUPS;

    int tid = threadIdx.x;
    int ty = tid >> 4, tx = tid & 15;

    const float* Qg = g_Q + ((size_t)(b * SS + q0)) * QDIM + h * HD;
#pragma unroll
    for (int l = 0; l < 8; l++) {
        int idx = tid + l * 256;
        int r = idx >> 5;
        int c4 = (idx & 31) * 4;
        *(float4*)&Qs[r * LDT + c4] = *(const float4*)(Qg + (size_t)r * QDIM + c4);
    }
    if (tid < 64) { m_s[tid] = -1e30f; l_s[tid] = 0.f; }

    float Oa[4][8];
#pragma unroll
    for (int i = 0; i < 4; i++)
#pragma unroll
        for (int j = 0; j < 8; j++) Oa[i][j] = 0.f;

    const float scale = 0.08838834764831845f;
    int ntiles = q0 / BKV + 1;

    for (int t = 0; t < ntiles; t++) {
        int k0 = t * BKV;
        __syncthreads();

        const float* Kg = g_K + ((size_t)(b * SS + k0)) * KVDIM + kh * HD;
        const float* Vg = g_V + ((size_t)(b * SS + k0)) * KVDIM + kh * HD;
#pragma unroll
        for (int l = 0; l < 8; l++) {
            int idx = tid + l * 256;
            int r = idx >> 5;
            int c4 = (idx & 31) * 4;
            *(float4*)&Ks[r * LDT + c4] = *(const float4*)(Kg + (size_t)r * KVDIM + c4);
            *(float4*)&Vs[r * LDT + c4] = *(const float4*)(Vg + (size_t)r * KVDIM + c4);
        }
        __syncthreads();

        float acc[4][4];
#pragma unroll
        for (int i = 0; i < 4; i++)
#pragma unroll
            for (int j = 0; j < 4; j++) acc[i][j] = 0.f;

        for (int d = 0; d < HD; d += 4) {
            float4 q[4], k[4];
#pragma unroll
            for (int i = 0; i < 4; i++) q[i] = *(const float4*)&Qs[(ty * 4 + i) * LDT + d];
#pragma unroll
            for (int j = 0; j < 4; j++) k[j] = *(const float4*)&Ks[(tx * 4 + j) * LDT + d];
#pragma unroll
            for (int i = 0; i < 4; i++)
#pragma unroll
                for (int j = 0; j < 4; j++) {
                    acc[i][j] = fmaf(q[i].x, k[j].x, acc[i][j]);
                    acc[i][j] = fmaf(q[i].y, k[j].y, acc[i][j]);
                    acc[i][j] = fmaf(q[i].z, k[j].z, acc[i][j]);
                    acc[i][j] = fmaf(q[i].w, k[j].w, acc[i][j]);
                }
        }
        bool diag = (t == ntiles - 1);
#pragma unroll
        for (int i = 0; i < 4; i++)
#pragma unroll
            for (int j = 0; j < 4; j++) {
                float v = acc[i][j] * scale;
                if (diag && (k0 + tx * 4 + j > q0 + ty * 4 + i)) v = -1e30f;
                Sc[(ty * 4 + i) * LDSS + tx * 4 + j] = v;
            }
        __syncthreads();

        {
            int row = tid >> 2, qd = tid & 3;
            int base = qd * 16;
            float mprev = m_s[row];
            float p[16];
            float tmax = -1e30f;
#pragma unroll
            for (int c = 0; c < 16; c++) {
                p[c] = Sc[row * LDSS + base + c];
                tmax = fmaxf(tmax, p[c]);
            }
            tmax = fmaxf(tmax, __shfl_xor_sync(0xffffffffu, tmax, 1));
            tmax = fmaxf(tmax, __shfl_xor_sync(0xffffffffu, tmax, 2));
            float newm = fmaxf(mprev, tmax);
            float lsum = 0.f;
#pragma unroll
            for (int c = 0; c < 16; c++) {
                p[c] = __expf(p[c] - newm);
                Sc[row * LDSS + base + c] = p[c];
                lsum += p[c];
            }
            lsum += __shfl_xor_sync(0xffffffffu, lsum, 1);
            lsum += __shfl_xor_sync(0xffffffffu, lsum, 2);
            if (qd == 0) {
                float corr = __expf(mprev - newm);
                corr_s[row] = corr;
                m_s[row] = newm;
                l_s[row] = l_s[row] * corr + lsum;
            }
        }
        __syncthreads();

        float cf[4];
#pragma unroll
        for (int i = 0; i < 4; i++) cf[i] = corr_s[ty * 4 + i];
#pragma unroll
        for (int i = 0; i < 4; i++)
#pragma unroll
            for (int j = 0; j < 8; j++) Oa[i][j] *= cf[i];

        for (int c = 0; c < BKV; c++) {
            float s0 = Sc[(ty * 4 + 0) * LDSS + c];
            float s1 = Sc[(ty * 4 + 1) * LDSS + c];
            float s2 = Sc[(ty * 4 + 2) * LDSS + c];
            float s3 = Sc[(ty * 4 + 3) * LDSS + c];
            float4 va = *(const float4*)&Vs[c * LDT + tx * 8];
            float4 vb = *(const float4*)&Vs[c * LDT + tx * 8 + 4];
            float vv[8] = {va.x, va.y, va.z, va.w, vb.x, vb.y, vb.z, vb.w};
#pragma unroll
            for (int j = 0; j < 8; j++) {
                Oa[0][j] = fmaf(s0, vv[j], Oa[0][j]);
                Oa[1][j] = fmaf(s1, vv[j], Oa[1][j]);
                Oa[2][j] = fmaf(s2, vv[j], Oa[2][j]);
                Oa[3][j] = fmaf(s3, vv[j], Oa[3][j]);
            }
        }
    }
    __syncthreads();

#pragma unroll
    for (int i = 0; i < 4; i++) {
        float inv = 1.f / l_s[ty * 4 + i];
        int m = b * SS + q0 + ty * 4 + i;
        float* arow = g_A + (size_t)m * QDIM + h * HD + tx * 8;
        float4 r0 = make_float4(Oa[i][0] * inv, Oa[i][1] * inv, Oa[i][2] * inv, Oa[i][3] * inv);
        float4 r1 = make_float4(Oa[i][4] * inv, Oa[i][5] * inv, Oa[i][6] * inv, Oa[i][7] * inv);
        *(float4*)(arow + 0) = r0;
        *(float4*)(arow + 4) = r1;
    }
}

// ---------------------------------------------------------------------------
extern "C" void kernel_launch(void* const* d_in, const int* in_sizes, int n_in,
                              void* d_out, int out_size) {
    const float* X = (const float*)d_in[0];
    const float* Wq = (const float*)d_in[1];
    const float* Wk = (const float*)d_in[2];
    const float* Wv = (const float*)d_in[3];
    const float* Wo = (const float*)d_in[4];
    float* out = (float*)d_out;

    // 0. Split inputs to bf16 hi/lo
    split_inputs_kernel<<<(N4_TOTAL + 255) / 256, 256>>>(X, Wq, Wk, Wv, Wo);

    // 1. QKV projections (tensor core, bf16 split)
    cudaFuncSetAttribute(qkv_gemm_kernel, cudaFuncAttributeMaxDynamicSharedMemorySize,
                         GEMM_SMEM);
    qkv_gemm_kernel<<<dim3(24, 32), 256, GEMM_SMEM>>>();

    // 2. RoPE
    rope_table_kernel<<<(SS * 64 + 255) / 256, 256>>>();
    {
        int total = M_TOT * (NH + NKV) * 64;
        rope_apply_kernel<<<(total + 255) / 256, 256>>>();
    }

    // 3. Flash attention (fp32 SIMT)
    size_t smem_bytes = FLASH_SMEM_FLOATS * sizeof(float);
    cudaFuncSetAttribute(flash_kernel, cudaFuncAttributeMaxDynamicSharedMemorySize,
                         (int)smem_bytes);
    flash_kernel<<<dim3(SS / BQ, NH, BB), 256, smem_bytes>>>();

    // 4. Split attention output, then output projection
    split_A_kernel<<<(N4_X + 255) / 256, 256>>>();
    cudaFuncSetAttribute(out_gemm_kernel, cudaFuncAttributeMaxDynamicSharedMemorySize,
                         GEMM_SMEM);
    out_gemm_kernel<<<dim3(16, 32), 256, GEMM_SMEM>>>(out);
}

// round 3
// speedup vs baseline: 3.8138x; 2.6826x over previous
#include <cuda_runtime.h>
#include <cuda_bf16.h>
#include <math.h>
#include <stdint.h>

// Problem constants
#define BB 2
#define SS 2048
#define HH 2048
#define NH 16
#define NKV 4
#define HD 128
#define GROUPS (NH / NKV)        // 4
#define M_TOT (BB * SS)          // 4096
#define QDIM (NH * HD)           // 2048
#define KVDIM (NKV * HD)         // 512
#define KDIM 2048                // GEMM reduction dim

// fp32 scratch (pre-RoPE projections)
__device__ __align__(16) float g_Q[M_TOT * QDIM];
__device__ __align__(16) float g_K[M_TOT * KVDIM];
__device__ __align__(16) float g_V[M_TOT * KVDIM];
__device__ float g_cos[SS * 64];
__device__ float g_sin[SS * 64];

// bf16 hi/lo split buffers for GEMMs
__device__ __align__(16) __nv_bfloat16 g_Xhi[M_TOT * KDIM], g_Xlo[M_TOT * KDIM];
__device__ __align__(16) __nv_bfloat16 g_Wqhi[QDIM * KDIM], g_Wqlo[QDIM * KDIM];
__device__ __align__(16) __nv_bfloat16 g_Wkhi[KVDIM * KDIM], g_Wklo[KVDIM * KDIM];
__device__ __align__(16) __nv_bfloat16 g_Wvhi[KVDIM * KDIM], g_Wvlo[KVDIM * KDIM];
__device__ __align__(16) __nv_bfloat16 g_Wohi[HH * KDIM], g_Wolo[HH * KDIM];
__device__ __align__(16) __nv_bfloat16 g_Ahi[M_TOT * KDIM], g_Alo[M_TOT * KDIM];

// bf16 hi/lo head-major buffers for flash: [b, h, s, d]
__device__ __align__(16) __nv_bfloat16 g_Qbhi[M_TOT * QDIM], g_Qblo[M_TOT * QDIM];
__device__ __align__(16) __nv_bfloat16 g_Kbhi[M_TOT * KVDIM], g_Kblo[M_TOT * KVDIM];
__device__ __align__(16) __nv_bfloat16 g_Vbhi[M_TOT * KVDIM], g_Vblo[M_TOT * KVDIM];

// ---------------------------------------------------------------------------
// Helpers
// ---------------------------------------------------------------------------
__device__ __forceinline__ void split1(float x, __nv_bfloat16& h, __nv_bfloat16& l) {
    h = __float2bfloat16(x);
    l = __float2bfloat16(x - __bfloat162float(h));
}
__device__ __forceinline__ void split4(const float4 v, __nv_bfloat16* hi, __nv_bfloat16* lo) {
    float x[4] = {v.x, v.y, v.z, v.w};
#pragma unroll
    for (int i = 0; i < 4; i++) split1(x[i], hi[i], lo[i]);
}
__device__ __forceinline__ uint32_t pack_bf2(__nv_bfloat16 a, __nv_bfloat16 b) {
    __nv_bfloat162 t(a, b);
    return *(uint32_t*)&t;
}
__device__ __forceinline__ void cp16(uint32_t saddr, const void* gaddr) {
    asm volatile("cp.async.cg.shared.global [%0], [%1], 16;\n" ::"r"(saddr), "l"(gaddr));
}
__device__ __forceinline__ void ldsm4(uint32_t* r, uint32_t addr) {
    asm volatile("ldmatrix.sync.aligned.m8n8.x4.shared.b16 {%0,%1,%2,%3}, [%4];\n"
                 : "=r"(r[0]), "=r"(r[1]), "=r"(r[2]), "=r"(r[3]) : "r"(addr));
}
__device__ __forceinline__ void ldsm4t(uint32_t* r, uint32_t addr) {
    asm volatile("ldmatrix.sync.aligned.m8n8.x4.trans.shared.b16 {%0,%1,%2,%3}, [%4];\n"
                 : "=r"(r[0]), "=r"(r[1]), "=r"(r[2]), "=r"(r[3]) : "r"(addr));
}
__device__ __forceinline__ void mma16816(float* c, const uint32_t* a, uint32_t b0, uint32_t b1) {
    asm volatile("mma.sync.aligned.m16n8k16.row.col.f32.bf16.bf16.f32 "
                 "{%0,%1,%2,%3}, {%4,%5,%6,%7}, {%8,%9}, {%0,%1,%2,%3};\n"
                 : "+f"(c[0]), "+f"(c[1]), "+f"(c[2]), "+f"(c[3])
                 : "r"(a[0]), "r"(a[1]), "r"(a[2]), "r"(a[3]), "r"(b0), "r"(b1));
}

// ---------------------------------------------------------------------------
// Input split
// ---------------------------------------------------------------------------
#define N4_X  ((M_TOT * KDIM) / 4)
#define N4_WQ ((QDIM * KDIM) / 4)
#define N4_WKV ((KVDIM * KDIM) / 4)
#define N4_WO ((HH * KDIM) / 4)
#define N4_TOTAL (N4_X + N4_WQ + 2 * N4_WKV + N4_WO)

__global__ void split_inputs_kernel(const float* __restrict__ X,
                                    const float* __restrict__ Wq,
                                    const float* __restrict__ Wk,
                                    const float* __restrict__ Wv,
                                    const float* __restrict__ Wo) {
    int i = blockIdx.x * blockDim.x + threadIdx.x;
    if (i >= N4_TOTAL) return;
    const float* src;
    __nv_bfloat16 *hi, *lo;
    int off;
    if (i < N4_X) {
        src = X; hi = g_Xhi; lo = g_Xlo; off = i;
    } else if (i < N4_X + N4_WQ) {
        src = Wq; hi = g_Wqhi; lo = g_Wqlo; off = i - N4_X;
    } else if (i < N4_X + N4_WQ + N4_WKV) {
        src = Wk; hi = g_Wkhi; lo = g_Wklo; off = i - N4_X - N4_WQ;
    } else if (i < N4_X + N4_WQ + 2 * N4_WKV) {
        src = Wv; hi = g_Wvhi; lo = g_Wvlo; off = i - N4_X - N4_WQ - N4_WKV;
    } else {
        src = Wo; hi = g_Wohi; lo = g_Wolo; off = i - N4_X - N4_WQ - 2 * N4_WKV;
    }
    float4 v = *(const float4*)(src + (size_t)off * 4);
    __nv_bfloat16 h[4], l[4];
    split4(v, h, l);
    *(uint32_t*)(hi + (size_t)off * 4 + 0) = pack_bf2(h[0], h[1]);
    *(uint32_t*)(hi + (size_t)off * 4 + 2) = pack_bf2(h[2], h[3]);
    *(uint32_t*)(lo + (size_t)off * 4 + 0) = pack_bf2(l[0], l[1]);
    *(uint32_t*)(lo + (size_t)off * 4 + 2) = pack_bf2(l[2], l[3]);
}

// ---------------------------------------------------------------------------
// bf16-split tensor-core GEMM (from round 2, unchanged)
// ---------------------------------------------------------------------------
#define STAGE_BYTES 32768
#define GEMM_SMEM (2 * STAGE_BYTES)

__device__ __forceinline__ uint32_t sw_off(int row, int k) {
    int c = (k >> 3) ^ (row & 3);
    return (uint32_t)((row * 4 + c) << 4);
}

__device__ __forceinline__ void load_stage(uint32_t sbase, int stage,
                                           const __nv_bfloat16* __restrict__ Ahi,
                                           const __nv_bfloat16* __restrict__ Alo,
                                           const __nv_bfloat16* __restrict__ Bhi,
                                           const __nv_bfloat16* __restrict__ Blo,
                                           int m0, int n0, int k0, int tid) {
    uint32_t st = sbase + stage * STAGE_BYTES;
#pragma unroll
    for (int l = 0; l < 2; l++) {
        int idx = tid + l * 256;
        int row = idx >> 2;
        int c = idx & 3;
        uint32_t spos = sw_off(row, c * 8);
        size_t goffA = (size_t)(m0 + row) * KDIM + k0 + c * 8;
        size_t goffB = (size_t)(n0 + row) * KDIM + k0 + c * 8;
        cp16(st + spos, Ahi + goffA);
        cp16(st + 8192 + spos, Alo + goffA);
        cp16(st + 16384 + spos, Bhi + goffB);
        cp16(st + 24576 + spos, Blo + goffB);
    }
}

__device__ __forceinline__ void gemm_split_tile(const __nv_bfloat16* __restrict__ Ahi,
                                                const __nv_bfloat16* __restrict__ Alo,
                                                const __nv_bfloat16* __restrict__ Bhi,
                                                const __nv_bfloat16* __restrict__ Blo,
                                                float* __restrict__ Y,
                                                int m0, int n0, int ldy) {
    extern __shared__ char smem_raw[];
    uint32_t sbase = (uint32_t)__cvta_generic_to_shared(smem_raw);

    int tid = threadIdx.x;
    int lane = tid & 31;
    int wid = tid >> 5;
    int wm = wid & 1;
    int wn = wid >> 1;

    float acc[4][4][4];
#pragma unroll
    for (int i = 0; i < 4; i++)
#pragma unroll
        for (int j = 0; j < 4; j++)
#pragma unroll
            for (int r = 0; r < 4; r++) acc[i][j][r] = 0.f;

    load_stage(sbase, 0, Ahi, Alo, Bhi, Blo, m0, n0, 0, tid);
    asm volatile("cp.async.commit_group;\n");

    const int KT = KDIM / 32;
    int mid = lane >> 3, rin = lane & 7;

    for (int kt = 0; kt < KT; kt++) {
        int buf = kt & 1;
        if (kt + 1 < KT) {
            load_stage(sbase, buf ^ 1, Ahi, Alo, Bhi, Blo, m0, n0, (kt + 1) * 32, tid);
            asm volatile("cp.async.commit_group;\n");
            asm volatile("cp.async.wait_group 1;\n");
        } else {
            asm volatile("cp.async.wait_group 0;\n");
        }
        __syncthreads();

        uint32_t aHiB = sbase + buf * STAGE_BYTES;
        uint32_t aLoB = aHiB + 8192;
        uint32_t bHiB = aHiB + 16384;
        uint32_t bLoB = aHiB + 24576;

#pragma unroll
        for (int kk = 0; kk < 2; kk++) {
            uint32_t ah[4][4], al[4][4];
#pragma unroll
            for (int i = 0; i < 4; i++) {
                int m_l = wm * 64 + i * 16 + (mid & 1) * 8 + rin;
                int k_l = kk * 16 + (mid >> 1) * 8;
                uint32_t so = sw_off(m_l, k_l);
                ldsm4(ah[i], aHiB + so);
                ldsm4(al[i], aLoB + so);
            }
#pragma unroll
            for (int j2 = 0; j2 < 2; j2++) {
                uint32_t bh[4], bl[4];
                int n_l = wn * 32 + (j2 * 2 + (mid >> 1)) * 8 + rin;
                int k_l = kk * 16 + (mid & 1) * 8;
                uint32_t so = sw_off(n_l, k_l);
                ldsm4(bh, bHiB + so);
                ldsm4(bl, bLoB + so);
#pragma unroll
                for (int jj = 0; jj < 2; jj++) {
                    int j = j2 * 2 + jj;
#pragma unroll
                    for (int i = 0; i < 4; i++) {
                        mma16816(acc[i][j], ah[i], bh[jj * 2], bh[jj * 2 + 1]);
                        mma16816(acc[i][j], ah[i], bl[jj * 2], bl[jj * 2 + 1]);
                        mma16816(acc[i][j], al[i], bh[jj * 2], bh[jj * 2 + 1]);
                    }
                }
            }
        }
        __syncthreads();
    }

#pragma unroll
    for (int i = 0; i < 4; i++) {
#pragma unroll
        for (int j = 0; j < 4; j++) {
            int r0 = m0 + wm * 64 + i * 16 + (lane >> 2);
            int cc = n0 + wn * 32 + j * 8 + (lane & 3) * 2;
            *(float2*)&Y[(size_t)r0 * ldy + cc] = make_float2(acc[i][j][0], acc[i][j][1]);
            *(float2*)&Y[(size_t)(r0 + 8) * ldy + cc] = make_float2(acc[i][j][2], acc[i][j][3]);
        }
    }
}

__global__ __launch_bounds__(256, 2) void qkv_gemm_kernel() {
    int bx = blockIdx.x;
    int m0 = blockIdx.y * 128;
    if (bx < 16)
        gemm_split_tile(g_Xhi, g_Xlo, g_Wqhi, g_Wqlo, g_Q, m0, bx * 128, QDIM);
    else if (bx < 20)
        gemm_split_tile(g_Xhi, g_Xlo, g_Wkhi, g_Wklo, g_K, m0, (bx - 16) * 128, KVDIM);
    else
        gemm_split_tile(g_Xhi, g_Xlo, g_Wvhi, g_Wvlo, g_V, m0, (bx - 20) * 128, KVDIM);
}

__global__ __launch_bounds__(256, 2) void out_gemm_kernel(float* __restrict__ out) {
    gemm_split_tile(g_Ahi, g_Alo, g_Wohi, g_Wolo, out, blockIdx.y * 128, blockIdx.x * 128, HH);
}

// ---------------------------------------------------------------------------
// RoPE table + fused RoPE/convert/relayout
// ---------------------------------------------------------------------------
__global__ void rope_table_kernel() {
    int idx = blockIdx.x * blockDim.x + threadIdx.x;
    if (idx >= SS * 64) return;
    int pos = idx >> 6;
    int i = idx & 63;
    double inv = pow(10000.0, -(double)i / 64.0);
    double ang = (double)pos * inv;
    double sd, cd;
    sincos(ang, &sd, &cd);
    g_cos[idx] = (float)cd;
    g_sin[idx] = (float)sd;
}

// One thread per (row, head, d-pair). Q gets rope, K gets rope, V straight.
#define RC_Q (M_TOT * NH * 64)
#define RC_K (M_TOT * NKV * 64)
#define RC_V (M_TOT * NKV * 64)

__global__ void rope_convert_kernel() {
    int idx = blockIdx.x * blockDim.x + threadIdx.x;
    if (idx >= RC_Q + RC_K + RC_V) return;

    if (idx < RC_Q) {
        int m = idx / (NH * 64);
        int r = idx - m * (NH * 64);
        int h = r >> 6, d = r & 63;
        int b = m >> 11, s = m & (SS - 1);
        float x1 = g_Q[(size_t)m * QDIM + h * HD + d];
        float x2 = g_Q[(size_t)m * QDIM + h * HD + d + 64];
        float c = g_cos[s * 64 + d], sn = g_sin[s * 64 + d];
        float y1 = x1 * c - x2 * sn;
        float y2 = x2 * c + x1 * sn;
        size_t dst = ((size_t)(b * NH + h) * SS + s) * HD + d;
        __nv_bfloat16 h1, l1, h2, l2;
        split1(y1, h1, l1);
        split1(y2, h2, l2);
        g_Qbhi[dst] = h1; g_Qblo[dst] = l1;
        g_Qbhi[dst + 64] = h2; g_Qblo[dst + 64] = l2;
    } else if (idx < RC_Q + RC_K) {
        int e = idx - RC_Q;
        int m = e / (NKV * 64);
        int r = e - m * (NKV * 64);
        int h = r >> 6, d = r & 63;
        int b = m >> 11, s = m & (SS - 1);
        float x1 = g_K[(size_t)m * KVDIM + h * HD + d];
        float x2 = g_K[(size_t)m * KVDIM + h * HD + d + 64];
        float c = g_cos[s * 64 + d], sn = g_sin[s * 64 + d];
        float y1 = x1 * c - x2 * sn;
        float y2 = x2 * c + x1 * sn;
        size_t dst = ((size_t)(b * NKV + h) * SS + s) * HD + d;
        __nv_bfloat16 h1, l1, h2, l2;
        split1(y1, h1, l1);
        split1(y2, h2, l2);
        g_Kbhi[dst] = h1; g_Kblo[dst] = l1;
        g_Kbhi[dst + 64] = h2; g_Kblo[dst + 64] = l2;
    } else {
        int e = idx - RC_Q - RC_K;
        int m = e / (NKV * 64);
        int r = e - m * (NKV * 64);
        int h = r >> 6, d = r & 63;
        int b = m >> 11, s = m & (SS - 1);
        float x1 = g_V[(size_t)m * KVDIM + h * HD + d];
        float x2 = g_V[(size_t)m * KVDIM + h * HD + d + 64];
        size_t dst = ((size_t)(b * NKV + h) * SS + s) * HD + d;
        __nv_bfloat16 h1, l1, h2, l2;
        split1(x1, h1, l1);
        split1(x2, h2, l2);
        g_Vbhi[dst] = h1; g_Vblo[dst] = l1;
        g_Vbhi[dst + 64] = h2; g_Vblo[dst + 64] = l2;
    }
}

// ---------------------------------------------------------------------------
// Tensor-core flash attention (causal, bf16-split), BQ=128, BKV=64, 8 warps
// smem: Qhi 32K | Qlo 32K | stage{0,1}: Khi 16K | Klo 16K | Vhi 16K | Vlo 16K
// ---------------------------------------------------------------------------
#define FQ 128
#define FK 64
#define FLASH_SMEM (65536 + 2 * 65536)   // 192 KB

// rows are 256B (128 bf16 = 16 chunks of 16B); XOR-swizzle chunk by row&7
__device__ __forceinline__ uint32_t sw256(int row, int chunk) {
    return (uint32_t)(row * 256 + ((chunk ^ (row & 7)) << 4));
}

__device__ __forceinline__ void flash_load_kv(uint32_t sb, int t, int st,
                                              const __nv_bfloat16* Kh, const __nv_bfloat16* Kl,
                                              const __nv_bfloat16* Vh, const __nv_bfloat16* Vl,
                                              int tid) {
    uint32_t base = sb + 65536 + st * 65536;
    size_t g0 = (size_t)t * FK * HD;
#pragma unroll
    for (int l = 0; l < 4; l++) {
        int idx = tid + l * 256;      // 0..1023 = 64 rows x 16 chunks
        int row = idx >> 4;
        int c = idx & 15;
        uint32_t off = sw256(row, c);
        size_t go = g0 + (size_t)row * HD + c * 8;
        cp16(base + off, Kh + go);
        cp16(base + 16384 + off, Kl + go);
        cp16(base + 32768 + off, Vh + go);
        cp16(base + 49152 + off, Vl + go);
    }
}

__global__ __launch_bounds__(256) void flash_tc_kernel() {
    extern __shared__ char smem_raw[];
    uint32_t sb = (uint32_t)__cvta_generic_to_shared(smem_raw);
    uint32_t Qhi_s = sb, Qlo_s = sb + 32768;

    int qt = (int)(gridDim.x - 1 - blockIdx.x);   // big tiles first
    int h = blockIdx.y, b = blockIdx.z;
    int q0 = qt * FQ;
    int kh = h / GROUPS;

    int tid = threadIdx.x, lane = tid & 31, wid = tid >> 5;
    int mid = lane >> 3, rin = lane & 7;

    const __nv_bfloat16* Qhig = g_Qbhi + ((size_t)(b * NH + h) * SS + q0) * HD;
    const __nv_bfloat16* Qlog = g_Qblo + ((size_t)(b * NH + h) * SS + q0) * HD;
    const __nv_bfloat16* Khg = g_Kbhi + (size_t)(b * NKV + kh) * SS * HD;
    const __nv_bfloat16* Klg = g_Kblo + (size_t)(b * NKV + kh) * SS * HD;
    const __nv_bfloat16* Vhg = g_Vbhi + (size_t)(b * NKV + kh) * SS * HD;
    const __nv_bfloat16* Vlg = g_Vblo + (size_t)(b * NKV + kh) * SS * HD;

    // Load Q tile (both hi and lo)
#pragma unroll
    for (int l = 0; l < 8; l++) {
        int idx = tid + l * 256;      // 0..2047 = 128 rows x 16 chunks
        int row = idx >> 4;
        int c = idx & 15;
        uint32_t off = sw256(row, c);
        size_t go = (size_t)row * HD + c * 8;
        cp16(Qhi_s + off, Qhig + go);
        cp16(Qlo_s + off, Qlog + go);
    }
    flash_load_kv(sb, 0, 0, Khg, Klg, Vhg, Vlg, tid);
    asm volatile("cp.async.commit_group;\n");

    float m_lo = -1e30f, m_hi = -1e30f, l_lo = 0.f, l_hi = 0.f;
    float oacc[16][4];
#pragma unroll
    for (int v = 0; v < 16; v++)
#pragma unroll
        for (int r = 0; r < 4; r++) oacc[v][r] = 0.f;

    const float scale = 0.08838834764831845f;
    const int ntile = 2 * qt + 2;
    const int rlo = q0 + wid * 16 + (lane >> 2);
    const int rhi = rlo + 8;

    for (int t = 0; t < ntile; t++) {
        int buf = t & 1;
        if (t + 1 < ntile) {
            flash_load_kv(sb, t + 1, buf ^ 1, Khg, Klg, Vhg, Vlg, tid);
            asm volatile("cp.async.commit_group;\n");
            asm volatile("cp.async.wait_group 1;\n");
        } else {
            asm volatile("cp.async.wait_group 0;\n");
        }
        __syncthreads();

        uint32_t kbh = sb + 65536 + buf * 65536;
        uint32_t kbl = kbh + 16384;
        uint32_t vbh = kbh + 32768;
        uint32_t vbl = kbh + 49152;

        // ---- S = Q K^T (split: hh + hl + lh) ----
        float sacc[8][4];
#pragma unroll
        for (int n = 0; n < 8; n++)
#pragma unroll
            for (int r = 0; r < 4; r++) sacc[n][r] = 0.f;

#pragma unroll
        for (int kk = 0; kk < 8; kk++) {
            uint32_t ah[4], al[4];
            {
                int m_l = wid * 16 + (mid & 1) * 8 + rin;
                int chnk = kk * 2 + (mid >> 1);
                uint32_t so = sw256(m_l, chnk);
                ldsm4(ah, Qhi_s + so);
                ldsm4(al, Qlo_s + so);
            }
#pragma unroll
            for (int j2 = 0; j2 < 4; j2++) {
                uint32_t bh[4], bl[4];
                int n_l = (j2 * 2 + (mid >> 1)) * 8 + rin;
                int chnk = kk * 2 + (mid & 1);
                uint32_t so = sw256(n_l, chnk);
                ldsm4(bh, kbh + so);
                ldsm4(bl, kbl + so);
#pragma unroll
                for (int jj = 0; jj < 2; jj++) {
                    int j = j2 * 2 + jj;
                    mma16816(sacc[j], ah, bh[jj * 2], bh[jj * 2 + 1]);
                    mma16816(sacc[j], ah, bl[jj * 2], bl[jj * 2 + 1]);
                    mma16816(sacc[j], al, bh[jj * 2], bh[jj * 2 + 1]);
                }
            }
        }

        // ---- scale + causal mask ----
        int k0 = t * FK;
        bool diag = (t >= 2 * qt);
#pragma unroll
        for (int n = 0; n < 8; n++) {
            int c0 = k0 + n * 8 + (lane & 3) * 2;
            sacc[n][0] *= scale;
            sacc[n][1] *= scale;
            sacc[n][2] *= scale;
            sacc[n][3] *= scale;
            if (diag) {
                if (c0 > rlo) sacc[n][0] = -1e30f;
                if (c0 + 1 > rlo) sacc[n][1] = -1e30f;
                if (c0 > rhi) sacc[n][2] = -1e30f;
                if (c0 + 1 > rhi) sacc[n][3] = -1e30f;
            }
        }

        // ---- online softmax (rows rlo, rhi) ----
        float mx0 = -1e30f, mx1 = -1e30f;
#pragma unroll
        for (int n = 0; n < 8; n++) {
            mx0 = fmaxf(mx0, fmaxf(sacc[n][0], sacc[n][1]));
            mx1 = fmaxf(mx1, fmaxf(sacc[n][2], sacc[n][3]));
        }
        mx0 = fmaxf(mx0, __shfl_xor_sync(0xffffffffu, mx0, 1));
        mx0 = fmaxf(mx0, __shfl_xor_sync(0xffffffffu, mx0, 2));
        mx1 = fmaxf(mx1, __shfl_xor_sync(0xffffffffu, mx1, 1));
        mx1 = fmaxf(mx1, __shfl_xor_sync(0xffffffffu, mx1, 2));
        float newm0 = fmaxf(m_lo, mx0);
        float newm1 = fmaxf(m_hi, mx1);
        float corr0 = __expf(m_lo - newm0);
        float corr1 = __expf(m_hi - newm1);
        m_lo = newm0;
        m_hi = newm1;

        float ls0 = 0.f, ls1 = 0.f;
#pragma unroll
        for (int n = 0; n < 8; n++) {
            sacc[n][0] = __expf(sacc[n][0] - newm0);
            sacc[n][1] = __expf(sacc[n][1] - newm0);
            sacc[n][2] = __expf(sacc[n][2] - newm1);
            sacc[n][3] = __expf(sacc[n][3] - newm1);
            ls0 += sacc[n][0] + sacc[n][1];
            ls1 += sacc[n][2] + sacc[n][3];
        }
        ls0 += __shfl_xor_sync(0xffffffffu, ls0, 1);
        ls0 += __shfl_xor_sync(0xffffffffu, ls0, 2);
        ls1 += __shfl_xor_sync(0xffffffffu, ls1, 1);
        ls1 += __shfl_xor_sync(0xffffffffu, ls1, 2);
        l_lo = l_lo * corr0 + ls0;
        l_hi = l_hi * corr1 + ls1;

#pragma unroll
        for (int v = 0; v < 16; v++) {
            oacc[v][0] *= corr0;
            oacc[v][1] *= corr0;
            oacc[v][2] *= corr1;
            oacc[v][3] *= corr1;
        }

        // ---- O += P V (split: hh + hl + lh) ----
#pragma unroll
        for (int kk = 0; kk < 4; kk++) {
            // A-frags for P from score regs (n-tiles 2kk, 2kk+1)
            uint32_t aph[4], apl[4];
            {
                __nv_bfloat16 h0, l0, h1, l1;
                split1(sacc[2 * kk][0], h0, l0);
                split1(sacc[2 * kk][1], h1, l1);
                aph[0] = pack_bf2(h0, h1);
                apl[0] = pack_bf2(l0, l1);
                split1(sacc[2 * kk][2], h0, l0);
                split1(sacc[2 * kk][3], h1, l1);
                aph[1] = pack_bf2(h0, h1);
                apl[1] = pack_bf2(l0, l1);
                split1(sacc[2 * kk + 1][0], h0, l0);
                split1(sacc[2 * kk + 1][1], h1, l1);
                aph[2] = pack_bf2(h0, h1);
                apl[2] = pack_bf2(l0, l1);
                split1(sacc[2 * kk + 1][2], h0, l0);
                split1(sacc[2 * kk + 1][3], h1, l1);
                aph[3] = pack_bf2(h0, h1);
                apl[3] = pack_bf2(l0, l1);
            }
#pragma unroll
            for (int v2 = 0; v2 < 8; v2++) {
                // trans ldmatrix: lanes 0-7 m0, 8-15 m1, 16-23 m2, 24-31 m3
                // m0: rows kk*16+r,  chunk v2*2   -> b0 of vnt=v2*2
                // m1: rows kk*16+8+r, chunk v2*2  -> b1 of vnt=v2*2
                // m2/m3: chunk v2*2+1              -> vnt=v2*2+1
                int g = lane >> 3;
                int row = kk * 16 + (g & 1) * 8 + rin;
                int chnk = v2 * 2 + (g >> 1);
                uint32_t so = sw256(row, chnk);
                uint32_t vh[4], vl[4];
                ldsm4t(vh, vbh + so);
                ldsm4t(vl, vbl + so);
#pragma unroll
                for (int gg = 0; gg < 2; gg++) {
                    int vnt = v2 * 2 + gg;
                    mma16816(oacc[vnt], aph, vh[gg * 2], vh[gg * 2 + 1]);
                    mma16816(oacc[vnt], aph, vl[gg * 2], vl[gg * 2 + 1]);
                    mma16816(oacc[vnt], apl, vh[gg * 2], vh[gg * 2 + 1]);
                }
            }
        }
        __syncthreads();  // everyone done with this stage's K/V before reload
    }

    // ---- epilogue: normalize and write bf16 hi/lo to g_Ahi/g_Alo ----
    float inv0 = 1.f / l_lo;
    float inv1 = 1.f / l_hi;
    int row0 = b * SS + q0 + wid * 16 + (lane >> 2);
    int row1 = row0 + 8;
#pragma unroll
    for (int v = 0; v < 16; v++) {
        int col = h * HD + v * 8 + (lane & 3) * 2;
        float o0 = oacc[v][0] * inv0, o1 = oacc[v][1] * inv0;
        float o2 = oacc[v][2] * inv1, o3 = oacc[v][3] * inv1;
        __nv_bfloat16 h0, l0, h1, l1;
        split1(o0, h0, l0);
        split1(o1, h1, l1);
        *(uint32_t*)(g_Ahi + (size_t)row0 * KDIM + col) = pack_bf2(h0, h1);
        *(uint32_t*)(g_Alo + (size_t)row0 * KDIM + col) = pack_bf2(l0, l1);
        split1(o2, h0, l0);
        split1(o3, h1, l1);
        *(uint32_t*)(g_Ahi + (size_t)row1 * KDIM + col) = pack_bf2(h0, h1);
        *(uint32_t*)(g_Alo + (size_t)row1 * KDIM + col) = pack_bf2(l0, l1);
    }
}

// ---------------------------------------------------------------------------
extern "C" void kernel_launch(void* const* d_in, const int* in_sizes, int n_in,
                              void* d_out, int out_size) {
    const float* X = (const float*)d_in[0];
    const float* Wq = (const float*)d_in[1];
    const float* Wk = (const float*)d_in[2];
    const float* Wv = (const float*)d_in[3];
    const float* Wo = (const float*)d_in[4];
    float* out = (float*)d_out;

    // 0. Split inputs to bf16 hi/lo
    split_inputs_kernel<<<(N4_TOTAL + 255) / 256, 256>>>(X, Wq, Wk, Wv, Wo);

    // 1. QKV projections
    cudaFuncSetAttribute(qkv_gemm_kernel, cudaFuncAttributeMaxDynamicSharedMemorySize,
                         GEMM_SMEM);
    qkv_gemm_kernel<<<dim3(24, 32), 256, GEMM_SMEM>>>();

    // 2. RoPE table + fused rope/convert/relayout
    rope_table_kernel<<<(SS * 64 + 255) / 256, 256>>>();
    {
        int total = RC_Q + RC_K + RC_V;
        rope_convert_kernel<<<(total + 255) / 256, 256>>>();
    }

    // 3. Tensor-core flash attention
    cudaFuncSetAttribute(flash_tc_kernel, cudaFuncAttributeMaxDynamicSharedMemorySize,
                         FLASH_SMEM);
    flash_tc_kernel<<<dim3(SS / FQ, NH, BB), 256, FLASH_SMEM>>>();

    // 4. Output projection
    cudaFuncSetAttribute(out_gemm_kernel, cudaFuncAttributeMaxDynamicSharedMemorySize,
                         GEMM_SMEM);
    out_gemm_kernel<<<dim3(16, 32), 256, GEMM_SMEM>>>(out);
}

// round 5
// speedup vs baseline: 4.5377x; 1.1898x over previous
#include <cuda_runtime.h>
#include <cuda_bf16.h>
#include <cuda_fp16.h>
#include <math.h>
#include <stdint.h>

// Problem constants
#define BB 2
#define SS 2048
#define HH 2048
#define NH 16
#define NKV 4
#define HD 128
#define GROUPS (NH / NKV)        // 4
#define M_TOT (BB * SS)          // 4096
#define QDIM (NH * HD)           // 2048
#define KVDIM (NKV * HD)         // 512
#define KDIM 2048                // GEMM reduction dim

// fp32 scratch (pre-RoPE projections)
__device__ __align__(16) float g_Q[M_TOT * QDIM];
__device__ __align__(16) float g_K[M_TOT * KVDIM];
__device__ __align__(16) float g_V[M_TOT * KVDIM];
__device__ float g_cos[SS * 64];
__device__ float g_sin[SS * 64];

// fp16 split buffers for projection GEMMs (A split hi/lo, W rounded)
__device__ __align__(16) __half g_Xhi[M_TOT * KDIM], g_Xlo[M_TOT * KDIM];
__device__ __align__(16) __half g_Wqh[QDIM * KDIM];
__device__ __align__(16) __half g_Wkh[KVDIM * KDIM];
__device__ __align__(16) __half g_Wvh[KVDIM * KDIM];
__device__ __align__(16) __half g_Woh[HH * KDIM];
__device__ __align__(16) __half g_Ahi[M_TOT * KDIM], g_Alo[M_TOT * KDIM];

// bf16 hi/lo head-major buffers for flash: [b, h, s, d]
__device__ __align__(16) __nv_bfloat16 g_Qbhi[M_TOT * QDIM], g_Qblo[M_TOT * QDIM];
__device__ __align__(16) __nv_bfloat16 g_Kbhi[M_TOT * KVDIM], g_Kblo[M_TOT * KVDIM];
__device__ __align__(16) __nv_bfloat16 g_Vbhi[M_TOT * KVDIM], g_Vblo[M_TOT * KVDIM];

// ---------------------------------------------------------------------------
// Helpers
// ---------------------------------------------------------------------------
__device__ __forceinline__ void split1(float x, __nv_bfloat16& h, __nv_bfloat16& l) {
    h = __float2bfloat16(x);
    l = __float2bfloat16(x - __bfloat162float(h));
}
__device__ __forceinline__ void split1h(float x, __half& h, __half& l) {
    h = __float2half_rn(x);
    l = __float2half_rn(x - __half2float(h));
}
__device__ __forceinline__ uint32_t pack_bf2(__nv_bfloat16 a, __nv_bfloat16 b) {
    __nv_bfloat162 t(a, b);
    return *(uint32_t*)&t;
}
__device__ __forceinline__ uint32_t pack_h2(__half a, __half b) {
    __half2 t(a, b);
    return *(uint32_t*)&t;
}
__device__ __forceinline__ void cp16(uint32_t saddr, const void* gaddr) {
    asm volatile("cp.async.cg.shared.global [%0], [%1], 16;\n" ::"r"(saddr), "l"(gaddr));
}
__device__ __forceinline__ void ldsm4(uint32_t* r, uint32_t addr) {
    asm volatile("ldmatrix.sync.aligned.m8n8.x4.shared.b16 {%0,%1,%2,%3}, [%4];\n"
                 : "=r"(r[0]), "=r"(r[1]), "=r"(r[2]), "=r"(r[3]) : "r"(addr));
}
__device__ __forceinline__ void ldsm4t(uint32_t* r, uint32_t addr) {
    asm volatile("ldmatrix.sync.aligned.m8n8.x4.trans.shared.b16 {%0,%1,%2,%3}, [%4];\n"
                 : "=r"(r[0]), "=r"(r[1]), "=r"(r[2]), "=r"(r[3]) : "r"(addr));
}
// bf16 mma (flash)
__device__ __forceinline__ void mma16816(float* c, const uint32_t* a, uint32_t b0, uint32_t b1) {
    asm volatile("mma.sync.aligned.m16n8k16.row.col.f32.bf16.bf16.f32 "
                 "{%0,%1,%2,%3}, {%4,%5,%6,%7}, {%8,%9}, {%0,%1,%2,%3};\n"
                 : "+f"(c[0]), "+f"(c[1]), "+f"(c[2]), "+f"(c[3])
                 : "r"(a[0]), "r"(a[1]), "r"(a[2]), "r"(a[3]), "r"(b0), "r"(b1));
}
// fp16 mma (projections)
__device__ __forceinline__ void mma16816h(float* c, const uint32_t* a, uint32_t b0, uint32_t b1) {
    asm volatile("mma.sync.aligned.m16n8k16.row.col.f32.f16.f16.f32 "
                 "{%0,%1,%2,%3}, {%4,%5,%6,%7}, {%8,%9}, {%0,%1,%2,%3};\n"
                 : "+f"(c[0]), "+f"(c[1]), "+f"(c[2]), "+f"(c[3])
                 : "r"(a[0]), "r"(a[1]), "r"(a[2]), "r"(a[3]), "r"(b0), "r"(b1));
}

// ---------------------------------------------------------------------------
// Input split: X -> fp16 hi/lo, weights -> fp16 (rounded)
// ---------------------------------------------------------------------------
#define N4_X  ((M_TOT * KDIM) / 4)
#define N4_WQ ((QDIM * KDIM) / 4)
#define N4_WKV ((KVDIM * KDIM) / 4)
#define N4_WO ((HH * KDIM) / 4)
#define N4_TOTAL (N4_X + N4_WQ + 2 * N4_WKV + N4_WO)

__global__ void split_inputs_kernel(const float* __restrict__ X,
                                    const float* __restrict__ Wq,
                                    const float* __restrict__ Wk,
                                    const float* __restrict__ Wv,
                                    const float* __restrict__ Wo) {
    int i = blockIdx.x * blockDim.x + threadIdx.x;
    if (i >= N4_TOTAL) return;
    if (i < N4_X) {
        float4 v = *(const float4*)(X + (size_t)i * 4);
        float x[4] = {v.x, v.y, v.z, v.w};
        __half h[4], l[4];
#pragma unroll
        for (int q = 0; q < 4; q++) split1h(x[q], h[q], l[q]);
        *(uint32_t*)(g_Xhi + (size_t)i * 4 + 0) = pack_h2(h[0], h[1]);
        *(uint32_t*)(g_Xhi + (size_t)i * 4 + 2) = pack_h2(h[2], h[3]);
        *(uint32_t*)(g_Xlo + (size_t)i * 4 + 0) = pack_h2(l[0], l[1]);
        *(uint32_t*)(g_Xlo + (size_t)i * 4 + 2) = pack_h2(l[2], l[3]);
        return;
    }
    const float* src;
    __half* dst;
    int off;
    if (i < N4_X + N4_WQ) {
        src = Wq; dst = g_Wqh; off = i - N4_X;
    } else if (i < N4_X + N4_WQ + N4_WKV) {
        src = Wk; dst = g_Wkh; off = i - N4_X - N4_WQ;
    } else if (i < N4_X + N4_WQ + 2 * N4_WKV) {
        src = Wv; dst = g_Wvh; off = i - N4_X - N4_WQ - N4_WKV;
    } else {
        src = Wo; dst = g_Woh; off = i - N4_X - N4_WQ - 2 * N4_WKV;
    }
    float4 v = *(const float4*)(src + (size_t)off * 4);
    *(uint32_t*)(dst + (size_t)off * 4 + 0) = pack_h2(__float2half_rn(v.x), __float2half_rn(v.y));
    *(uint32_t*)(dst + (size_t)off * 4 + 2) = pack_h2(__float2half_rn(v.z), __float2half_rn(v.w));
}

// ---------------------------------------------------------------------------
// fp16 2-term split GEMM: Y[m][n] = sum_k (Ahi+Alo)[m][k] * B[n][k]
// Block 128x128x32, 256 threads (8 warps: 2m x 4n), 3-stage cp.async pipeline.
// smem stage: Ahi 8K | Alo 8K | B 8K = 24K, x3 stages = 72K
// ---------------------------------------------------------------------------
#define STAGE16 24576
#define GEMM_SMEM (3 * STAGE16)
#define KT16 (KDIM / 32)   // 64

__device__ __forceinline__ uint32_t sw_off(int row, int k) {
    int c = (k >> 3) ^ (row & 3);
    return (uint32_t)((row * 4 + c) << 4);
}

__device__ __forceinline__ void load_stage16(uint32_t S, int buf,
                                             const __half* __restrict__ Ahi,
                                             const __half* __restrict__ Alo,
                                             const __half* __restrict__ B,
                                             int m0, int n0, int k0, int tid) {
    uint32_t st = S + buf * STAGE16;
#pragma unroll
    for (int l = 0; l < 2; l++) {
        int idx = tid + l * 256;          // 0..511 = 128 rows x 4 chunks
        int row = idx >> 2;
        int c = idx & 3;
        uint32_t spos = sw_off(row, c * 8);
        size_t ga = (size_t)(m0 + row) * KDIM + k0 + c * 8;
        size_t gb = (size_t)(n0 + row) * KDIM + k0 + c * 8;
        cp16(st + spos, Ahi + ga);
        cp16(st + 8192 + spos, Alo + ga);
        cp16(st + 16384 + spos, B + gb);
    }
    asm volatile("cp.async.commit_group;\n");
}

__device__ __forceinline__ void gemm_fp16_tile(const __half* __restrict__ Ahi,
                                               const __half* __restrict__ Alo,
                                               const __half* __restrict__ B,
                                               float* __restrict__ Y,
                                               int m0, int n0, int ldy) {
    extern __shared__ char smem_raw[];
    uint32_t S = (uint32_t)__cvta_generic_to_shared(smem_raw);

    int tid = threadIdx.x;
    int lane = tid & 31;
    int wid = tid >> 5;
    int wm = wid & 1;
    int wn = wid >> 1;
    int mid = lane >> 3, rin = lane & 7;

    float acc[4][4][4];
#pragma unroll
    for (int i = 0; i < 4; i++)
#pragma unroll
        for (int j = 0; j < 4; j++)
#pragma unroll
            for (int r = 0; r < 4; r++) acc[i][j][r] = 0.f;

    load_stage16(S, 0, Ahi, Alo, B, m0, n0, 0, tid);
    load_stage16(S, 1, Ahi, Alo, B, m0, n0, 32, tid);

    for (int kt = 0; kt < KT16; kt++) {
        if (kt < KT16 - 1)
            asm volatile("cp.async.wait_group 1;\n");
        else
            asm volatile("cp.async.wait_group 0;\n");
        __syncthreads();

        if (kt + 2 < KT16)
            load_stage16(S, (kt + 2) % 3, Ahi, Alo, B, m0, n0, (kt + 2) * 32, tid);

        uint32_t aHiB = S + (kt % 3) * STAGE16;
        uint32_t aLoB = aHiB + 8192;
        uint32_t bB = aHiB + 16384;

#pragma unroll
        for (int kk = 0; kk < 2; kk++) {
            uint32_t ah[4][4], al[4][4];
#pragma unroll
            for (int i = 0; i < 4; i++) {
                int m_l = wm * 64 + i * 16 + (mid & 1) * 8 + rin;
                int k_l = kk * 16 + (mid >> 1) * 8;
                uint32_t so = sw_off(m_l, k_l);
                ldsm4(ah[i], aHiB + so);
                ldsm4(al[i], aLoB + so);
            }
#pragma unroll
            for (int j2 = 0; j2 < 2; j2++) {
                uint32_t bh[4];
                int n_l = wn * 32 + (j2 * 2 + (mid >> 1)) * 8 + rin;
                int k_l = kk * 16 + (mid & 1) * 8;
                uint32_t so = sw_off(n_l, k_l);
                ldsm4(bh, bB + so);
#pragma unroll
                for (int jj = 0; jj < 2; jj++) {
                    int j = j2 * 2 + jj;
#pragma unroll
                    for (int i = 0; i < 4; i++) {
                        mma16816h(acc[i][j], ah[i], bh[jj * 2], bh[jj * 2 + 1]);
                        mma16816h(acc[i][j], al[i], bh[jj * 2], bh[jj * 2 + 1]);
                    }
                }
            }
        }
    }

#pragma unroll
    for (int i = 0; i < 4; i++) {
#pragma unroll
        for (int j = 0; j < 4; j++) {
            int r0 = m0 + wm * 64 + i * 16 + (lane >> 2);
            int cc = n0 + wn * 32 + j * 8 + (lane & 3) * 2;
            *(float2*)&Y[(size_t)r0 * ldy + cc] = make_float2(acc[i][j][0], acc[i][j][1]);
            *(float2*)&Y[(size_t)(r0 + 8) * ldy + cc] = make_float2(acc[i][j][2], acc[i][j][3]);
        }
    }
}

// Fused QKV projection: grid (24, 32). bx 0..15 -> Q, 16..19 -> K, 20..23 -> V
__global__ __launch_bounds__(256, 2) void qkv_gemm_kernel() {
    int bx = blockIdx.x;
    int m0 = blockIdx.y * 128;
    if (bx < 16)
        gemm_fp16_tile(g_Xhi, g_Xlo, g_Wqh, g_Q, m0, bx * 128, QDIM);
    else if (bx < 20)
        gemm_fp16_tile(g_Xhi, g_Xlo, g_Wkh, g_K, m0, (bx - 16) * 128, KVDIM);
    else
        gemm_fp16_tile(g_Xhi, g_Xlo, g_Wvh, g_V, m0, (bx - 20) * 128, KVDIM);
}

// Output projection: grid (16, 32)
__global__ __launch_bounds__(256, 2) void out_gemm_kernel(float* __restrict__ out) {
    gemm_fp16_tile(g_Ahi, g_Alo, g_Woh, out, blockIdx.y * 128, blockIdx.x * 128, HH);
}

// ---------------------------------------------------------------------------
// RoPE table + fused RoPE/convert/relayout (bf16 hi/lo for flash)
// ---------------------------------------------------------------------------
__global__ void rope_table_kernel() {
    int idx = blockIdx.x * blockDim.x + threadIdx.x;
    if (idx >= SS * 64) return;
    int pos = idx >> 6;
    int i = idx & 63;
    double inv = pow(10000.0, -(double)i / 64.0);
    double ang = (double)pos * inv;
    double sd, cd;
    sincos(ang, &sd, &cd);
    g_cos[idx] = (float)cd;
    g_sin[idx] = (float)sd;
}

#define RC_Q (M_TOT * NH * 64)
#define RC_K (M_TOT * NKV * 64)
#define RC_V (M_TOT * NKV * 64)

__global__ void rope_convert_kernel() {
    int idx = blockIdx.x * blockDim.x + threadIdx.x;
    if (idx >= RC_Q + RC_K + RC_V) return;

    if (idx < RC_Q) {
        int m = idx / (NH * 64);
        int r = idx - m * (NH * 64);
        int h = r >> 6, d = r & 63;
        int b = m >> 11, s = m & (SS - 1);
        float x1 = g_Q[(size_t)m * QDIM + h * HD + d];
        float x2 = g_Q[(size_t)m * QDIM + h * HD + d + 64];
        float c = g_cos[s * 64 + d], sn = g_sin[s * 64 + d];
        float y1 = x1 * c - x2 * sn;
        float y2 = x2 * c + x1 * sn;
        size_t dst = ((size_t)(b * NH + h) * SS + s) * HD + d;
        __nv_bfloat16 h1, l1, h2, l2;
        split1(y1, h1, l1);
        split1(y2, h2, l2);
        g_Qbhi[dst] = h1; g_Qblo[dst] = l1;
        g_Qbhi[dst + 64] = h2; g_Qblo[dst + 64] = l2;
    } else if (idx < RC_Q + RC_K) {
        int e = idx - RC_Q;
        int m = e / (NKV * 64);
        int r = e - m * (NKV * 64);
        int h = r >> 6, d = r & 63;
        int b = m >> 11, s = m & (SS - 1);
        float x1 = g_K[(size_t)m * KVDIM + h * HD + d];
        float x2 = g_K[(size_t)m * KVDIM + h * HD + d + 64];
        float c = g_cos[s * 64 + d], sn = g_sin[s * 64 + d];
        float y1 = x1 * c - x2 * sn;
        float y2 = x2 * c + x1 * sn;
        size_t dst = ((size_t)(b * NKV + h) * SS + s) * HD + d;
        __nv_bfloat16 h1, l1, h2, l2;
        split1(y1, h1, l1);
        split1(y2, h2, l2);
        g_Kbhi[dst] = h1; g_Kblo[dst] = l1;
        g_Kbhi[dst + 64] = h2; g_Kblo[dst + 64] = l2;
    } else {
        int e = idx - RC_Q - RC_K;
        int m = e / (NKV * 64);
        int r = e - m * (NKV * 64);
        int h = r >> 6, d = r & 63;
        int b = m >> 11, s = m & (SS - 1);
        float x1 = g_V[(size_t)m * KVDIM + h * HD + d];
        float x2 = g_V[(size_t)m * KVDIM + h * HD + d + 64];
        size_t dst = ((size_t)(b * NKV + h) * SS + s) * HD + d;
        __nv_bfloat16 h1, l1, h2, l2;
        split1(x1, h1, l1);
        split1(x2, h2, l2);
        g_Vbhi[dst] = h1; g_Vblo[dst] = l1;
        g_Vbhi[dst + 64] = h2; g_Vblo[dst + 64] = l2;
    }
}

// ---------------------------------------------------------------------------
// Tensor-core flash attention (causal, bf16 3-term split), BQ=128, BKV=64
// ---------------------------------------------------------------------------
#define FQ 128
#define FK 64
#define FLASH_SMEM (65536 + 2 * 65536)   // 192 KB

__device__ __forceinline__ uint32_t sw256(int row, int chunk) {
    return (uint32_t)(row * 256 + ((chunk ^ (row & 7)) << 4));
}

__device__ __forceinline__ void flash_load_kv(uint32_t sb, int t, int st,
                                              const __nv_bfloat16* Kh, const __nv_bfloat16* Kl,
                                              const __nv_bfloat16* Vh, const __nv_bfloat16* Vl,
                                              int tid) {
    uint32_t base = sb + 65536 + st * 65536;
    size_t g0 = (size_t)t * FK * HD;
#pragma unroll
    for (int l = 0; l < 4; l++) {
        int idx = tid + l * 256;
        int row = idx >> 4;
        int c = idx & 15;
        uint32_t off = sw256(row, c);
        size_t go = g0 + (size_t)row * HD + c * 8;
        cp16(base + off, Kh + go);
        cp16(base + 16384 + off, Kl + go);
        cp16(base + 32768 + off, Vh + go);
        cp16(base + 49152 + off, Vl + go);
    }
}

__global__ __launch_bounds__(256) void flash_tc_kernel() {
    extern __shared__ char smem_raw[];
    uint32_t sb = (uint32_t)__cvta_generic_to_shared(smem_raw);
    uint32_t Qhi_s = sb, Qlo_s = sb + 32768;

    int qt = (int)(gridDim.x - 1 - blockIdx.x);
    int h = blockIdx.y, b = blockIdx.z;
    int q0 = qt * FQ;
    int kh = h / GROUPS;

    int tid = threadIdx.x, lane = tid & 31, wid = tid >> 5;
    int mid = lane >> 3, rin = lane & 7;

    const __nv_bfloat16* Qhig = g_Qbhi + ((size_t)(b * NH + h) * SS + q0) * HD;
    const __nv_bfloat16* Qlog = g_Qblo + ((size_t)(b * NH + h) * SS + q0) * HD;
    const __nv_bfloat16* Khg = g_Kbhi + (size_t)(b * NKV + kh) * SS * HD;
    const __nv_bfloat16* Klg = g_Kblo + (size_t)(b * NKV + kh) * SS * HD;
    const __nv_bfloat16* Vhg = g_Vbhi + (size_t)(b * NKV + kh) * SS * HD;
    const __nv_bfloat16* Vlg = g_Vblo + (size_t)(b * NKV + kh) * SS * HD;

#pragma unroll
    for (int l = 0; l < 8; l++) {
        int idx = tid + l * 256;
        int row = idx >> 4;
        int c = idx & 15;
        uint32_t off = sw256(row, c);
        size_t go = (size_t)row * HD + c * 8;
        cp16(Qhi_s + off, Qhig + go);
        cp16(Qlo_s + off, Qlog + go);
    }
    flash_load_kv(sb, 0, 0, Khg, Klg, Vhg, Vlg, tid);
    asm volatile("cp.async.commit_group;\n");

    float m_lo = -1e30f, m_hi = -1e30f, l_lo = 0.f, l_hi = 0.f;
    float oacc[16][4];
#pragma unroll
    for (int v = 0; v < 16; v++)
#pragma unroll
        for (int r = 0; r < 4; r++) oacc[v][r] = 0.f;

    const float scale = 0.08838834764831845f;
    const int ntile = 2 * qt + 2;
    const int rlo = q0 + wid * 16 + (lane >> 2);
    const int rhi = rlo + 8;

    for (int t = 0; t < ntile; t++) {
        int buf = t & 1;
        if (t + 1 < ntile) {
            flash_load_kv(sb, t + 1, buf ^ 1, Khg, Klg, Vhg, Vlg, tid);
            asm volatile("cp.async.commit_group;\n");
            asm volatile("cp.async.wait_group 1;\n");
        } else {
            asm volatile("cp.async.wait_group 0;\n");
        }
        __syncthreads();

        uint32_t kbh = sb + 65536 + buf * 65536;
        uint32_t kbl = kbh + 16384;
        uint32_t vbh = kbh + 32768;
        uint32_t vbl = kbh + 49152;

        float sacc[8][4];
#pragma unroll
        for (int n = 0; n < 8; n++)
#pragma unroll
            for (int r = 0; r < 4; r++) sacc[n][r] = 0.f;

#pragma unroll
        for (int kk = 0; kk < 8; kk++) {
            uint32_t ah[4], al[4];
            {
                int m_l = wid * 16 + (mid & 1) * 8 + rin;
                int chnk = kk * 2 + (mid >> 1);
                uint32_t so = sw256(m_l, chnk);
                ldsm4(ah, Qhi_s + so);
                ldsm4(al, Qlo_s + so);
            }
#pragma unroll
            for (int j2 = 0; j2 < 4; j2++) {
                uint32_t bh[4], bl[4];
                int n_l = (j2 * 2 + (mid >> 1)) * 8 + rin;
                int chnk = kk * 2 + (mid & 1);
                uint32_t so = sw256(n_l, chnk);
                ldsm4(bh, kbh + so);
                ldsm4(bl, kbl + so);
#pragma unroll
                for (int jj = 0; jj < 2; jj++) {
                    int j = j2 * 2 + jj;
                    mma16816(sacc[j], ah, bh[jj * 2], bh[jj * 2 + 1]);
                    mma16816(sacc[j], ah, bl[jj * 2], bl[jj * 2 + 1]);
                    mma16816(sacc[j], al, bh[jj * 2], bh[jj * 2 + 1]);
                }
            }
        }

        int k0 = t * FK;
        bool diag = (t >= 2 * qt);
#pragma unroll
        for (int n = 0; n < 8; n++) {
            int c0 = k0 + n * 8 + (lane & 3) * 2;
            sacc[n][0] *= scale;
            sacc[n][1] *= scale;
            sacc[n][2] *= scale;
            sacc[n][3] *= scale;
            if (diag) {
                if (c0 > rlo) sacc[n][0] = -1e30f;
                if (c0 + 1 > rlo) sacc[n][1] = -1e30f;
                if (c0 > rhi) sacc[n][2] = -1e30f;
                if (c0 + 1 > rhi) sacc[n][3] = -1e30f;
            }
        }

        float mx0 = -1e30f, mx1 = -1e30f;
#pragma unroll
        for (int n = 0; n < 8; n++) {
            mx0 = fmaxf(mx0, fmaxf(sacc[n][0], sacc[n][1]));
            mx1 = fmaxf(mx1, fmaxf(sacc[n][2], sacc[n][3]));
        }
        mx0 = fmaxf(mx0, __shfl_xor_sync(0xffffffffu, mx0, 1));
        mx0 = fmaxf(mx0, __shfl_xor_sync(0xffffffffu, mx0, 2));
        mx1 = fmaxf(mx1, __shfl_xor_sync(0xffffffffu, mx1, 1));
        mx1 = fmaxf(mx1, __shfl_xor_sync(0xffffffffu, mx1, 2));
        float newm0 = fmaxf(m_lo, mx0);
        float newm1 = fmaxf(m_hi, mx1);
        float corr0 = __expf(m_lo - newm0);
        float corr1 = __expf(m_hi - newm1);
        m_lo = newm0;
        m_hi = newm1;

        float ls0 = 0.f, ls1 = 0.f;
#pragma unroll
        for (int n = 0; n < 8; n++) {
            sacc[n][0] = __expf(sacc[n][0] - newm0);
            sacc[n][1] = __expf(sacc[n][1] - newm0);
            sacc[n][2] = __expf(sacc[n][2] - newm1);
            sacc[n][3] = __expf(sacc[n][3] - newm1);
            ls0 += sacc[n][0] + sacc[n][1];
            ls1 += sacc[n][2] + sacc[n][3];
        }
        ls0 += __shfl_xor_sync(0xffffffffu, ls0, 1);
        ls0 += __shfl_xor_sync(0xffffffffu, ls0, 2);
        ls1 += __shfl_xor_sync(0xffffffffu, ls1, 1);
        ls1 += __shfl_xor_sync(0xffffffffu, ls1, 2);
        l_lo = l_lo * corr0 + ls0;
        l_hi = l_hi * corr1 + ls1;

#pragma unroll
        for (int v = 0; v < 16; v++) {
            oacc[v][0] *= corr0;
            oacc[v][1] *= corr0;
            oacc[v][2] *= corr1;
            oacc[v][3] *= corr1;
        }

#pragma unroll
        for (int kk = 0; kk < 4; kk++) {
            uint32_t aph[4], apl[4];
            {
                __nv_bfloat16 h0, l0, h1, l1;
                split1(sacc[2 * kk][0], h0, l0);
                split1(sacc[2 * kk][1], h1, l1);
                aph[0] = pack_bf2(h0, h1);
                apl[0] = pack_bf2(l0, l1);
                split1(sacc[2 * kk][2], h0, l0);
                split1(sacc[2 * kk][3], h1, l1);
                aph[1] = pack_bf2(h0, h1);
                apl[1] = pack_bf2(l0, l1);
                split1(sacc[2 * kk + 1][0], h0, l0);
                split1(sacc[2 * kk + 1][1], h1, l1);
                aph[2] = pack_bf2(h0, h1);
                apl[2] = pack_bf2(l0, l1);
                split1(sacc[2 * kk + 1][2], h0, l0);
                split1(sacc[2 * kk + 1][3], h1, l1);
                aph[3] = pack_bf2(h0, h1);
                apl[3] = pack_bf2(l0, l1);
            }
#pragma unroll
            for (int v2 = 0; v2 < 8; v2++) {
                int g = lane >> 3;
                int row = kk * 16 + (g & 1) * 8 + rin;
                int chnk = v2 * 2 + (g >> 1);
                uint32_t so = sw256(row, chnk);
                uint32_t vh[4], vl[4];
                ldsm4t(vh, vbh + so);
                ldsm4t(vl, vbl + so);
#pragma unroll
                for (int gg = 0; gg < 2; gg++) {
                    int vnt = v2 * 2 + gg;
                    mma16816(oacc[vnt], aph, vh[gg * 2], vh[gg * 2 + 1]);
                    mma16816(oacc[vnt], aph, vl[gg * 2], vl[gg * 2 + 1]);
                    mma16816(oacc[vnt], apl, vh[gg * 2], vh[gg * 2 + 1]);
                }
            }
        }
        __syncthreads();
    }

    // epilogue: normalize, write fp16 hi/lo to g_Ahi/g_Alo for the out-proj
    float inv0 = 1.f / l_lo;
    float inv1 = 1.f / l_hi;
    int row0 = b * SS + q0 + wid * 16 + (lane >> 2);
    int row1 = row0 + 8;
#pragma unroll
    for (int v = 0; v < 16; v++) {
        int col = h * HD + v * 8 + (lane & 3) * 2;
        float o0 = oacc[v][0] * inv0, o1 = oacc[v][1] * inv0;
        float o2 = oacc[v][2] * inv1, o3 = oacc[v][3] * inv1;
        __half h0, l0, h1, l1;
        split1h(o0, h0, l0);
        split1h(o1, h1, l1);
        *(uint32_t*)(g_Ahi + (size_t)row0 * KDIM + col) = pack_h2(h0, h1);
        *(uint32_t*)(g_Alo + (size_t)row0 * KDIM + col) = pack_h2(l0, l1);
        split1h(o2, h0, l0);
        split1h(o3, h1, l1);
        *(uint32_t*)(g_Ahi + (size_t)row1 * KDIM + col) = pack_h2(h0, h1);
        *(uint32_t*)(g_Alo + (size_t)row1 * KDIM + col) = pack_h2(l0, l1);
    }
}

// ---------------------------------------------------------------------------
extern "C" void kernel_launch(void* const* d_in, const int* in_sizes, int n_in,
                              void* d_out, int out_size) {
    const float* X = (const float*)d_in[0];
    const float* Wq = (const float*)d_in[1];
    const float* Wk = (const float*)d_in[2];
    const float* Wv = (const float*)d_in[3];
    const float* Wo = (const float*)d_in[4];
    float* out = (float*)d_out;

    // 0. Split inputs
    split_inputs_kernel<<<(N4_TOTAL + 255) / 256, 256>>>(X, Wq, Wk, Wv, Wo);

    // 1. QKV projections (fp16 2-term, mma.sync)
    cudaFuncSetAttribute(qkv_gemm_kernel, cudaFuncAttributeMaxDynamicSharedMemorySize,
                         GEMM_SMEM);
    qkv_gemm_kernel<<<dim3(24, 32), 256, GEMM_SMEM>>>();

    // 2. RoPE table + fused rope/convert/relayout
    rope_table_kernel<<<(SS * 64 + 255) / 256, 256>>>();
    {
        int total = RC_Q + RC_K + RC_V;
        rope_convert_kernel<<<(total + 255) / 256, 256>>>();
    }

    // 3. Tensor-core flash attention (bf16 3-term)
    cudaFuncSetAttribute(flash_tc_kernel, cudaFuncAttributeMaxDynamicSharedMemorySize,
                         FLASH_SMEM);
    flash_tc_kernel<<<dim3(SS / FQ, NH, BB), 256, FLASH_SMEM>>>();

    // 4. Output projection (fp16 2-term, mma.sync)
    cudaFuncSetAttribute(out_gemm_kernel, cudaFuncAttributeMaxDynamicSharedMemorySize,
                         GEMM_SMEM);
    out_gemm_kernel<<<dim3(16, 32), 256, GEMM_SMEM>>>(out);
}

// round 6
// speedup vs baseline: 6.0032x; 1.3230x over previous
#include <cuda_runtime.h>
#include <cuda_bf16.h>
#include <cuda_fp16.h>
#include <math.h>
#include <stdint.h>

// Problem constants
#define BB 2
#define SS 2048
#define HH 2048
#define NH 16
#define NKV 4
#define HD 128
#define GROUPS (NH / NKV)        // 4
#define M_TOT (BB * SS)          // 4096
#define QDIM (NH * HD)           // 2048
#define KVDIM (NKV * HD)         // 512
#define KDIM 2048                // GEMM reduction dim

// fp32 scratch (pre-RoPE projections)
__device__ __align__(16) float g_Q[M_TOT * QDIM];
__device__ __align__(16) float g_K[M_TOT * KVDIM];
__device__ __align__(16) float g_V[M_TOT * KVDIM];
__device__ float g_cos[SS * 64];
__device__ float g_sin[SS * 64];

// fp16 buffers
__device__ __align__(16) __half g_Xh[M_TOT * KDIM];                  // X rounded (1-term)
__device__ __align__(16) __half g_Wqh[QDIM * KDIM];
__device__ __align__(16) __half g_Wkh[KVDIM * KDIM];
__device__ __align__(16) __half g_Wvh[KVDIM * KDIM];
__device__ __align__(16) __half g_Woh[HH * KDIM];
__device__ __align__(16) __half g_Ahi[M_TOT * KDIM], g_Alo[M_TOT * KDIM];  // flash out 2-term

// fp16 head-major buffers for flash: [b, h, s, d]
__device__ __align__(16) __half g_Qbhi[M_TOT * QDIM], g_Qblo[M_TOT * QDIM];  // Q 2-term
__device__ __align__(16) __half g_Kb[M_TOT * KVDIM];                          // K 1-term
__device__ __align__(16) __half g_Vb[M_TOT * KVDIM];                          // V 1-term

// ---------------------------------------------------------------------------
// Helpers
// ---------------------------------------------------------------------------
__device__ __forceinline__ void split1h(float x, __half& h, __half& l) {
    h = __float2half_rn(x);
    l = __float2half_rn(x - __half2float(h));
}
__device__ __forceinline__ uint32_t pack_h2(__half a, __half b) {
    __half2 t(a, b);
    return *(uint32_t*)&t;
}
__device__ __forceinline__ void cp16(uint32_t saddr, const void* gaddr) {
    asm volatile("cp.async.cg.shared.global [%0], [%1], 16;\n" ::"r"(saddr), "l"(gaddr));
}
__device__ __forceinline__ void ldsm4(uint32_t* r, uint32_t addr) {
    asm volatile("ldmatrix.sync.aligned.m8n8.x4.shared.b16 {%0,%1,%2,%3}, [%4];\n"
                 : "=r"(r[0]), "=r"(r[1]), "=r"(r[2]), "=r"(r[3]) : "r"(addr));
}
__device__ __forceinline__ void ldsm4t(uint32_t* r, uint32_t addr) {
    asm volatile("ldmatrix.sync.aligned.m8n8.x4.trans.shared.b16 {%0,%1,%2,%3}, [%4];\n"
                 : "=r"(r[0]), "=r"(r[1]), "=r"(r[2]), "=r"(r[3]) : "r"(addr));
}
// fp16 mma
__device__ __forceinline__ void mma16816h(float* c, const uint32_t* a, uint32_t b0, uint32_t b1) {
    asm volatile("mma.sync.aligned.m16n8k16.row.col.f32.f16.f16.f32 "
                 "{%0,%1,%2,%3}, {%4,%5,%6,%7}, {%8,%9}, {%0,%1,%2,%3};\n"
                 : "+f"(c[0]), "+f"(c[1]), "+f"(c[2]), "+f"(c[3])
                 : "r"(a[0]), "r"(a[1]), "r"(a[2]), "r"(a[3]), "r"(b0), "r"(b1));
}

// ---------------------------------------------------------------------------
// Input split: X -> fp16, weights -> fp16 (all rounded)
// ---------------------------------------------------------------------------
#define N4_X  ((M_TOT * KDIM) / 4)
#define N4_WQ ((QDIM * KDIM) / 4)
#define N4_WKV ((KVDIM * KDIM) / 4)
#define N4_WO ((HH * KDIM) / 4)
#define N4_TOTAL (N4_X + N4_WQ + 2 * N4_WKV + N4_WO)

__global__ void split_inputs_kernel(const float* __restrict__ X,
                                    const float* __restrict__ Wq,
                                    const float* __restrict__ Wk,
                                    const float* __restrict__ Wv,
                                    const float* __restrict__ Wo) {
    int i = blockIdx.x * blockDim.x + threadIdx.x;
    if (i >= N4_TOTAL) return;
    const float* src;
    __half* dst;
    int off;
    if (i < N4_X) {
        src = X; dst = g_Xh; off = i;
    } else if (i < N4_X + N4_WQ) {
        src = Wq; dst = g_Wqh; off = i - N4_X;
    } else if (i < N4_X + N4_WQ + N4_WKV) {
        src = Wk; dst = g_Wkh; off = i - N4_X - N4_WQ;
    } else if (i < N4_X + N4_WQ + 2 * N4_WKV) {
        src = Wv; dst = g_Wvh; off = i - N4_X - N4_WQ - N4_WKV;
    } else {
        src = Wo; dst = g_Woh; off = i - N4_X - N4_WQ - 2 * N4_WKV;
    }
    float4 v = *(const float4*)(src + (size_t)off * 4);
    *(uint32_t*)(dst + (size_t)off * 4 + 0) = pack_h2(__float2half_rn(v.x), __float2half_rn(v.y));
    *(uint32_t*)(dst + (size_t)off * 4 + 2) = pack_h2(__float2half_rn(v.z), __float2half_rn(v.w));
}

// ---------------------------------------------------------------------------
// Shared GEMM smem swizzle (32-K chunks, 64B rows of fp16)
// ---------------------------------------------------------------------------
__device__ __forceinline__ uint32_t sw_off(int row, int k) {
    int c = (k >> 3) ^ (row & 3);
    return (uint32_t)((row * 4 + c) << 4);
}

// ---------------------------------------------------------------------------
// 1-term fp16 GEMM (QKV): Y[m][n] = sum_k A[m][k] * B[n][k]
// Block 128x128x32, 8 warps, 3-stage. Stage: A 8K | B 8K = 16K.
// ---------------------------------------------------------------------------
#define STAGE1T 16384
#define GEMM1T_SMEM (3 * STAGE1T)
#define KT16 (KDIM / 32)   // 64

__device__ __forceinline__ void load_stage1t(uint32_t S, int buf,
                                             const __half* __restrict__ A,
                                             const __half* __restrict__ B,
                                             int m0, int n0, int k0, int tid) {
    uint32_t st = S + buf * STAGE1T;
#pragma unroll
    for (int l = 0; l < 2; l++) {
        int idx = tid + l * 256;          // 0..511 = 128 rows x 4 chunks
        int row = idx >> 2;
        int c = idx & 3;
        uint32_t spos = sw_off(row, c * 8);
        size_t ga = (size_t)(m0 + row) * KDIM + k0 + c * 8;
        size_t gb = (size_t)(n0 + row) * KDIM + k0 + c * 8;
        cp16(st + spos, A + ga);
        cp16(st + 8192 + spos, B + gb);
    }
    asm volatile("cp.async.commit_group;\n");
}

__device__ __forceinline__ void gemm_fp16_1t(const __half* __restrict__ A,
                                             const __half* __restrict__ B,
                                             float* __restrict__ Y,
                                             int m0, int n0, int ldy) {
    extern __shared__ char smem_raw[];
    uint32_t S = (uint32_t)__cvta_generic_to_shared(smem_raw);

    int tid = threadIdx.x;
    int lane = tid & 31;
    int wid = tid >> 5;
    int wm = wid & 1;
    int wn = wid >> 1;
    int mid = lane >> 3, rin = lane & 7;

    float acc[4][4][4];
#pragma unroll
    for (int i = 0; i < 4; i++)
#pragma unroll
        for (int j = 0; j < 4; j++)
#pragma unroll
            for (int r = 0; r < 4; r++) acc[i][j][r] = 0.f;

    load_stage1t(S, 0, A, B, m0, n0, 0, tid);
    load_stage1t(S, 1, A, B, m0, n0, 32, tid);

    for (int kt = 0; kt < KT16; kt++) {
        if (kt < KT16 - 1)
            asm volatile("cp.async.wait_group 1;\n");
        else
            asm volatile("cp.async.wait_group 0;\n");
        __syncthreads();

        if (kt + 2 < KT16)
            load_stage1t(S, (kt + 2) % 3, A, B, m0, n0, (kt + 2) * 32, tid);

        uint32_t aB = S + (kt % 3) * STAGE1T;
        uint32_t bB = aB + 8192;

#pragma unroll
        for (int kk = 0; kk < 2; kk++) {
            uint32_t ah[4][4];
#pragma unroll
            for (int i = 0; i < 4; i++) {
                int m_l = wm * 64 + i * 16 + (mid & 1) * 8 + rin;
                int k_l = kk * 16 + (mid >> 1) * 8;
                ldsm4(ah[i], aB + sw_off(m_l, k_l));
            }
#pragma unroll
            for (int j2 = 0; j2 < 2; j2++) {
                uint32_t bh[4];
                int n_l = wn * 32 + (j2 * 2 + (mid >> 1)) * 8 + rin;
                int k_l = kk * 16 + (mid & 1) * 8;
                ldsm4(bh, bB + sw_off(n_l, k_l));
#pragma unroll
                for (int jj = 0; jj < 2; jj++) {
                    int j = j2 * 2 + jj;
#pragma unroll
                    for (int i = 0; i < 4; i++)
                        mma16816h(acc[i][j], ah[i], bh[jj * 2], bh[jj * 2 + 1]);
                }
            }
        }
    }

#pragma unroll
    for (int i = 0; i < 4; i++) {
#pragma unroll
        for (int j = 0; j < 4; j++) {
            int r0 = m0 + wm * 64 + i * 16 + (lane >> 2);
            int cc = n0 + wn * 32 + j * 8 + (lane & 3) * 2;
            *(float2*)&Y[(size_t)r0 * ldy + cc] = make_float2(acc[i][j][0], acc[i][j][1]);
            *(float2*)&Y[(size_t)(r0 + 8) * ldy + cc] = make_float2(acc[i][j][2], acc[i][j][3]);
        }
    }
}

__global__ __launch_bounds__(256, 2) void qkv_gemm_kernel() {
    int bx = blockIdx.x;
    int m0 = blockIdx.y * 128;
    if (bx < 16)
        gemm_fp16_1t(g_Xh, g_Wqh, g_Q, m0, bx * 128, QDIM);
    else if (bx < 20)
        gemm_fp16_1t(g_Xh, g_Wkh, g_K, m0, (bx - 16) * 128, KVDIM);
    else
        gemm_fp16_1t(g_Xh, g_Wvh, g_V, m0, (bx - 20) * 128, KVDIM);
}

// ---------------------------------------------------------------------------
// 2-term fp16 GEMM (out-proj): Y = (Ahi+Alo) * B^T
// Stage: Ahi 8K | Alo 8K | B 8K = 24K, x3.
// ---------------------------------------------------------------------------
#define STAGE16 24576
#define GEMM_SMEM (3 * STAGE16)

__device__ __forceinline__ void load_stage16(uint32_t S, int buf,
                                             const __half* __restrict__ Ahi,
                                             const __half* __restrict__ Alo,
                                             const __half* __restrict__ B,
                                             int m0, int n0, int k0, int tid) {
    uint32_t st = S + buf * STAGE16;
#pragma unroll
    for (int l = 0; l < 2; l++) {
        int idx = tid + l * 256;
        int row = idx >> 2;
        int c = idx & 3;
        uint32_t spos = sw_off(row, c * 8);
        size_t ga = (size_t)(m0 + row) * KDIM + k0 + c * 8;
        size_t gb = (size_t)(n0 + row) * KDIM + k0 + c * 8;
        cp16(st + spos, Ahi + ga);
        cp16(st + 8192 + spos, Alo + ga);
        cp16(st + 16384 + spos, B + gb);
    }
    asm volatile("cp.async.commit_group;\n");
}

__global__ __launch_bounds__(256, 2) void out_gemm_kernel(float* __restrict__ out) {
    extern __shared__ char smem_raw[];
    uint32_t S = (uint32_t)__cvta_generic_to_shared(smem_raw);
    int m0 = blockIdx.y * 128, n0 = blockIdx.x * 128, ldy = HH;

    int tid = threadIdx.x;
    int lane = tid & 31;
    int wid = tid >> 5;
    int wm = wid & 1;
    int wn = wid >> 1;
    int mid = lane >> 3, rin = lane & 7;

    float acc[4][4][4];
#pragma unroll
    for (int i = 0; i < 4; i++)
#pragma unroll
        for (int j = 0; j < 4; j++)
#pragma unroll
            for (int r = 0; r < 4; r++) acc[i][j][r] = 0.f;

    load_stage16(S, 0, g_Ahi, g_Alo, g_Woh, m0, n0, 0, tid);
    load_stage16(S, 1, g_Ahi, g_Alo, g_Woh, m0, n0, 32, tid);

    for (int kt = 0; kt < KT16; kt++) {
        if (kt < KT16 - 1)
            asm volatile("cp.async.wait_group 1;\n");
        else
            asm volatile("cp.async.wait_group 0;\n");
        __syncthreads();

        if (kt + 2 < KT16)
            load_stage16(S, (kt + 2) % 3, g_Ahi, g_Alo, g_Woh, m0, n0, (kt + 2) * 32, tid);

        uint32_t aHiB = S + (kt % 3) * STAGE16;
        uint32_t aLoB = aHiB + 8192;
        uint32_t bB = aHiB + 16384;

#pragma unroll
        for (int kk = 0; kk < 2; kk++) {
            uint32_t ah[4][4], al[4][4];
#pragma unroll
            for (int i = 0; i < 4; i++) {
                int m_l = wm * 64 + i * 16 + (mid & 1) * 8 + rin;
                int k_l = kk * 16 + (mid >> 1) * 8;
                uint32_t so = sw_off(m_l, k_l);
                ldsm4(ah[i], aHiB + so);
                ldsm4(al[i], aLoB + so);
            }
#pragma unroll
            for (int j2 = 0; j2 < 2; j2++) {
                uint32_t bh[4];
                int n_l = wn * 32 + (j2 * 2 + (mid >> 1)) * 8 + rin;
                int k_l = kk * 16 + (mid & 1) * 8;
                ldsm4(bh, bB + sw_off(n_l, k_l));
#pragma unroll
                for (int jj = 0; jj < 2; jj++) {
                    int j = j2 * 2 + jj;
#pragma unroll
                    for (int i = 0; i < 4; i++) {
                        mma16816h(acc[i][j], ah[i], bh[jj * 2], bh[jj * 2 + 1]);
                        mma16816h(acc[i][j], al[i], bh[jj * 2], bh[jj * 2 + 1]);
                    }
                }
            }
        }
    }

#pragma unroll
    for (int i = 0; i < 4; i++) {
#pragma unroll
        for (int j = 0; j < 4; j++) {
            int r0 = m0 + wm * 64 + i * 16 + (lane >> 2);
            int cc = n0 + wn * 32 + j * 8 + (lane & 3) * 2;
            *(float2*)&out[(size_t)r0 * ldy + cc] = make_float2(acc[i][j][0], acc[i][j][1]);
            *(float2*)&out[(size_t)(r0 + 8) * ldy + cc] = make_float2(acc[i][j][2], acc[i][j][3]);
        }
    }
}

// ---------------------------------------------------------------------------
// RoPE table + fused RoPE/convert/relayout (fp16: Q hi/lo, K/V rounded)
// ---------------------------------------------------------------------------
__global__ void rope_table_kernel() {
    int idx = blockIdx.x * blockDim.x + threadIdx.x;
    if (idx >= SS * 64) return;
    int pos = idx >> 6;
    int i = idx & 63;
    double inv = pow(10000.0, -(double)i / 64.0);
    double ang = (double)pos * inv;
    double sd, cd;
    sincos(ang, &sd, &cd);
    g_cos[idx] = (float)cd;
    g_sin[idx] = (float)sd;
}

#define RC_Q (M_TOT * NH * 64)
#define RC_K (M_TOT * NKV * 64)
#define RC_V (M_TOT * NKV * 64)

__global__ void rope_convert_kernel() {
    int idx = blockIdx.x * blockDim.x + threadIdx.x;
    if (idx >= RC_Q + RC_K + RC_V) return;

    if (idx < RC_Q) {
        int m = idx / (NH * 64);
        int r = idx - m * (NH * 64);
        int h = r >> 6, d = r & 63;
        int b = m >> 11, s = m & (SS - 1);
        float x1 = g_Q[(size_t)m * QDIM + h * HD + d];
        float x2 = g_Q[(size_t)m * QDIM + h * HD + d + 64];
        float c = g_cos[s * 64 + d], sn = g_sin[s * 64 + d];
        float y1 = x1 * c - x2 * sn;
        float y2 = x2 * c + x1 * sn;
        size_t dst = ((size_t)(b * NH + h) * SS + s) * HD + d;
        __half h1, l1, h2, l2;
        split1h(y1, h1, l1);
        split1h(y2, h2, l2);
        g_Qbhi[dst] = h1; g_Qblo[dst] = l1;
        g_Qbhi[dst + 64] = h2; g_Qblo[dst + 64] = l2;
    } else if (idx < RC_Q + RC_K) {
        int e = idx - RC_Q;
        int m = e / (NKV * 64);
        int r = e - m * (NKV * 64);
        int h = r >> 6, d = r & 63;
        int b = m >> 11, s = m & (SS - 1);
        float x1 = g_K[(size_t)m * KVDIM + h * HD + d];
        float x2 = g_K[(size_t)m * KVDIM + h * HD + d + 64];
        float c = g_cos[s * 64 + d], sn = g_sin[s * 64 + d];
        float y1 = x1 * c - x2 * sn;
        float y2 = x2 * c + x1 * sn;
        size_t dst = ((size_t)(b * NKV + h) * SS + s) * HD + d;
        g_Kb[dst] = __float2half_rn(y1);
        g_Kb[dst + 64] = __float2half_rn(y2);
    } else {
        int e = idx - RC_Q - RC_K;
        int m = e / (NKV * 64);
        int r = e - m * (NKV * 64);
        int h = r >> 6, d = r & 63;
        int b = m >> 11, s = m & (SS - 1);
        float x1 = g_V[(size_t)m * KVDIM + h * HD + d];
        float x2 = g_V[(size_t)m * KVDIM + h * HD + d + 64];
        size_t dst = ((size_t)(b * NKV + h) * SS + s) * HD + d;
        g_Vb[dst] = __float2half_rn(x1);
        g_Vb[dst + 64] = __float2half_rn(x2);
    }
}

// ---------------------------------------------------------------------------
// fp16 flash attention (causal): Q 2-term, K/V 1-term. BQ=128, BKV=64
// smem: Qhi 32K | Qlo 32K | stage{0,1}: K 16K | V 16K  -> 128 KB
// ---------------------------------------------------------------------------
#define FQ 128
#define FK 64
#define FLASH_SMEM (65536 + 2 * 32768)

__device__ __forceinline__ uint32_t sw256(int row, int chunk) {
    return (uint32_t)(row * 256 + ((chunk ^ (row & 7)) << 4));
}

__device__ __forceinline__ void flash_load_kv(uint32_t sb, int t, int st,
                                              const __half* Kh, const __half* Vh, int tid) {
    uint32_t base = sb + 65536 + st * 32768;
    size_t g0 = (size_t)t * FK * HD;
#pragma unroll
    for (int l = 0; l < 4; l++) {
        int idx = tid + l * 256;      // 0..1023 = 64 rows x 16 chunks
        int row = idx >> 4;
        int c = idx & 15;
        uint32_t off = sw256(row, c);
        size_t go = g0 + (size_t)row * HD + c * 8;
        cp16(base + off, Kh + go);
        cp16(base + 16384 + off, Vh + go);
    }
}

__global__ __launch_bounds__(256) void flash_tc_kernel() {
    extern __shared__ char smem_raw[];
    uint32_t sb = (uint32_t)__cvta_generic_to_shared(smem_raw);
    uint32_t Qhi_s = sb, Qlo_s = sb + 32768;

    int qt = (int)(gridDim.x - 1 - blockIdx.x);
    int h = blockIdx.y, b = blockIdx.z;
    int q0 = qt * FQ;
    int kh = h / GROUPS;

    int tid = threadIdx.x, lane = tid & 31, wid = tid >> 5;
    int mid = lane >> 3, rin = lane & 7;

    const __half* Qhig = g_Qbhi + ((size_t)(b * NH + h) * SS + q0) * HD;
    const __half* Qlog = g_Qblo + ((size_t)(b * NH + h) * SS + q0) * HD;
    const __half* Khg = g_Kb + (size_t)(b * NKV + kh) * SS * HD;
    const __half* Vhg = g_Vb + (size_t)(b * NKV + kh) * SS * HD;

#pragma unroll
    for (int l = 0; l < 8; l++) {
        int idx = tid + l * 256;
        int row = idx >> 4;
        int c = idx & 15;
        uint32_t off = sw256(row, c);
        size_t go = (size_t)row * HD + c * 8;
        cp16(Qhi_s + off, Qhig + go);
        cp16(Qlo_s + off, Qlog + go);
    }
    flash_load_kv(sb, 0, 0, Khg, Vhg, tid);
    asm volatile("cp.async.commit_group;\n");

    float m_lo = -1e30f, m_hi = -1e30f, l_lo = 0.f, l_hi = 0.f;
    float oacc[16][4];
#pragma unroll
    for (int v = 0; v < 16; v++)
#pragma unroll
        for (int r = 0; r < 4; r++) oacc[v][r] = 0.f;

    const float scale = 0.08838834764831845f;
    const int ntile = 2 * qt + 2;
    const int rlo = q0 + wid * 16 + (lane >> 2);
    const int rhi = rlo + 8;

    for (int t = 0; t < ntile; t++) {
        int buf = t & 1;
        if (t + 1 < ntile) {
            flash_load_kv(sb, t + 1, buf ^ 1, Khg, Vhg, tid);
            asm volatile("cp.async.commit_group;\n");
            asm volatile("cp.async.wait_group 1;\n");
        } else {
            asm volatile("cp.async.wait_group 0;\n");
        }
        __syncthreads();

        uint32_t kb = sb + 65536 + buf * 32768;
        uint32_t vb = kb + 16384;

        float sacc[8][4];
#pragma unroll
        for (int n = 0; n < 8; n++)
#pragma unroll
            for (int r = 0; r < 4; r++) sacc[n][r] = 0.f;

#pragma unroll
        for (int kk = 0; kk < 8; kk++) {
            uint32_t ah[4], al[4];
            {
                int m_l = wid * 16 + (mid & 1) * 8 + rin;
                int chnk = kk * 2 + (mid >> 1);
                uint32_t so = sw256(m_l, chnk);
                ldsm4(ah, Qhi_s + so);
                ldsm4(al, Qlo_s + so);
            }
#pragma unroll
            for (int j2 = 0; j2 < 4; j2++) {
                uint32_t bh[4];
                int n_l = (j2 * 2 + (mid >> 1)) * 8 + rin;
                int chnk = kk * 2 + (mid & 1);
                ldsm4(bh, kb + sw256(n_l, chnk));
#pragma unroll
                for (int jj = 0; jj < 2; jj++) {
                    int j = j2 * 2 + jj;
                    mma16816h(sacc[j], ah, bh[jj * 2], bh[jj * 2 + 1]);
                    mma16816h(sacc[j], al, bh[jj * 2], bh[jj * 2 + 1]);
                }
            }
        }

        int k0 = t * FK;
        bool diag = (t >= 2 * qt);
#pragma unroll
        for (int n = 0; n < 8; n++) {
            int c0 = k0 + n * 8 + (lane & 3) * 2;
            sacc[n][0] *= scale;
            sacc[n][1] *= scale;
            sacc[n][2] *= scale;
            sacc[n][3] *= scale;
            if (diag) {
                if (c0 > rlo) sacc[n][0] = -1e30f;
                if (c0 + 1 > rlo) sacc[n][1] = -1e30f;
                if (c0 > rhi) sacc[n][2] = -1e30f;
                if (c0 + 1 > rhi) sacc[n][3] = -1e30f;
            }
        }

        float mx0 = -1e30f, mx1 = -1e30f;
#pragma unroll
        for (int n = 0; n < 8; n++) {
            mx0 = fmaxf(mx0, fmaxf(sacc[n][0], sacc[n][1]));
            mx1 = fmaxf(mx1, fmaxf(sacc[n][2], sacc[n][3]));
        }
        mx0 = fmaxf(mx0, __shfl_xor_sync(0xffffffffu, mx0, 1));
        mx0 = fmaxf(mx0, __shfl_xor_sync(0xffffffffu, mx0, 2));
        mx1 = fmaxf(mx1, __shfl_xor_sync(0xffffffffu, mx1, 1));
        mx1 = fmaxf(mx1, __shfl_xor_sync(0xffffffffu, mx1, 2));
        float newm0 = fmaxf(m_lo, mx0);
        float newm1 = fmaxf(m_hi, mx1);
        float corr0 = __expf(m_lo - newm0);
        float corr1 = __expf(m_hi - newm1);
        m_lo = newm0;
        m_hi = newm1;

        float ls0 = 0.f, ls1 = 0.f;
#pragma unroll
        for (int n = 0; n < 8; n++) {
            sacc[n][0] = __expf(sacc[n][0] - newm0);
            sacc[n][1] = __expf(sacc[n][1] - newm0);
            sacc[n][2] = __expf(sacc[n][2] - newm1);
            sacc[n][3] = __expf(sacc[n][3] - newm1);
            ls0 += sacc[n][0] + sacc[n][1];
            ls1 += sacc[n][2] + sacc[n][3];
        }
        ls0 += __shfl_xor_sync(0xffffffffu, ls0, 1);
        ls0 += __shfl_xor_sync(0xffffffffu, ls0, 2);
        ls1 += __shfl_xor_sync(0xffffffffu, ls1, 1);
        ls1 += __shfl_xor_sync(0xffffffffu, ls1, 2);
        l_lo = l_lo * corr0 + ls0;
        l_hi = l_hi * corr1 + ls1;

#pragma unroll
        for (int v = 0; v < 16; v++) {
            oacc[v][0] *= corr0;
            oacc[v][1] *= corr0;
            oacc[v][2] *= corr1;
            oacc[v][3] *= corr1;
        }

#pragma unroll
        for (int kk = 0; kk < 4; kk++) {
            uint32_t aph[4], apl[4];
            {
                __half h0, l0, h1, l1;
                split1h(sacc[2 * kk][0], h0, l0);
                split1h(sacc[2 * kk][1], h1, l1);
                aph[0] = pack_h2(h0, h1);
                apl[0] = pack_h2(l0, l1);
                split1h(sacc[2 * kk][2], h0, l0);
                split1h(sacc[2 * kk][3], h1, l1);
                aph[1] = pack_h2(h0, h1);
                apl[1] = pack_h2(l0, l1);
                split1h(sacc[2 * kk + 1][0], h0, l0);
                split1h(sacc[2 * kk + 1][1], h1, l1);
                aph[2] = pack_h2(h0, h1);
                apl[2] = pack_h2(l0, l1);
                split1h(sacc[2 * kk + 1][2], h0, l0);
                split1h(sacc[2 * kk + 1][3], h1, l1);
                aph[3] = pack_h2(h0, h1);
                apl[3] = pack_h2(l0, l1);
            }
#pragma unroll
            for (int v2 = 0; v2 < 8; v2++) {
                int g = lane >> 3;
                int row = kk * 16 + (g & 1) * 8 + rin;
                int chnk = v2 * 2 + (g >> 1);
                uint32_t vh[4];
                ldsm4t(vh, vb + sw256(row, chnk));
#pragma unroll
                for (int gg = 0; gg < 2; gg++) {
                    int vnt = v2 * 2 + gg;
                    mma16816h(oacc[vnt], aph, vh[gg * 2], vh[gg * 2 + 1]);
                    mma16816h(oacc[vnt], apl, vh[gg * 2], vh[gg * 2 + 1]);
                }
            }
        }
        __syncthreads();
    }

    // epilogue: normalize, write fp16 hi/lo for the out-proj
    float inv0 = 1.f / l_lo;
    float inv1 = 1.f / l_hi;
    int row0 = b * SS + q0 + wid * 16 + (lane >> 2);
    int row1 = row0 + 8;
#pragma unroll
    for (int v = 0; v < 16; v++) {
        int col = h * HD + v * 8 + (lane & 3) * 2;
        float o0 = oacc[v][0] * inv0, o1 = oacc[v][1] * inv0;
        float o2 = oacc[v][2] * inv1, o3 = oacc[v][3] * inv1;
        __half h0, l0, h1, l1;
        split1h(o0, h0, l0);
        split1h(o1, h1, l1);
        *(uint32_t*)(g_Ahi + (size_t)row0 * KDIM + col) = pack_h2(h0, h1);
        *(uint32_t*)(g_Alo + (size_t)row0 * KDIM + col) = pack_h2(l0, l1);
        split1h(o2, h0, l0);
        split1h(o3, h1, l1);
        *(uint32_t*)(g_Ahi + (size_t)row1 * KDIM + col) = pack_h2(h0, h1);
        *(uint32_t*)(g_Alo + (size_t)row1 * KDIM + col) = pack_h2(l0, l1);
    }
}

// ---------------------------------------------------------------------------
extern "C" void kernel_launch(void* const* d_in, const int* in_sizes, int n_in,
                              void* d_out, int out_size) {
    const float* X = (const float*)d_in[0];
    const float* Wq = (const float*)d_in[1];
    const float* Wk = (const float*)d_in[2];
    const float* Wv = (const float*)d_in[3];
    const float* Wo = (const float*)d_in[4];
    float* out = (float*)d_out;

    // 0. Round inputs to fp16
    split_inputs_kernel<<<(N4_TOTAL + 255) / 256, 256>>>(X, Wq, Wk, Wv, Wo);

    // 1. QKV projections (fp16 1-term)
    cudaFuncSetAttribute(qkv_gemm_kernel, cudaFuncAttributeMaxDynamicSharedMemorySize,
                         GEMM1T_SMEM);
    qkv_gemm_kernel<<<dim3(24, 32), 256, GEMM1T_SMEM>>>();

    // 2. RoPE table + fused rope/convert/relayout
    rope_table_kernel<<<(SS * 64 + 255) / 256, 256>>>();
    {
        int total = RC_Q + RC_K + RC_V;
        rope_convert_kernel<<<(total + 255) / 256, 256>>>();
    }

    // 3. fp16 flash attention (Q 2-term, K/V 1-term)
    cudaFuncSetAttribute(flash_tc_kernel, cudaFuncAttributeMaxDynamicSharedMemorySize,
                         FLASH_SMEM);
    flash_tc_kernel<<<dim3(SS / FQ, NH, BB), 256, FLASH_SMEM>>>();

    // 4. Output projection (fp16 2-term)
    cudaFuncSetAttribute(out_gemm_kernel, cudaFuncAttributeMaxDynamicSharedMemorySize,
                         GEMM_SMEM);
    out_gemm_kernel<<<dim3(16, 32), 256, GEMM_SMEM>>>(out);
}

// round 7
// speedup vs baseline: 7.4336x; 1.2383x over previous
#include <cuda_runtime.h>
#include <cuda_bf16.h>
#include <cuda_fp16.h>
#include <math.h>
#include <stdint.h>

// Problem constants
#define BB 2
#define SS 2048
#define HH 2048
#define NH 16
#define NKV 4
#define HD 128
#define GROUPS (NH / NKV)        // 4
#define M_TOT (BB * SS)          // 4096
#define QDIM (NH * HD)           // 2048
#define KVDIM (NKV * HD)         // 512
#define KDIM 2048                // GEMM reduction dim

// fp32 scratch (pre-RoPE projections)
__device__ __align__(16) float g_Q[M_TOT * QDIM];
__device__ __align__(16) float g_K[M_TOT * KVDIM];
__device__ __align__(16) float g_V[M_TOT * KVDIM];
__device__ float g_cos[SS * 64];
__device__ float g_sin[SS * 64];

// fp16 buffers
__device__ __align__(16) __half g_Xh[M_TOT * KDIM];
__device__ __align__(16) __half g_Wqh[QDIM * KDIM];
__device__ __align__(16) __half g_Wkh[KVDIM * KDIM];
__device__ __align__(16) __half g_Wvh[KVDIM * KDIM];
__device__ __align__(16) __half g_Woh[HH * KDIM];
__device__ __align__(16) __half g_Ah[M_TOT * KDIM];     // flash out, rounded (1-term)

// fp16 head-major buffers for flash: [b, h, s, d]
__device__ __align__(16) __half g_Qbhi[M_TOT * QDIM], g_Qblo[M_TOT * QDIM];  // Q 2-term
__device__ __align__(16) __half g_Kb[M_TOT * KVDIM];                          // K 1-term
__device__ __align__(16) __half g_Vb[M_TOT * KVDIM];                          // V 1-term

// ---------------------------------------------------------------------------
// Helpers
// ---------------------------------------------------------------------------
__device__ __forceinline__ void split1h(float x, __half& h, __half& l) {
    h = __float2half_rn(x);
    l = __float2half_rn(x - __half2float(h));
}
__device__ __forceinline__ uint32_t pack_h2(__half a, __half b) {
    __half2 t(a, b);
    return *(uint32_t*)&t;
}
__device__ __forceinline__ uint32_t pack_f2h2(float a, float b) {
    __half2 t(__float2half_rn(a), __float2half_rn(b));
    return *(uint32_t*)&t;
}
__device__ __forceinline__ void cp16(uint32_t saddr, const void* gaddr) {
    asm volatile("cp.async.cg.shared.global [%0], [%1], 16;\n" ::"r"(saddr), "l"(gaddr));
}
__device__ __forceinline__ void ldsm4(uint32_t* r, uint32_t addr) {
    asm volatile("ldmatrix.sync.aligned.m8n8.x4.shared.b16 {%0,%1,%2,%3}, [%4];\n"
                 : "=r"(r[0]), "=r"(r[1]), "=r"(r[2]), "=r"(r[3]) : "r"(addr));
}
__device__ __forceinline__ void ldsm4t(uint32_t* r, uint32_t addr) {
    asm volatile("ldmatrix.sync.aligned.m8n8.x4.trans.shared.b16 {%0,%1,%2,%3}, [%4];\n"
                 : "=r"(r[0]), "=r"(r[1]), "=r"(r[2]), "=r"(r[3]) : "r"(addr));
}
__device__ __forceinline__ void mma16816h(float* c, const uint32_t* a, uint32_t b0, uint32_t b1) {
    asm volatile("mma.sync.aligned.m16n8k16.row.col.f32.f16.f16.f32 "
                 "{%0,%1,%2,%3}, {%4,%5,%6,%7}, {%8,%9}, {%0,%1,%2,%3};\n"
                 : "+f"(c[0]), "+f"(c[1]), "+f"(c[2]), "+f"(c[3])
                 : "r"(a[0]), "r"(a[1]), "r"(a[2]), "r"(a[3]), "r"(b0), "r"(b1));
}

// ---------------------------------------------------------------------------
// Input split: X -> fp16, weights -> fp16 (all rounded)
// ---------------------------------------------------------------------------
#define N4_X  ((M_TOT * KDIM) / 4)
#define N4_WQ ((QDIM * KDIM) / 4)
#define N4_WKV ((KVDIM * KDIM) / 4)
#define N4_WO ((HH * KDIM) / 4)
#define N4_TOTAL (N4_X + N4_WQ + 2 * N4_WKV + N4_WO)

__global__ void split_inputs_kernel(const float* __restrict__ X,
                                    const float* __restrict__ Wq,
                                    const float* __restrict__ Wk,
                                    const float* __restrict__ Wv,
                                    const float* __restrict__ Wo) {
    int i = blockIdx.x * blockDim.x + threadIdx.x;
    if (i >= N4_TOTAL) return;
    const float* src;
    __half* dst;
    int off;
    if (i < N4_X) {
        src = X; dst = g_Xh; off = i;
    } else if (i < N4_X + N4_WQ) {
        src = Wq; dst = g_Wqh; off = i - N4_X;
    } else if (i < N4_X + N4_WQ + N4_WKV) {
        src = Wk; dst = g_Wkh; off = i - N4_X - N4_WQ;
    } else if (i < N4_X + N4_WQ + 2 * N4_WKV) {
        src = Wv; dst = g_Wvh; off = i - N4_X - N4_WQ - N4_WKV;
    } else {
        src = Wo; dst = g_Woh; off = i - N4_X - N4_WQ - 2 * N4_WKV;
    }
    float4 v = *(const float4*)(src + (size_t)off * 4);
    *(uint32_t*)(dst + (size_t)off * 4 + 0) = pack_f2h2(v.x, v.y);
    *(uint32_t*)(dst + (size_t)off * 4 + 2) = pack_f2h2(v.z, v.w);
}

// ---------------------------------------------------------------------------
// Shared GEMM smem swizzle (32-K chunks, 64B rows of fp16)
// ---------------------------------------------------------------------------
__device__ __forceinline__ uint32_t sw_off(int row, int k) {
    int c = (k >> 3) ^ (row & 3);
    return (uint32_t)((row * 4 + c) << 4);
}

// ---------------------------------------------------------------------------
// 1-term fp16 GEMM: Y[m][n] = sum_k A[m][k] * B[n][k]
// Block 128x128x32, 8 warps, 3-stage. Stage: A 8K | B 8K = 16K.
// ---------------------------------------------------------------------------
#define STAGE1T 16384
#define GEMM1T_SMEM (3 * STAGE1T)
#define KT16 (KDIM / 32)   // 64

__device__ __forceinline__ void load_stage1t(uint32_t S, int buf,
                                             const __half* __restrict__ A,
                                             const __half* __restrict__ B,
                                             int m0, int n0, int k0, int tid) {
    uint32_t st = S + buf * STAGE1T;
#pragma unroll
    for (int l = 0; l < 2; l++) {
        int idx = tid + l * 256;          // 0..511 = 128 rows x 4 chunks
        int row = idx >> 2;
        int c = idx & 3;
        uint32_t spos = sw_off(row, c * 8);
        size_t ga = (size_t)(m0 + row) * KDIM + k0 + c * 8;
        size_t gb = (size_t)(n0 + row) * KDIM + k0 + c * 8;
        cp16(st + spos, A + ga);
        cp16(st + 8192 + spos, B + gb);
    }
    asm volatile("cp.async.commit_group;\n");
}

__device__ __forceinline__ void gemm_fp16_1t(const __half* __restrict__ A,
                                             const __half* __restrict__ B,
                                             float* __restrict__ Y,
                                             int m0, int n0, int ldy) {
    extern __shared__ char smem_raw[];
    uint32_t S = (uint32_t)__cvta_generic_to_shared(smem_raw);

    int tid = threadIdx.x;
    int lane = tid & 31;
    int wid = tid >> 5;
    int wm = wid & 1;
    int wn = wid >> 1;
    int mid = lane >> 3, rin = lane & 7;

    float acc[4][4][4];
#pragma unroll
    for (int i = 0; i < 4; i++)
#pragma unroll
        for (int j = 0; j < 4; j++)
#pragma unroll
            for (int r = 0; r < 4; r++) acc[i][j][r] = 0.f;

    load_stage1t(S, 0, A, B, m0, n0, 0, tid);
    load_stage1t(S, 1, A, B, m0, n0, 32, tid);

    for (int kt = 0; kt < KT16; kt++) {
        if (kt < KT16 - 1)
            asm volatile("cp.async.wait_group 1;\n");
        else
            asm volatile("cp.async.wait_group 0;\n");
        __syncthreads();

        if (kt + 2 < KT16)
            load_stage1t(S, (kt + 2) % 3, A, B, m0, n0, (kt + 2) * 32, tid);

        uint32_t aB = S + (kt % 3) * STAGE1T;
        uint32_t bB = aB + 8192;

#pragma unroll
        for (int kk = 0; kk < 2; kk++) {
            uint32_t ah[4][4];
#pragma unroll
            for (int i = 0; i < 4; i++) {
                int m_l = wm * 64 + i * 16 + (mid & 1) * 8 + rin;
                int k_l = kk * 16 + (mid >> 1) * 8;
                ldsm4(ah[i], aB + sw_off(m_l, k_l));
            }
#pragma unroll
            for (int j2 = 0; j2 < 2; j2++) {
                uint32_t bh[4];
                int n_l = wn * 32 + (j2 * 2 + (mid >> 1)) * 8 + rin;
                int k_l = kk * 16 + (mid & 1) * 8;
                ldsm4(bh, bB + sw_off(n_l, k_l));
#pragma unroll
                for (int jj = 0; jj < 2; jj++) {
                    int j = j2 * 2 + jj;
#pragma unroll
                    for (int i = 0; i < 4; i++)
                        mma16816h(acc[i][j], ah[i], bh[jj * 2], bh[jj * 2 + 1]);
                }
            }
        }
    }

#pragma unroll
    for (int i = 0; i < 4; i++) {
#pragma unroll
        for (int j = 0; j < 4; j++) {
            int r0 = m0 + wm * 64 + i * 16 + (lane >> 2);
            int cc = n0 + wn * 32 + j * 8 + (lane & 3) * 2;
            *(float2*)&Y[(size_t)r0 * ldy + cc] = make_float2(acc[i][j][0], acc[i][j][1]);
            *(float2*)&Y[(size_t)(r0 + 8) * ldy + cc] = make_float2(acc[i][j][2], acc[i][j][3]);
        }
    }
}

__global__ __launch_bounds__(256, 2) void qkv_gemm_kernel() {
    int bx = blockIdx.x;
    int m0 = blockIdx.y * 128;
    if (bx < 16)
        gemm_fp16_1t(g_Xh, g_Wqh, g_Q, m0, bx * 128, QDIM);
    else if (bx < 20)
        gemm_fp16_1t(g_Xh, g_Wkh, g_K, m0, (bx - 16) * 128, KVDIM);
    else
        gemm_fp16_1t(g_Xh, g_Wvh, g_V, m0, (bx - 20) * 128, KVDIM);
}

__global__ __launch_bounds__(256, 2) void out_gemm_kernel(float* __restrict__ out) {
    gemm_fp16_1t(g_Ah, g_Woh, out, blockIdx.y * 128, blockIdx.x * 128, HH);
}

// ---------------------------------------------------------------------------
// RoPE table + fused RoPE/convert/relayout (fp16: Q hi/lo, K/V rounded)
// ---------------------------------------------------------------------------
__global__ void rope_table_kernel() {
    int idx = blockIdx.x * blockDim.x + threadIdx.x;
    if (idx >= SS * 64) return;
    int pos = idx >> 6;
    int i = idx & 63;
    double inv = pow(10000.0, -(double)i / 64.0);
    double ang = (double)pos * inv;
    double sd, cd;
    sincos(ang, &sd, &cd);
    g_cos[idx] = (float)cd;
    g_sin[idx] = (float)sd;
}

#define RC_Q (M_TOT * NH * 64)
#define RC_K (M_TOT * NKV * 64)
#define RC_V (M_TOT * NKV * 64)

__global__ void rope_convert_kernel() {
    int idx = blockIdx.x * blockDim.x + threadIdx.x;
    if (idx >= RC_Q + RC_K + RC_V) return;

    if (idx < RC_Q) {
        int m = idx / (NH * 64);
        int r = idx - m * (NH * 64);
        int h = r >> 6, d = r & 63;
        int b = m >> 11, s = m & (SS - 1);
        float x1 = g_Q[(size_t)m * QDIM + h * HD + d];
        float x2 = g_Q[(size_t)m * QDIM + h * HD + d + 64];
        float c = g_cos[s * 64 + d], sn = g_sin[s * 64 + d];
        float y1 = x1 * c - x2 * sn;
        float y2 = x2 * c + x1 * sn;
        size_t dst = ((size_t)(b * NH + h) * SS + s) * HD + d;
        __half h1, l1, h2, l2;
        split1h(y1, h1, l1);
        split1h(y2, h2, l2);
        g_Qbhi[dst] = h1; g_Qblo[dst] = l1;
        g_Qbhi[dst + 64] = h2; g_Qblo[dst + 64] = l2;
    } else if (idx < RC_Q + RC_K) {
        int e = idx - RC_Q;
        int m = e / (NKV * 64);
        int r = e - m * (NKV * 64);
        int h = r >> 6, d = r & 63;
        int b = m >> 11, s = m & (SS - 1);
        float x1 = g_K[(size_t)m * KVDIM + h * HD + d];
        float x2 = g_K[(size_t)m * KVDIM + h * HD + d + 64];
        float c = g_cos[s * 64 + d], sn = g_sin[s * 64 + d];
        float y1 = x1 * c - x2 * sn;
        float y2 = x2 * c + x1 * sn;
        size_t dst = ((size_t)(b * NKV + h) * SS + s) * HD + d;
        g_Kb[dst] = __float2half_rn(y1);
        g_Kb[dst + 64] = __float2half_rn(y2);
    } else {
        int e = idx - RC_Q - RC_K;
        int m = e / (NKV * 64);
        int r = e - m * (NKV * 64);
        int h = r >> 6, d = r & 63;
        int b = m >> 11, s = m & (SS - 1);
        float x1 = g_V[(size_t)m * KVDIM + h * HD + d];
        float x2 = g_V[(size_t)m * KVDIM + h * HD + d + 64];
        size_t dst = ((size_t)(b * NKV + h) * SS + s) * HD + d;
        g_Vb[dst] = __float2half_rn(x1);
        g_Vb[dst + 64] = __float2half_rn(x2);
    }
}

// ---------------------------------------------------------------------------
// fp16 flash attention (causal): QK 2-term Q, PV 1-term P. BQ=128, BKV=64
// smem: Qhi 32K | Qlo 32K | stage{0,1}: K 16K | V 16K  -> 128 KB
// ---------------------------------------------------------------------------
#define FQ 128
#define FK 64
#define FLASH_SMEM (65536 + 2 * 32768)

__device__ __forceinline__ uint32_t sw256(int row, int chunk) {
    return (uint32_t)(row * 256 + ((chunk ^ (row & 7)) << 4));
}

__device__ __forceinline__ void flash_load_kv(uint32_t sb, int t, int st,
                                              const __half* Kh, const __half* Vh, int tid) {
    uint32_t base = sb + 65536 + st * 32768;
    size_t g0 = (size_t)t * FK * HD;
#pragma unroll
    for (int l = 0; l < 4; l++) {
        int idx = tid + l * 256;      // 0..1023 = 64 rows x 16 chunks
        int row = idx >> 4;
        int c = idx & 15;
        uint32_t off = sw256(row, c);
        size_t go = g0 + (size_t)row * HD + c * 8;
        cp16(base + off, Kh + go);
        cp16(base + 16384 + off, Vh + go);
    }
}

__global__ __launch_bounds__(256) void flash_tc_kernel() {
    extern __shared__ char smem_raw[];
    uint32_t sb = (uint32_t)__cvta_generic_to_shared(smem_raw);
    uint32_t Qhi_s = sb, Qlo_s = sb + 32768;

    int qt = (int)(gridDim.x - 1 - blockIdx.x);
    int h = blockIdx.y, b = blockIdx.z;
    int q0 = qt * FQ;
    int kh = h / GROUPS;

    int tid = threadIdx.x, lane = tid & 31, wid = tid >> 5;
    int mid = lane >> 3, rin = lane & 7;

    const __half* Qhig = g_Qbhi + ((size_t)(b * NH + h) * SS + q0) * HD;
    const __half* Qlog = g_Qblo + ((size_t)(b * NH + h) * SS + q0) * HD;
    const __half* Khg = g_Kb + (size_t)(b * NKV + kh) * SS * HD;
    const __half* Vhg = g_Vb + (size_t)(b * NKV + kh) * SS * HD;

#pragma unroll
    for (int l = 0; l < 8; l++) {
        int idx = tid + l * 256;
        int row = idx >> 4;
        int c = idx & 15;
        uint32_t off = sw256(row, c);
        size_t go = (size_t)row * HD + c * 8;
        cp16(Qhi_s + off, Qhig + go);
        cp16(Qlo_s + off, Qlog + go);
    }
    flash_load_kv(sb, 0, 0, Khg, Vhg, tid);
    asm volatile("cp.async.commit_group;\n");

    float m_lo = -1e30f, m_hi = -1e30f, l_lo = 0.f, l_hi = 0.f;
    float oacc[16][4];
#pragma unroll
    for (int v = 0; v < 16; v++)
#pragma unroll
        for (int r = 0; r < 4; r++) oacc[v][r] = 0.f;

    const float scale = 0.08838834764831845f;
    const int ntile = 2 * qt + 2;
    const int rlo = q0 + wid * 16 + (lane >> 2);
    const int rhi = rlo + 8;

    for (int t = 0; t < ntile; t++) {
        int buf = t & 1;
        if (t + 1 < ntile) {
            flash_load_kv(sb, t + 1, buf ^ 1, Khg, Vhg, tid);
            asm volatile("cp.async.commit_group;\n");
            asm volatile("cp.async.wait_group 1;\n");
        } else {
            asm volatile("cp.async.wait_group 0;\n");
        }
        __syncthreads();

        uint32_t kb = sb + 65536 + buf * 32768;
        uint32_t vb = kb + 16384;

        float sacc[8][4];
#pragma unroll
        for (int n = 0; n < 8; n++)
#pragma unroll
            for (int r = 0; r < 4; r++) sacc[n][r] = 0.f;

#pragma unroll
        for (int kk = 0; kk < 8; kk++) {
            uint32_t ah[4], al[4];
            {
                int m_l = wid * 16 + (mid & 1) * 8 + rin;
                int chnk = kk * 2 + (mid >> 1);
                uint32_t so = sw256(m_l, chnk);
                ldsm4(ah, Qhi_s + so);
                ldsm4(al, Qlo_s + so);
            }
#pragma unroll
            for (int j2 = 0; j2 < 4; j2++) {
                uint32_t bh[4];
                int n_l = (j2 * 2 + (mid >> 1)) * 8 + rin;
                int chnk = kk * 2 + (mid & 1);
                ldsm4(bh, kb + sw256(n_l, chnk));
#pragma unroll
                for (int jj = 0; jj < 2; jj++) {
                    int j = j2 * 2 + jj;
                    mma16816h(sacc[j], ah, bh[jj * 2], bh[jj * 2 + 1]);
                    mma16816h(sacc[j], al, bh[jj * 2], bh[jj * 2 + 1]);
                }
            }
        }

        int k0 = t * FK;
        bool diag = (t >= 2 * qt);
#pragma unroll
        for (int n = 0; n < 8; n++) {
            int c0 = k0 + n * 8 + (lane & 3) * 2;
            sacc[n][0] *= scale;
            sacc[n][1] *= scale;
            sacc[n][2] *= scale;
            sacc[n][3] *= scale;
            if (diag) {
                if (c0 > rlo) sacc[n][0] = -1e30f;
                if (c0 + 1 > rlo) sacc[n][1] = -1e30f;
                if (c0 > rhi) sacc[n][2] = -1e30f;
                if (c0 + 1 > rhi) sacc[n][3] = -1e30f;
            }
        }

        float mx0 = -1e30f, mx1 = -1e30f;
#pragma unroll
        for (int n = 0; n < 8; n++) {
            mx0 = fmaxf(mx0, fmaxf(sacc[n][0], sacc[n][1]));
            mx1 = fmaxf(mx1, fmaxf(sacc[n][2], sacc[n][3]));
        }
        mx0 = fmaxf(mx0, __shfl_xor_sync(0xffffffffu, mx0, 1));
        mx0 = fmaxf(mx0, __shfl_xor_sync(0xffffffffu, mx0, 2));
        mx1 = fmaxf(mx1, __shfl_xor_sync(0xffffffffu, mx1, 1));
        mx1 = fmaxf(mx1, __shfl_xor_sync(0xffffffffu, mx1, 2));
        float newm0 = fmaxf(m_lo, mx0);
        float newm1 = fmaxf(m_hi, mx1);
        float corr0 = __expf(m_lo - newm0);
        float corr1 = __expf(m_hi - newm1);
        m_lo = newm0;
        m_hi = newm1;

        float ls0 = 0.f, ls1 = 0.f;
#pragma unroll
        for (int n = 0; n < 8; n++) {
            sacc[n][0] = __expf(sacc[n][0] - newm0);
            sacc[n][1] = __expf(sacc[n][1] - newm0);
            sacc[n][2] = __expf(sacc[n][2] - newm1);
            sacc[n][3] = __expf(sacc[n][3] - newm1);
            ls0 += sacc[n][0] + sacc[n][1];
            ls1 += sacc[n][2] + sacc[n][3];
        }
        ls0 += __shfl_xor_sync(0xffffffffu, ls0, 1);
        ls0 += __shfl_xor_sync(0xffffffffu, ls0, 2);
        ls1 += __shfl_xor_sync(0xffffffffu, ls1, 1);
        ls1 += __shfl_xor_sync(0xffffffffu, ls1, 2);
        l_lo = l_lo * corr0 + ls0;
        l_hi = l_hi * corr1 + ls1;

#pragma unroll
        for (int v = 0; v < 16; v++) {
            oacc[v][0] *= corr0;
            oacc[v][1] *= corr0;
            oacc[v][2] *= corr1;
            oacc[v][3] *= corr1;
        }

        // ---- O += P V  (P rounded 1-term, V 1-term) ----
#pragma unroll
        for (int kk = 0; kk < 4; kk++) {
            uint32_t aph[4];
            aph[0] = pack_f2h2(sacc[2 * kk][0], sacc[2 * kk][1]);
            aph[1] = pack_f2h2(sacc[2 * kk][2], sacc[2 * kk][3]);
            aph[2] = pack_f2h2(sacc[2 * kk + 1][0], sacc[2 * kk + 1][1]);
            aph[3] = pack_f2h2(sacc[2 * kk + 1][2], sacc[2 * kk + 1][3]);
#pragma unroll
            for (int v2 = 0; v2 < 8; v2++) {
                int g = lane >> 3;
                int row = kk * 16 + (g & 1) * 8 + rin;
                int chnk = v2 * 2 + (g >> 1);
                uint32_t vh[4];
                ldsm4t(vh, vb + sw256(row, chnk));
#pragma unroll
                for (int gg = 0; gg < 2; gg++) {
                    int vnt = v2 * 2 + gg;
                    mma16816h(oacc[vnt], aph, vh[gg * 2], vh[gg * 2 + 1]);
                }
            }
        }
        __syncthreads();
    }

    // epilogue: normalize, write rounded fp16 for the out-proj
    float inv0 = 1.f / l_lo;
    float inv1 = 1.f / l_hi;
    int row0 = b * SS + q0 + wid * 16 + (lane >> 2);
    int row1 = row0 + 8;
#pragma unroll
    for (int v = 0; v < 16; v++) {
        int col = h * HD + v * 8 + (lane & 3) * 2;
        *(uint32_t*)(g_Ah + (size_t)row0 * KDIM + col) =
            pack_f2h2(oacc[v][0] * inv0, oacc[v][1] * inv0);
        *(uint32_t*)(g_Ah + (size_t)row1 * KDIM + col) =
            pack_f2h2(oacc[v][2] * inv1, oacc[v][3] * inv1);
    }
}

// ---------------------------------------------------------------------------
extern "C" void kernel_launch(void* const* d_in, const int* in_sizes, int n_in,
                              void* d_out, int out_size) {
    const float* X = (const float*)d_in[0];
    const float* Wq = (const float*)d_in[1];
    const float* Wk = (const float*)d_in[2];
    const float* Wv = (const float*)d_in[3];
    const float* Wo = (const float*)d_in[4];
    float* out = (float*)d_out;

    // 0. Round inputs to fp16
    split_inputs_kernel<<<(N4_TOTAL + 255) / 256, 256>>>(X, Wq, Wk, Wv, Wo);

    // 1. QKV projections (fp16 1-term)
    cudaFuncSetAttribute(qkv_gemm_kernel, cudaFuncAttributeMaxDynamicSharedMemorySize,
                         GEMM1T_SMEM);
    qkv_gemm_kernel<<<dim3(24, 32), 256, GEMM1T_SMEM>>>();

    // 2. RoPE table + fused rope/convert/relayout
    rope_table_kernel<<<(SS * 64 + 255) / 256, 256>>>();
    {
        int total = RC_Q + RC_K + RC_V;
        rope_convert_kernel<<<(total + 255) / 256, 256>>>();
    }

    // 3. fp16 flash attention (QK: Q 2-term; PV: 1-term)
    cudaFuncSetAttribute(flash_tc_kernel, cudaFuncAttributeMaxDynamicSharedMemorySize,
                         FLASH_SMEM);
    flash_tc_kernel<<<dim3(SS / FQ, NH, BB), 256, FLASH_SMEM>>>();

    // 4. Output projection (fp16 1-term)
    cudaFuncSetAttribute(out_gemm_kernel, cudaFuncAttributeMaxDynamicSharedMemorySize,
                         GEMM1T_SMEM);
    out_gemm_kernel<<<dim3(16, 32), 256, GEMM1T_SMEM>>>(out);
}

// round 8
// speedup vs baseline: 7.9587x; 1.0706x over previous
#include <cuda_runtime.h>
#include <cuda_fp16.h>
#include <math.h>
#include <stdint.h>

// Problem constants
#define BB 2
#define SS 2048
#define HH 2048
#define NH 16
#define NKV 4
#define HD 128
#define GROUPS (NH / NKV)        // 4
#define M_TOT (BB * SS)          // 4096
#define QDIM (NH * HD)           // 2048
#define KVDIM (NKV * HD)         // 512
#define KDIM 2048                // GEMM reduction dim

__device__ float g_cos[SS * 64];
__device__ float g_sin[SS * 64];

// fp16 buffers
__device__ __align__(16) __half g_Xh[M_TOT * KDIM];
__device__ __align__(16) __half g_Wqh[QDIM * KDIM];
__device__ __align__(16) __half g_Wkh[KVDIM * KDIM];
__device__ __align__(16) __half g_Wvh[KVDIM * KDIM];
__device__ __align__(16) __half g_Woh[HH * KDIM];
__device__ __align__(16) __half g_Ah[M_TOT * KDIM];     // flash out (rounded)

// fp16 head-major buffers for flash: [b, h, s, d]
__device__ __align__(16) __half g_Qb[M_TOT * QDIM];
__device__ __align__(16) __half g_Kb[M_TOT * KVDIM];
__device__ __align__(16) __half g_Vb[M_TOT * KVDIM];

// ---------------------------------------------------------------------------
// Helpers
// ---------------------------------------------------------------------------
__device__ __forceinline__ uint32_t pack_f2h2(float a, float b) {
    __half2 t(__float2half_rn(a), __float2half_rn(b));
    return *(uint32_t*)&t;
}
__device__ __forceinline__ void cp16(uint32_t saddr, const void* gaddr) {
    asm volatile("cp.async.cg.shared.global [%0], [%1], 16;\n" ::"r"(saddr), "l"(gaddr));
}
__device__ __forceinline__ void ldsm4(uint32_t* r, uint32_t addr) {
    asm volatile("ldmatrix.sync.aligned.m8n8.x4.shared.b16 {%0,%1,%2,%3}, [%4];\n"
                 : "=r"(r[0]), "=r"(r[1]), "=r"(r[2]), "=r"(r[3]) : "r"(addr));
}
__device__ __forceinline__ void ldsm4t(uint32_t* r, uint32_t addr) {
    asm volatile("ldmatrix.sync.aligned.m8n8.x4.trans.shared.b16 {%0,%1,%2,%3}, [%4];\n"
                 : "=r"(r[0]), "=r"(r[1]), "=r"(r[2]), "=r"(r[3]) : "r"(addr));
}
__device__ __forceinline__ void mma16816h(float* c, const uint32_t* a, uint32_t b0, uint32_t b1) {
    asm volatile("mma.sync.aligned.m16n8k16.row.col.f32.f16.f16.f32 "
                 "{%0,%1,%2,%3}, {%4,%5,%6,%7}, {%8,%9}, {%0,%1,%2,%3};\n"
                 : "+f"(c[0]), "+f"(c[1]), "+f"(c[2]), "+f"(c[3])
                 : "r"(a[0]), "r"(a[1]), "r"(a[2]), "r"(a[3]), "r"(b0), "r"(b1));
}

// ---------------------------------------------------------------------------
// Input split: X -> fp16, weights -> fp16 (all rounded)
// ---------------------------------------------------------------------------
#define N4_X  ((M_TOT * KDIM) / 4)
#define N4_WQ ((QDIM * KDIM) / 4)
#define N4_WKV ((KVDIM * KDIM) / 4)
#define N4_WO ((HH * KDIM) / 4)
#define N4_TOTAL (N4_X + N4_WQ + 2 * N4_WKV + N4_WO)

__global__ void split_inputs_kernel(const float* __restrict__ X,
                                    const float* __restrict__ Wq,
                                    const float* __restrict__ Wk,
                                    const float* __restrict__ Wv,
                                    const float* __restrict__ Wo) {
    int i = blockIdx.x * blockDim.x + threadIdx.x;
    if (i >= N4_TOTAL) return;
    const float* src;
    __half* dst;
    int off;
    if (i < N4_X) {
        src = X; dst = g_Xh; off = i;
    } else if (i < N4_X + N4_WQ) {
        src = Wq; dst = g_Wqh; off = i - N4_X;
    } else if (i < N4_X + N4_WQ + N4_WKV) {
        src = Wk; dst = g_Wkh; off = i - N4_X - N4_WQ;
    } else if (i < N4_X + N4_WQ + 2 * N4_WKV) {
        src = Wv; dst = g_Wvh; off = i - N4_X - N4_WQ - N4_WKV;
    } else {
        src = Wo; dst = g_Woh; off = i - N4_X - N4_WQ - 2 * N4_WKV;
    }
    float4 v = *(const float4*)(src + (size_t)off * 4);
    *(uint32_t*)(dst + (size_t)off * 4 + 0) = pack_f2h2(v.x, v.y);
    *(uint32_t*)(dst + (size_t)off * 4 + 2) = pack_f2h2(v.z, v.w);
}

// ---------------------------------------------------------------------------
// RoPE table
// ---------------------------------------------------------------------------
__global__ void rope_table_kernel() {
    int idx = blockIdx.x * blockDim.x + threadIdx.x;
    if (idx >= SS * 64) return;
    int pos = idx >> 6;
    int i = idx & 63;
    double inv = pow(10000.0, -(double)i / 64.0);
    double ang = (double)pos * inv;
    double sd, cd;
    sincos(ang, &sd, &cd);
    g_cos[idx] = (float)cd;
    g_sin[idx] = (float)sd;
}

// ---------------------------------------------------------------------------
// Shared GEMM smem swizzle (32-K chunks, 64B rows of fp16)
// ---------------------------------------------------------------------------
__device__ __forceinline__ uint32_t sw_off(int row, int k) {
    int c = (k >> 3) ^ (row & 3);
    return (uint32_t)((row * 4 + c) << 4);
}

#define STAGE1T 16384
#define KT16 (KDIM / 32)   // 64

__device__ __forceinline__ void load_stage1t(uint32_t S, int buf,
                                             const __half* __restrict__ A,
                                             const __half* __restrict__ B,
                                             int m0, int n0, int k0, int tid) {
    uint32_t st = S + buf * STAGE1T;
#pragma unroll
    for (int l = 0; l < 2; l++) {
        int idx = tid + l * 256;          // 0..511 = 128 rows x 4 chunks
        int row = idx >> 2;
        int c = idx & 3;
        uint32_t spos = sw_off(row, c * 8);
        size_t ga = (size_t)(m0 + row) * KDIM + k0 + c * 8;
        size_t gb = (size_t)(n0 + row) * KDIM + k0 + c * 8;
        cp16(st + spos, A + ga);
        cp16(st + 8192 + spos, B + gb);
    }
    asm volatile("cp.async.commit_group;\n");
}

// Core 128x128x2048 mainloop, leaves result in acc[4][4][4]
#define GEMM_MAINLOOP(A, B, m0, n0)                                                   \
    float acc[4][4][4];                                                               \
    _Pragma("unroll") for (int i = 0; i < 4; i++)                                     \
        _Pragma("unroll") for (int j = 0; j < 4; j++)                                 \
            _Pragma("unroll") for (int r = 0; r < 4; r++) acc[i][j][r] = 0.f;         \
    load_stage1t(S, 0, A, B, m0, n0, 0, tid);                                         \
    load_stage1t(S, 1, A, B, m0, n0, 32, tid);                                        \
    for (int kt = 0; kt < KT16; kt++) {                                               \
        if (kt < KT16 - 1)                                                            \
            asm volatile("cp.async.wait_group 1;\n");                                 \
        else                                                                          \
            asm volatile("cp.async.wait_group 0;\n");                                 \
        __syncthreads();                                                              \
        if (kt + 2 < KT16)                                                            \
            load_stage1t(S, (kt + 2) % 3, A, B, m0, n0, (kt + 2) * 32, tid);          \
        uint32_t aB = S + (kt % 3) * STAGE1T;                                         \
        uint32_t bB = aB + 8192;                                                      \
        _Pragma("unroll") for (int kk = 0; kk < 2; kk++) {                            \
            uint32_t ah[4][4];                                                        \
            _Pragma("unroll") for (int i = 0; i < 4; i++) {                           \
                int m_l = wm * 64 + i * 16 + (mid & 1) * 8 + rin;                     \
                int k_l = kk * 16 + (mid >> 1) * 8;                                   \
                ldsm4(ah[i], aB + sw_off(m_l, k_l));                                  \
            }                                                                         \
            _Pragma("unroll") for (int j2 = 0; j2 < 2; j2++) {                        \
                uint32_t bh[4];                                                       \
                int n_l = wn * 32 + (j2 * 2 + (mid >> 1)) * 8 + rin;                  \
                int k_l = kk * 16 + (mid & 1) * 8;                                    \
                ldsm4(bh, bB + sw_off(n_l, k_l));                                     \
                _Pragma("unroll") for (int jj = 0; jj < 2; jj++) {                    \
                    int j = j2 * 2 + jj;                                              \
                    _Pragma("unroll") for (int i = 0; i < 4; i++)                     \
                        mma16816h(acc[i][j], ah[i], bh[jj * 2], bh[jj * 2 + 1]);      \
                }                                                                     \
            }                                                                         \
        }                                                                             \
    }

// ---------------------------------------------------------------------------
// QKV GEMM with fused RoPE + fp16 head-major epilogue.
// grid (24, 32): bx 0-15 Q heads, 16-19 K heads, 20-23 V heads.
// smem: max(3*16K pipeline, 128x132 fp32 tile = 66K) = 67584 B
// ---------------------------------------------------------------------------
#define QKV_SMEM 67584

__global__ __launch_bounds__(256, 2) void qkv_gemm_kernel() {
    extern __shared__ char smem_raw[];
    uint32_t S = (uint32_t)__cvta_generic_to_shared(smem_raw);
    int tid = threadIdx.x;
    int lane = tid & 31, wid = tid >> 5;
    int wm = wid & 1, wn = wid >> 1;
    int mid = lane >> 3, rin = lane & 7;

    int bx = blockIdx.x;
    int m0 = blockIdx.y * 128;

    const __half* A = g_Xh;
    const __half* B;
    __half* dstH;
    int head, nhd;
    bool do_rope;
    if (bx < 16) {
        B = g_Wqh; dstH = g_Qb; head = bx; nhd = NH; do_rope = true;
    } else if (bx < 20) {
        B = g_Wkh; dstH = g_Kb; head = bx - 16; nhd = NKV; do_rope = true;
    } else {
        B = g_Wvh; dstH = g_Vb; head = bx - 20; nhd = NKV; do_rope = false;
    }
    int n0 = head * HD;

    GEMM_MAINLOOP(A, B, m0, n0)

    // ---- fused epilogue: stage fp32 tile in smem, rope pairs, fp16 out ----
    __syncthreads();   // all warps done reading the last pipeline stage
    float* tile = (float*)smem_raw;
#pragma unroll
    for (int i = 0; i < 4; i++) {
#pragma unroll
        for (int j = 0; j < 4; j++) {
            int r0 = wm * 64 + i * 16 + (lane >> 2);
            int cc = wn * 32 + j * 8 + (lane & 3) * 2;
            *(float2*)&tile[r0 * 132 + cc] = make_float2(acc[i][j][0], acc[i][j][1]);
            *(float2*)&tile[(r0 + 8) * 132 + cc] = make_float2(acc[i][j][2], acc[i][j][3]);
        }
    }
    __syncthreads();

    for (int it = tid; it < 128 * 64; it += 256) {
        int row = it >> 6, d = it & 63;
        int m = m0 + row;
        int s = m & (SS - 1), b = m >> 11;
        float x1 = tile[row * 132 + d];
        float x2 = tile[row * 132 + d + 64];
        float y1 = x1, y2 = x2;
        if (do_rope) {
            float c = g_cos[s * 64 + d], sn = g_sin[s * 64 + d];
            y1 = x1 * c - x2 * sn;
            y2 = x2 * c + x1 * sn;
        }
        size_t dst = ((size_t)(b * nhd + head) * SS + s) * HD + d;
        dstH[dst] = __float2half_rn(y1);
        dstH[dst + 64] = __float2half_rn(y2);
    }
}

// ---------------------------------------------------------------------------
// Output projection (1-term, fp32 out)
// ---------------------------------------------------------------------------
#define GEMM1T_SMEM (3 * STAGE1T)

__global__ __launch_bounds__(256, 2) void out_gemm_kernel(float* __restrict__ out) {
    extern __shared__ char smem_raw[];
    uint32_t S = (uint32_t)__cvta_generic_to_shared(smem_raw);
    int tid = threadIdx.x;
    int lane = tid & 31, wid = tid >> 5;
    int wm = wid & 1, wn = wid >> 1;
    int mid = lane >> 3, rin = lane & 7;
    int m0 = blockIdx.y * 128, n0 = blockIdx.x * 128;

    GEMM_MAINLOOP(g_Ah, g_Woh, m0, n0)

#pragma unroll
    for (int i = 0; i < 4; i++) {
#pragma unroll
        for (int j = 0; j < 4; j++) {
            int r0 = m0 + wm * 64 + i * 16 + (lane >> 2);
            int cc = n0 + wn * 32 + j * 8 + (lane & 3) * 2;
            *(float2*)&out[(size_t)r0 * HH + cc] = make_float2(acc[i][j][0], acc[i][j][1]);
            *(float2*)&out[(size_t)(r0 + 8) * HH + cc] = make_float2(acc[i][j][2], acc[i][j][3]);
        }
    }
}

// ---------------------------------------------------------------------------
// fp16 flash attention (causal), all operands 1-term. BQ=128, BKV=64
// smem: Q 32K | stage{0,1}: K 16K | V 16K  -> 96 KB
// ---------------------------------------------------------------------------
#define FQ 128
#define FK 64
#define FLASH_SMEM (32768 + 2 * 32768)

__device__ __forceinline__ uint32_t sw256(int row, int chunk) {
    return (uint32_t)(row * 256 + ((chunk ^ (row & 7)) << 4));
}

__device__ __forceinline__ void flash_load_kv(uint32_t sb, int t, int st,
                                              const __half* Kh, const __half* Vh, int tid) {
    uint32_t base = sb + 32768 + st * 32768;
    size_t g0 = (size_t)t * FK * HD;
#pragma unroll
    for (int l = 0; l < 4; l++) {
        int idx = tid + l * 256;      // 0..1023 = 64 rows x 16 chunks
        int row = idx >> 4;
        int c = idx & 15;
        uint32_t off = sw256(row, c);
        size_t go = g0 + (size_t)row * HD + c * 8;
        cp16(base + off, Kh + go);
        cp16(base + 16384 + off, Vh + go);
    }
}

__global__ __launch_bounds__(256) void flash_tc_kernel() {
    extern __shared__ char smem_raw[];
    uint32_t sb = (uint32_t)__cvta_generic_to_shared(smem_raw);
    uint32_t Qs = sb;

    int qt = (int)(gridDim.x - 1 - blockIdx.x);
    int h = blockIdx.y, b = blockIdx.z;
    int q0 = qt * FQ;
    int kh = h / GROUPS;

    int tid = threadIdx.x, lane = tid & 31, wid = tid >> 5;
    int mid = lane >> 3, rin = lane & 7;

    const __half* Qg = g_Qb + ((size_t)(b * NH + h) * SS + q0) * HD;
    const __half* Khg = g_Kb + (size_t)(b * NKV + kh) * SS * HD;
    const __half* Vhg = g_Vb + (size_t)(b * NKV + kh) * SS * HD;

#pragma unroll
    for (int l = 0; l < 8; l++) {
        int idx = tid + l * 256;      // 0..2047 = 128 rows x 16 chunks
        int row = idx >> 4;
        int c = idx & 15;
        cp16(Qs + sw256(row, c), Qg + (size_t)row * HD + c * 8);
    }
    flash_load_kv(sb, 0, 0, Khg, Vhg, tid);
    asm volatile("cp.async.commit_group;\n");

    float m_lo = -1e30f, m_hi = -1e30f, l_lo = 0.f, l_hi = 0.f;
    float oacc[16][4];
#pragma unroll
    for (int v = 0; v < 16; v++)
#pragma unroll
        for (int r = 0; r < 4; r++) oacc[v][r] = 0.f;

    const float scale = 0.08838834764831845f;
    const int ntile = 2 * qt + 2;
    const int rlo = q0 + wid * 16 + (lane >> 2);
    const int rhi = rlo + 8;

    for (int t = 0; t < ntile; t++) {
        int buf = t & 1;
        if (t + 1 < ntile) {
            flash_load_kv(sb, t + 1, buf ^ 1, Khg, Vhg, tid);
            asm volatile("cp.async.commit_group;\n");
            asm volatile("cp.async.wait_group 1;\n");
        } else {
            asm volatile("cp.async.wait_group 0;\n");
        }
        __syncthreads();

        uint32_t kb = sb + 32768 + buf * 32768;
        uint32_t vb = kb + 16384;

        float sacc[8][4];
#pragma unroll
        for (int n = 0; n < 8; n++)
#pragma unroll
            for (int r = 0; r < 4; r++) sacc[n][r] = 0.f;

#pragma unroll
        for (int kk = 0; kk < 8; kk++) {
            uint32_t ah[4];
            {
                int m_l = wid * 16 + (mid & 1) * 8 + rin;
                int chnk = kk * 2 + (mid >> 1);
                ldsm4(ah, Qs + sw256(m_l, chnk));
            }
#pragma unroll
            for (int j2 = 0; j2 < 4; j2++) {
                uint32_t bh[4];
                int n_l = (j2 * 2 + (mid >> 1)) * 8 + rin;
                int chnk = kk * 2 + (mid & 1);
                ldsm4(bh, kb + sw256(n_l, chnk));
#pragma unroll
                for (int jj = 0; jj < 2; jj++) {
                    int j = j2 * 2 + jj;
                    mma16816h(sacc[j], ah, bh[jj * 2], bh[jj * 2 + 1]);
                }
            }
        }

        int k0 = t * FK;
        bool diag = (t >= 2 * qt);
#pragma unroll
        for (int n = 0; n < 8; n++) {
            int c0 = k0 + n * 8 + (lane & 3) * 2;
            sacc[n][0] *= scale;
            sacc[n][1] *= scale;
            sacc[n][2] *= scale;
            sacc[n][3] *= scale;
            if (diag) {
                if (c0 > rlo) sacc[n][0] = -1e30f;
                if (c0 + 1 > rlo) sacc[n][1] = -1e30f;
                if (c0 > rhi) sacc[n][2] = -1e30f;
                if (c0 + 1 > rhi) sacc[n][3] = -1e30f;
            }
        }

        float mx0 = -1e30f, mx1 = -1e30f;
#pragma unroll
        for (int n = 0; n < 8; n++) {
            mx0 = fmaxf(mx0, fmaxf(sacc[n][0], sacc[n][1]));
            mx1 = fmaxf(mx1, fmaxf(sacc[n][2], sacc[n][3]));
        }
        mx0 = fmaxf(mx0, __shfl_xor_sync(0xffffffffu, mx0, 1));
        mx0 = fmaxf(mx0, __shfl_xor_sync(0xffffffffu, mx0, 2));
        mx1 = fmaxf(mx1, __shfl_xor_sync(0xffffffffu, mx1, 1));
        mx1 = fmaxf(mx1, __shfl_xor_sync(0xffffffffu, mx1, 2));
        float newm0 = fmaxf(m_lo, mx0);
        float newm1 = fmaxf(m_hi, mx1);
        float corr0 = __expf(m_lo - newm0);
        float corr1 = __expf(m_hi - newm1);
        m_lo = newm0;
        m_hi = newm1;

        float ls0 = 0.f, ls1 = 0.f;
#pragma unroll
        for (int n = 0; n < 8; n++) {
            sacc[n][0] = __expf(sacc[n][0] - newm0);
            sacc[n][1] = __expf(sacc[n][1] - newm0);
            sacc[n][2] = __expf(sacc[n][2] - newm1);
            sacc[n][3] = __expf(sacc[n][3] - newm1);
            ls0 += sacc[n][0] + sacc[n][1];
            ls1 += sacc[n][2] + sacc[n][3];
        }
        ls0 += __shfl_xor_sync(0xffffffffu, ls0, 1);
        ls0 += __shfl_xor_sync(0xffffffffu, ls0, 2);
        ls1 += __shfl_xor_sync(0xffffffffu, ls1, 1);
        ls1 += __shfl_xor_sync(0xffffffffu, ls1, 2);
        l_lo = l_lo * corr0 + ls0;
        l_hi = l_hi * corr1 + ls1;

#pragma unroll
        for (int v = 0; v < 16; v++) {
            oacc[v][0] *= corr0;
            oacc[v][1] *= corr0;
            oacc[v][2] *= corr1;
            oacc[v][3] *= corr1;
        }

        // ---- O += P V  (P rounded, V 1-term) ----
#pragma unroll
        for (int kk = 0; kk < 4; kk++) {
            uint32_t aph[4];
            aph[0] = pack_f2h2(sacc[2 * kk][0], sacc[2 * kk][1]);
            aph[1] = pack_f2h2(sacc[2 * kk][2], sacc[2 * kk][3]);
            aph[2] = pack_f2h2(sacc[2 * kk + 1][0], sacc[2 * kk + 1][1]);
            aph[3] = pack_f2h2(sacc[2 * kk + 1][2], sacc[2 * kk + 1][3]);
#pragma unroll
            for (int v2 = 0; v2 < 8; v2++) {
                int g = lane >> 3;
                int row = kk * 16 + (g & 1) * 8 + rin;
                int chnk = v2 * 2 + (g >> 1);
                uint32_t vh[4];
                ldsm4t(vh, vb + sw256(row, chnk));
#pragma unroll
                for (int gg = 0; gg < 2; gg++) {
                    int vnt = v2 * 2 + gg;
                    mma16816h(oacc[vnt], aph, vh[gg * 2], vh[gg * 2 + 1]);
                }
            }
        }
        __syncthreads();
    }

    // epilogue: normalize, write rounded fp16 for the out-proj
    float inv0 = 1.f / l_lo;
    float inv1 = 1.f / l_hi;
    int row0 = b * SS + q0 + wid * 16 + (lane >> 2);
    int row1 = row0 + 8;
#pragma unroll
    for (int v = 0; v < 16; v++) {
        int col = h * HD + v * 8 + (lane & 3) * 2;
        *(uint32_t*)(g_Ah + (size_t)row0 * KDIM + col) =
            pack_f2h2(oacc[v][0] * inv0, oacc[v][1] * inv0);
        *(uint32_t*)(g_Ah + (size_t)row1 * KDIM + col) =
            pack_f2h2(oacc[v][2] * inv1, oacc[v][3] * inv1);
    }
}

// ---------------------------------------------------------------------------
extern "C" void kernel_launch(void* const* d_in, const int* in_sizes, int n_in,
                              void* d_out, int out_size) {
    const float* X = (const float*)d_in[0];
    const float* Wq = (const float*)d_in[1];
    const float* Wk = (const float*)d_in[2];
    const float* Wv = (const float*)d_in[3];
    const float* Wo = (const float*)d_in[4];
    float* out = (float*)d_out;

    // 0. Round inputs to fp16 + RoPE table
    split_inputs_kernel<<<(N4_TOTAL + 255) / 256, 256>>>(X, Wq, Wk, Wv, Wo);
    rope_table_kernel<<<(SS * 64 + 255) / 256, 256>>>();

    // 1. QKV projections with fused RoPE + head-major fp16 epilogue
    cudaFuncSetAttribute(qkv_gemm_kernel, cudaFuncAttributeMaxDynamicSharedMemorySize,
                         QKV_SMEM);
    qkv_gemm_kernel<<<dim3(24, 32), 256, QKV_SMEM>>>();

    // 2. fp16 flash attention (1-term operands)
    cudaFuncSetAttribute(flash_tc_kernel, cudaFuncAttributeMaxDynamicSharedMemorySize,
                         FLASH_SMEM);
    flash_tc_kernel<<<dim3(SS / FQ, NH, BB), 256, FLASH_SMEM>>>();

    // 3. Output projection
    cudaFuncSetAttribute(out_gemm_kernel, cudaFuncAttributeMaxDynamicSharedMemorySize,
                         GEMM1T_SMEM);
    out_gemm_kernel<<<dim3(16, 32), 256, GEMM1T_SMEM>>>(out);
}

// round 9
// speedup vs baseline: 8.3982x; 1.0552x over previous
#include <cuda_runtime.h>
#include <cuda_fp16.h>
#include <math.h>
#include <stdint.h>

// Problem constants
#define BB 2
#define SS 2048
#define HH 2048
#define NH 16
#define NKV 4
#define HD 128
#define GROUPS (NH / NKV)        // 4
#define M_TOT (BB * SS)          // 4096
#define QDIM (NH * HD)           // 2048
#define KVDIM (NKV * HD)         // 512
#define KDIM 2048                // GEMM reduction dim

__device__ float g_cos[SS * 64];
__device__ float g_sin[SS * 64];

// fp16 buffers
__device__ __align__(16) __half g_Xh[M_TOT * KDIM];
__device__ __align__(16) __half g_Wqh[QDIM * KDIM];
__device__ __align__(16) __half g_Wkh[KVDIM * KDIM];
__device__ __align__(16) __half g_Wvh[KVDIM * KDIM];
__device__ __align__(16) __half g_Woh[HH * KDIM];
__device__ __align__(16) __half g_Ah[M_TOT * KDIM];     // flash out (rounded)

// fp16 head-major buffers for flash: [b, h, s, d]
__device__ __align__(16) __half g_Qb[M_TOT * QDIM];
__device__ __align__(16) __half g_Kb[M_TOT * KVDIM];
__device__ __align__(16) __half g_Vb[M_TOT * KVDIM];

// ---------------------------------------------------------------------------
// Helpers
// ---------------------------------------------------------------------------
__device__ __forceinline__ uint32_t pack_f2h2(float a, float b) {
    __half2 t(__float2half_rn(a), __float2half_rn(b));
    return *(uint32_t*)&t;
}
__device__ __forceinline__ void cp16(uint32_t saddr, const void* gaddr) {
    asm volatile("cp.async.cg.shared.global [%0], [%1], 16;\n" ::"r"(saddr), "l"(gaddr));
}
__device__ __forceinline__ void ldsm4(uint32_t* r, uint32_t addr) {
    asm volatile("ldmatrix.sync.aligned.m8n8.x4.shared.b16 {%0,%1,%2,%3}, [%4];\n"
                 : "=r"(r[0]), "=r"(r[1]), "=r"(r[2]), "=r"(r[3]) : "r"(addr));
}
__device__ __forceinline__ void ldsm4t(uint32_t* r, uint32_t addr) {
    asm volatile("ldmatrix.sync.aligned.m8n8.x4.trans.shared.b16 {%0,%1,%2,%3}, [%4];\n"
                 : "=r"(r[0]), "=r"(r[1]), "=r"(r[2]), "=r"(r[3]) : "r"(addr));
}
__device__ __forceinline__ void mma16816h(float* c, const uint32_t* a, uint32_t b0, uint32_t b1) {
    asm volatile("mma.sync.aligned.m16n8k16.row.col.f32.f16.f16.f32 "
                 "{%0,%1,%2,%3}, {%4,%5,%6,%7}, {%8,%9}, {%0,%1,%2,%3};\n"
                 : "+f"(c[0]), "+f"(c[1]), "+f"(c[2]), "+f"(c[3])
                 : "r"(a[0]), "r"(a[1]), "r"(a[2]), "r"(a[3]), "r"(b0), "r"(b1));
}

// ---------------------------------------------------------------------------
// Input split: X -> fp16, weights -> fp16 (all rounded)
// ---------------------------------------------------------------------------
#define N4_X  ((M_TOT * KDIM) / 4)
#define N4_WQ ((QDIM * KDIM) / 4)
#define N4_WKV ((KVDIM * KDIM) / 4)
#define N4_WO ((HH * KDIM) / 4)
#define N4_TOTAL (N4_X + N4_WQ + 2 * N4_WKV + N4_WO)

__global__ void split_inputs_kernel(const float* __restrict__ X,
                                    const float* __restrict__ Wq,
                                    const float* __restrict__ Wk,
                                    const float* __restrict__ Wv,
                                    const float* __restrict__ Wo) {
    int i = blockIdx.x * blockDim.x + threadIdx.x;
    if (i >= N4_TOTAL) return;
    const float* src;
    __half* dst;
    int off;
    if (i < N4_X) {
        src = X; dst = g_Xh; off = i;
    } else if (i < N4_X + N4_WQ) {
        src = Wq; dst = g_Wqh; off = i - N4_X;
    } else if (i < N4_X + N4_WQ + N4_WKV) {
        src = Wk; dst = g_Wkh; off = i - N4_X - N4_WQ;
    } else if (i < N4_X + N4_WQ + 2 * N4_WKV) {
        src = Wv; dst = g_Wvh; off = i - N4_X - N4_WQ - N4_WKV;
    } else {
        src = Wo; dst = g_Woh; off = i - N4_X - N4_WQ - 2 * N4_WKV;
    }
    float4 v = *(const float4*)(src + (size_t)off * 4);
    *(uint32_t*)(dst + (size_t)off * 4 + 0) = pack_f2h2(v.x, v.y);
    *(uint32_t*)(dst + (size_t)off * 4 + 2) = pack_f2h2(v.z, v.w);
}

// ---------------------------------------------------------------------------
// RoPE table
// ---------------------------------------------------------------------------
__global__ void rope_table_kernel() {
    int idx = blockIdx.x * blockDim.x + threadIdx.x;
    if (idx >= SS * 64) return;
    int pos = idx >> 6;
    int i = idx & 63;
    double inv = pow(10000.0, -(double)i / 64.0);
    double ang = (double)pos * inv;
    double sd, cd;
    sincos(ang, &sd, &cd);
    g_cos[idx] = (float)cd;
    g_sin[idx] = (float)sd;
}

// ---------------------------------------------------------------------------
// Shared GEMM smem swizzle (32-K chunks, 64B rows of fp16)
// ---------------------------------------------------------------------------
__device__ __forceinline__ uint32_t sw_off(int row, int k) {
    int c = (k >> 3) ^ (row & 3);
    return (uint32_t)((row * 4 + c) << 4);
}

#define STAGE1T 16384
#define KT16 (KDIM / 32)   // 64

__device__ __forceinline__ void load_stage1t(uint32_t S, int buf,
                                             const __half* __restrict__ A,
                                             const __half* __restrict__ B,
                                             int m0, int n0, int k0, int tid) {
    uint32_t st = S + buf * STAGE1T;
#pragma unroll
    for (int l = 0; l < 2; l++) {
        int idx = tid + l * 256;          // 0..511 = 128 rows x 4 chunks
        int row = idx >> 2;
        int c = idx & 3;
        uint32_t spos = sw_off(row, c * 8);
        size_t ga = (size_t)(m0 + row) * KDIM + k0 + c * 8;
        size_t gb = (size_t)(n0 + row) * KDIM + k0 + c * 8;
        cp16(st + spos, A + ga);
        cp16(st + 8192 + spos, B + gb);
    }
    asm volatile("cp.async.commit_group;\n");
}

// Core 128x128x2048 mainloop, leaves result in acc[4][4][4]
#define GEMM_MAINLOOP(A, B, m0, n0)                                                   \
    float acc[4][4][4];                                                               \
    _Pragma("unroll") for (int i = 0; i < 4; i++)                                     \
        _Pragma("unroll") for (int j = 0; j < 4; j++)                                 \
            _Pragma("unroll") for (int r = 0; r < 4; r++) acc[i][j][r] = 0.f;         \
    load_stage1t(S, 0, A, B, m0, n0, 0, tid);                                         \
    load_stage1t(S, 1, A, B, m0, n0, 32, tid);                                        \
    for (int kt = 0; kt < KT16; kt++) {                                               \
        if (kt < KT16 - 1)                                                            \
            asm volatile("cp.async.wait_group 1;\n");                                 \
        else                                                                          \
            asm volatile("cp.async.wait_group 0;\n");                                 \
        __syncthreads();                                                              \
        if (kt + 2 < KT16)                                                            \
            load_stage1t(S, (kt + 2) % 3, A, B, m0, n0, (kt + 2) * 32, tid);          \
        uint32_t aB = S + (kt % 3) * STAGE1T;                                         \
        uint32_t bB = aB + 8192;                                                      \
        _Pragma("unroll") for (int kk = 0; kk < 2; kk++) {                            \
            uint32_t ah[4][4];                                                        \
            _Pragma("unroll") for (int i = 0; i < 4; i++) {                           \
                int m_l = wm * 64 + i * 16 + (mid & 1) * 8 + rin;                     \
                int k_l = kk * 16 + (mid >> 1) * 8;                                   \
                ldsm4(ah[i], aB + sw_off(m_l, k_l));                                  \
            }                                                                         \
            _Pragma("unroll") for (int j2 = 0; j2 < 2; j2++) {                        \
                uint32_t bh[4];                                                       \
                int n_l = wn * 32 + (j2 * 2 + (mid >> 1)) * 8 + rin;                  \
                int k_l = kk * 16 + (mid & 1) * 8;                                    \
                ldsm4(bh, bB + sw_off(n_l, k_l));                                     \
                _Pragma("unroll") for (int jj = 0; jj < 2; jj++) {                    \
                    int j = j2 * 2 + jj;                                              \
                    _Pragma("unroll") for (int i = 0; i < 4; i++)                     \
                        mma16816h(acc[i][j], ah[i], bh[jj * 2], bh[jj * 2 + 1]);      \
                }                                                                     \
            }                                                                         \
        }                                                                             \
    }

// ---------------------------------------------------------------------------
// QKV GEMM with fused RoPE + fp16 head-major epilogue.
// grid (24, 32): bx 0-15 Q heads, 16-19 K heads, 20-23 V heads.
// ---------------------------------------------------------------------------
#define QKV_SMEM 67584

__global__ __launch_bounds__(256, 2) void qkv_gemm_kernel() {
    extern __shared__ char smem_raw[];
    uint32_t S = (uint32_t)__cvta_generic_to_shared(smem_raw);
    int tid = threadIdx.x;
    int lane = tid & 31, wid = tid >> 5;
    int wm = wid & 1, wn = wid >> 1;
    int mid = lane >> 3, rin = lane & 7;

    int bx = blockIdx.x;
    int m0 = blockIdx.y * 128;

    const __half* A = g_Xh;
    const __half* B;
    __half* dstH;
    int head, nhd;
    bool do_rope;
    if (bx < 16) {
        B = g_Wqh; dstH = g_Qb; head = bx; nhd = NH; do_rope = true;
    } else if (bx < 20) {
        B = g_Wkh; dstH = g_Kb; head = bx - 16; nhd = NKV; do_rope = true;
    } else {
        B = g_Wvh; dstH = g_Vb; head = bx - 20; nhd = NKV; do_rope = false;
    }
    int n0 = head * HD;

    GEMM_MAINLOOP(A, B, m0, n0)

    // ---- fused epilogue: stage fp32 tile in smem, rope pairs, fp16 out ----
    __syncthreads();
    float* tile = (float*)smem_raw;
#pragma unroll
    for (int i = 0; i < 4; i++) {
#pragma unroll
        for (int j = 0; j < 4; j++) {
            int r0 = wm * 64 + i * 16 + (lane >> 2);
            int cc = wn * 32 + j * 8 + (lane & 3) * 2;
            *(float2*)&tile[r0 * 132 + cc] = make_float2(acc[i][j][0], acc[i][j][1]);
            *(float2*)&tile[(r0 + 8) * 132 + cc] = make_float2(acc[i][j][2], acc[i][j][3]);
        }
    }
    __syncthreads();

    for (int it = tid; it < 128 * 64; it += 256) {
        int row = it >> 6, d = it & 63;
        int m = m0 + row;
        int s = m & (SS - 1), b = m >> 11;
        float x1 = tile[row * 132 + d];
        float x2 = tile[row * 132 + d + 64];
        float y1 = x1, y2 = x2;
        if (do_rope) {
            float c = g_cos[s * 64 + d], sn = g_sin[s * 64 + d];
            y1 = x1 * c - x2 * sn;
            y2 = x2 * c + x1 * sn;
        }
        size_t dst = ((size_t)(b * nhd + head) * SS + s) * HD + d;
        dstH[dst] = __float2half_rn(y1);
        dstH[dst + 64] = __float2half_rn(y2);
    }
}

// ---------------------------------------------------------------------------
// Output projection (1-term, fp32 out)
// ---------------------------------------------------------------------------
#define GEMM1T_SMEM (3 * STAGE1T)

__global__ __launch_bounds__(256, 2) void out_gemm_kernel(float* __restrict__ out) {
    extern __shared__ char smem_raw[];
    uint32_t S = (uint32_t)__cvta_generic_to_shared(smem_raw);
    int tid = threadIdx.x;
    int lane = tid & 31, wid = tid >> 5;
    int wm = wid & 1, wn = wid >> 1;
    int mid = lane >> 3, rin = lane & 7;
    int m0 = blockIdx.y * 128, n0 = blockIdx.x * 128;

    GEMM_MAINLOOP(g_Ah, g_Woh, m0, n0)

#pragma unroll
    for (int i = 0; i < 4; i++) {
#pragma unroll
        for (int j = 0; j < 4; j++) {
            int r0 = m0 + wm * 64 + i * 16 + (lane >> 2);
            int cc = n0 + wn * 32 + j * 8 + (lane & 3) * 2;
            *(float2*)&out[(size_t)r0 * HH + cc] = make_float2(acc[i][j][0], acc[i][j][1]);
            *(float2*)&out[(size_t)(r0 + 8) * HH + cc] = make_float2(acc[i][j][2], acc[i][j][3]);
        }
    }
}

// ---------------------------------------------------------------------------
// fp16 flash attention (causal), 1-term operands.
// BQ=64, 4 warps (128 threads), 2 CTAs/SM for phase interleaving.
// smem: Q 16K | stage{0,1}: K 16K | V 16K  -> 80 KB
// ---------------------------------------------------------------------------
#define FQ 64
#define FK 64
#define FTHREADS 128
#define FLASH_SMEM (16384 + 2 * 32768)

__device__ __forceinline__ uint32_t sw256(int row, int chunk) {
    return (uint32_t)(row * 256 + ((chunk ^ (row & 7)) << 4));
}

__device__ __forceinline__ void flash_load_kv(uint32_t sb, int t, int st,
                                              const __half* Kh, const __half* Vh, int tid) {
    uint32_t base = sb + 16384 + st * 32768;
    size_t g0 = (size_t)t * FK * HD;
#pragma unroll
    for (int l = 0; l < 8; l++) {
        int idx = tid + l * FTHREADS;    // 0..1023 = 64 rows x 16 chunks
        int row = idx >> 4;
        int c = idx & 15;
        uint32_t off = sw256(row, c);
        size_t go = g0 + (size_t)row * HD + c * 8;
        cp16(base + off, Kh + go);
        cp16(base + 16384 + off, Vh + go);
    }
}

__global__ __launch_bounds__(FTHREADS, 2) void flash_tc_kernel() {
    extern __shared__ char smem_raw[];
    uint32_t sb = (uint32_t)__cvta_generic_to_shared(smem_raw);
    uint32_t Qs = sb;

    int qt = (int)(gridDim.x - 1 - blockIdx.x);   // big tiles first
    int h = blockIdx.y, b = blockIdx.z;
    int q0 = qt * FQ;
    int kh = h / GROUPS;

    int tid = threadIdx.x, lane = tid & 31, wid = tid >> 5;  // wid 0..3
    int mid = lane >> 3, rin = lane & 7;

    const __half* Qg = g_Qb + ((size_t)(b * NH + h) * SS + q0) * HD;
    const __half* Khg = g_Kb + (size_t)(b * NKV + kh) * SS * HD;
    const __half* Vhg = g_Vb + (size_t)(b * NKV + kh) * SS * HD;

#pragma unroll
    for (int l = 0; l < 8; l++) {
        int idx = tid + l * FTHREADS;    // 0..1023 = 64 rows x 16 chunks
        int row = idx >> 4;
        int c = idx & 15;
        cp16(Qs + sw256(row, c), Qg + (size_t)row * HD + c * 8);
    }
    flash_load_kv(sb, 0, 0, Khg, Vhg, tid);
    asm volatile("cp.async.commit_group;\n");

    float m_lo = -1e30f, m_hi = -1e30f, l_lo = 0.f, l_hi = 0.f;
    float oacc[16][4];
#pragma unroll
    for (int v = 0; v < 16; v++)
#pragma unroll
        for (int r = 0; r < 4; r++) oacc[v][r] = 0.f;

    const float scale = 0.08838834764831845f;
    const int ntile = qt + 1;
    const int rlo = q0 + wid * 16 + (lane >> 2);
    const int rhi = rlo + 8;

    for (int t = 0; t < ntile; t++) {
        int buf = t & 1;
        if (t + 1 < ntile) {
            flash_load_kv(sb, t + 1, buf ^ 1, Khg, Vhg, tid);
            asm volatile("cp.async.commit_group;\n");
            asm volatile("cp.async.wait_group 1;\n");
        } else {
            asm volatile("cp.async.wait_group 0;\n");
        }
        __syncthreads();

        uint32_t kb = sb + 16384 + buf * 32768;
        uint32_t vb = kb + 16384;

        float sacc[8][4];
#pragma unroll
        for (int n = 0; n < 8; n++)
#pragma unroll
            for (int r = 0; r < 4; r++) sacc[n][r] = 0.f;

#pragma unroll
        for (int kk = 0; kk < 8; kk++) {
            uint32_t ah[4];
            {
                int m_l = wid * 16 + (mid & 1) * 8 + rin;
                int chnk = kk * 2 + (mid >> 1);
                ldsm4(ah, Qs + sw256(m_l, chnk));
            }
#pragma unroll
            for (int j2 = 0; j2 < 4; j2++) {
                uint32_t bh[4];
                int n_l = (j2 * 2 + (mid >> 1)) * 8 + rin;
                int chnk = kk * 2 + (mid & 1);
                ldsm4(bh, kb + sw256(n_l, chnk));
#pragma unroll
                for (int jj = 0; jj < 2; jj++) {
                    int j = j2 * 2 + jj;
                    mma16816h(sacc[j], ah, bh[jj * 2], bh[jj * 2 + 1]);
                }
            }
        }

        int k0 = t * FK;
        bool diag = (t == ntile - 1);
#pragma unroll
        for (int n = 0; n < 8; n++) {
            int c0 = k0 + n * 8 + (lane & 3) * 2;
            sacc[n][0] *= scale;
            sacc[n][1] *= scale;
            sacc[n][2] *= scale;
            sacc[n][3] *= scale;
            if (diag) {
                if (c0 > rlo) sacc[n][0] = -1e30f;
                if (c0 + 1 > rlo) sacc[n][1] = -1e30f;
                if (c0 > rhi) sacc[n][2] = -1e30f;
                if (c0 + 1 > rhi) sacc[n][3] = -1e30f;
            }
        }

        float mx0 = -1e30f, mx1 = -1e30f;
#pragma unroll
        for (int n = 0; n < 8; n++) {
            mx0 = fmaxf(mx0, fmaxf(sacc[n][0], sacc[n][1]));
            mx1 = fmaxf(mx1, fmaxf(sacc[n][2], sacc[n][3]));
        }
        mx0 = fmaxf(mx0, __shfl_xor_sync(0xffffffffu, mx0, 1));
        mx0 = fmaxf(mx0, __shfl_xor_sync(0xffffffffu, mx0, 2));
        mx1 = fmaxf(mx1, __shfl_xor_sync(0xffffffffu, mx1, 1));
        mx1 = fmaxf(mx1, __shfl_xor_sync(0xffffffffu, mx1, 2));
        float newm0 = fmaxf(m_lo, mx0);
        float newm1 = fmaxf(m_hi, mx1);
        float corr0 = __expf(m_lo - newm0);
        float corr1 = __expf(m_hi - newm1);
        m_lo = newm0;
        m_hi = newm1;

        float ls0 = 0.f, ls1 = 0.f;
#pragma unroll
        for (int n = 0; n < 8; n++) {
            sacc[n][0] = __expf(sacc[n][0] - newm0);
            sacc[n][1] = __expf(sacc[n][1] - newm0);
            sacc[n][2] = __expf(sacc[n][2] - newm1);
            sacc[n][3] = __expf(sacc[n][3] - newm1);
            ls0 += sacc[n][0] + sacc[n][1];
            ls1 += sacc[n][2] + sacc[n][3];
        }
        ls0 += __shfl_xor_sync(0xffffffffu, ls0, 1);
        ls0 += __shfl_xor_sync(0xffffffffu, ls0, 2);
        ls1 += __shfl_xor_sync(0xffffffffu, ls1, 1);
        ls1 += __shfl_xor_sync(0xffffffffu, ls1, 2);
        l_lo = l_lo * corr0 + ls0;
        l_hi = l_hi * corr1 + ls1;

#pragma unroll
        for (int v = 0; v < 16; v++) {
            oacc[v][0] *= corr0;
            oacc[v][1] *= corr0;
            oacc[v][2] *= corr1;
            oacc[v][3] *= corr1;
        }

        // ---- O += P V  (P rounded, V 1-term) ----
#pragma unroll
        for (int kk = 0; kk < 4; kk++) {
            uint32_t aph[4];
            aph[0] = pack_f2h2(sacc[2 * kk][0], sacc[2 * kk][1]);
            aph[1] = pack_f2h2(sacc[2 * kk][2], sacc[2 * kk][3]);
            aph[2] = pack_f2h2(sacc[2 * kk + 1][0], sacc[2 * kk + 1][1]);
            aph[3] = pack_f2h2(sacc[2 * kk + 1][2], sacc[2 * kk + 1][3]);
#pragma unroll
            for (int v2 = 0; v2 < 8; v2++) {
                int g = lane >> 3;
                int row = kk * 16 + (g & 1) * 8 + rin;
                int chnk = v2 * 2 + (g >> 1);
                uint32_t vh[4];
                ldsm4t(vh, vb + sw256(row, chnk));
#pragma unroll
                for (int gg = 0; gg < 2; gg++) {
                    int vnt = v2 * 2 + gg;
                    mma16816h(oacc[vnt], aph, vh[gg * 2], vh[gg * 2 + 1]);
                }
            }
        }
        __syncthreads();
    }

    // epilogue: normalize, write rounded fp16 for the out-proj
    float inv0 = 1.f / l_lo;
    float inv1 = 1.f / l_hi;
    int row0 = b * SS + q0 + wid * 16 + (lane >> 2);
    int row1 = row0 + 8;
#pragma unroll
    for (int v = 0; v < 16; v++) {
        int col = h * HD + v * 8 + (lane & 3) * 2;
        *(uint32_t*)(g_Ah + (size_t)row0 * KDIM + col) =
            pack_f2h2(oacc[v][0] * inv0, oacc[v][1] * inv0);
        *(uint32_t*)(g_Ah + (size_t)row1 * KDIM + col) =
            pack_f2h2(oacc[v][2] * inv1, oacc[v][3] * inv1);
    }
}

// ---------------------------------------------------------------------------
extern "C" void kernel_launch(void* const* d_in, const int* in_sizes, int n_in,
                              void* d_out, int out_size) {
    const float* X = (const float*)d_in[0];
    const float* Wq = (const float*)d_in[1];
    const float* Wk = (const float*)d_in[2];
    const float* Wv = (const float*)d_in[3];
    const float* Wo = (const float*)d_in[4];
    float* out = (float*)d_out;

    // 0. Round inputs to fp16 + RoPE table
    split_inputs_kernel<<<(N4_TOTAL + 255) / 256, 256>>>(X, Wq, Wk, Wv, Wo);
    rope_table_kernel<<<(SS * 64 + 255) / 256, 256>>>();

    // 1. QKV projections with fused RoPE + head-major fp16 epilogue
    cudaFuncSetAttribute(qkv_gemm_kernel, cudaFuncAttributeMaxDynamicSharedMemorySize,
                         QKV_SMEM);
    qkv_gemm_kernel<<<dim3(24, 32), 256, QKV_SMEM>>>();

    // 2. fp16 flash attention (BQ=64, 4 warps, 2 CTAs/SM)
    cudaFuncSetAttribute(flash_tc_kernel, cudaFuncAttributeMaxDynamicSharedMemorySize,
                         FLASH_SMEM);
    flash_tc_kernel<<<dim3(SS / FQ, NH, BB), FTHREADS, FLASH_SMEM>>>();

    // 3. Output projection
    cudaFuncSetAttribute(out_gemm_kernel, cudaFuncAttributeMaxDynamicSharedMemorySize,
                         GEMM1T_SMEM);
    out_gemm_kernel<<<dim3(16, 32), 256, GEMM1T_SMEM>>>(out);
}

// round 10
// speedup vs baseline: 8.4994x; 1.0121x over previous
#include <cuda_runtime.h>
#include <cuda_fp16.h>
#include <math.h>
#include <stdint.h>

// Problem constants
#define BB 2
#define SS 2048
#define HH 2048
#define NH 16
#define NKV 4
#define HD 128
#define GROUPS (NH / NKV)        // 4
#define M_TOT (BB * SS)          // 4096
#define QDIM (NH * HD)           // 2048
#define KVDIM (NKV * HD)         // 512
#define KDIM 2048                // GEMM reduction dim

__device__ float g_cos[SS * 64];
__device__ float g_sin[SS * 64];

// fp16 buffers
__device__ __align__(16) __half g_Xh[M_TOT * KDIM];
__device__ __align__(16) __half g_Wqh[QDIM * KDIM];
__device__ __align__(16) __half g_Wkh[KVDIM * KDIM];
__device__ __align__(16) __half g_Wvh[KVDIM * KDIM];
__device__ __align__(16) __half g_Woh[HH * KDIM];
__device__ __align__(16) __half g_Ah[M_TOT * KDIM];     // flash out (rounded)

// fp16 head-major buffers for flash: [b, h, s, d]
__device__ __align__(16) __half g_Qb[M_TOT * QDIM];
__device__ __align__(16) __half g_Kb[M_TOT * KVDIM];
__device__ __align__(16) __half g_Vb[M_TOT * KVDIM];

// ---------------------------------------------------------------------------
// Helpers
// ---------------------------------------------------------------------------
__device__ __forceinline__ uint32_t pack_f2h2(float a, float b) {
    __half2 t(__float2half_rn(a), __float2half_rn(b));
    return *(uint32_t*)&t;
}
__device__ __forceinline__ void cp16(uint32_t saddr, const void* gaddr) {
    asm volatile("cp.async.cg.shared.global [%0], [%1], 16;\n" ::"r"(saddr), "l"(gaddr));
}
__device__ __forceinline__ void ldsm4(uint32_t* r, uint32_t addr) {
    asm volatile("ldmatrix.sync.aligned.m8n8.x4.shared.b16 {%0,%1,%2,%3}, [%4];\n"
                 : "=r"(r[0]), "=r"(r[1]), "=r"(r[2]), "=r"(r[3]) : "r"(addr));
}
__device__ __forceinline__ void ldsm4t(uint32_t* r, uint32_t addr) {
    asm volatile("ldmatrix.sync.aligned.m8n8.x4.trans.shared.b16 {%0,%1,%2,%3}, [%4];\n"
                 : "=r"(r[0]), "=r"(r[1]), "=r"(r[2]), "=r"(r[3]) : "r"(addr));
}
__device__ __forceinline__ void mma16816h(float* c, const uint32_t* a, uint32_t b0, uint32_t b1) {
    asm volatile("mma.sync.aligned.m16n8k16.row.col.f32.f16.f16.f32 "
                 "{%0,%1,%2,%3}, {%4,%5,%6,%7}, {%8,%9}, {%0,%1,%2,%3};\n"
                 : "+f"(c[0]), "+f"(c[1]), "+f"(c[2]), "+f"(c[3])
                 : "r"(a[0]), "r"(a[1]), "r"(a[2]), "r"(a[3]), "r"(b0), "r"(b1));
}

// ---------------------------------------------------------------------------
// Input split: X -> fp16, weights -> fp16 (all rounded) + RoPE table (fused)
// ---------------------------------------------------------------------------
#define N4_X  ((M_TOT * KDIM) / 4)
#define N4_WQ ((QDIM * KDIM) / 4)
#define N4_WKV ((KVDIM * KDIM) / 4)
#define N4_WO ((HH * KDIM) / 4)
#define N4_TOTAL (N4_X + N4_WQ + 2 * N4_WKV + N4_WO)
#define NT_ROPE (SS * 64)
#define SPLIT_TOTAL (N4_TOTAL + NT_ROPE)

__global__ void split_inputs_kernel(const float* __restrict__ X,
                                    const float* __restrict__ Wq,
                                    const float* __restrict__ Wk,
                                    const float* __restrict__ Wv,
                                    const float* __restrict__ Wo) {
    int i = blockIdx.x * blockDim.x + threadIdx.x;
    if (i >= SPLIT_TOTAL) return;
    if (i >= N4_TOTAL) {
        int idx = i - N4_TOTAL;           // rope table entry
        int pos = idx >> 6;
        int d = idx & 63;
        double inv = pow(10000.0, -(double)d / 64.0);
        double ang = (double)pos * inv;
        double sd, cd;
        sincos(ang, &sd, &cd);
        g_cos[idx] = (float)cd;
        g_sin[idx] = (float)sd;
        return;
    }
    const float* src;
    __half* dst;
    int off;
    if (i < N4_X) {
        src = X; dst = g_Xh; off = i;
    } else if (i < N4_X + N4_WQ) {
        src = Wq; dst = g_Wqh; off = i - N4_X;
    } else if (i < N4_X + N4_WQ + N4_WKV) {
        src = Wk; dst = g_Wkh; off = i - N4_X - N4_WQ;
    } else if (i < N4_X + N4_WQ + 2 * N4_WKV) {
        src = Wv; dst = g_Wvh; off = i - N4_X - N4_WQ - N4_WKV;
    } else {
        src = Wo; dst = g_Woh; off = i - N4_X - N4_WQ - 2 * N4_WKV;
    }
    float4 v = *(const float4*)(src + (size_t)off * 4);
    *(uint32_t*)(dst + (size_t)off * 4 + 0) = pack_f2h2(v.x, v.y);
    *(uint32_t*)(dst + (size_t)off * 4 + 2) = pack_f2h2(v.z, v.w);
}

// ---------------------------------------------------------------------------
// Shared GEMM smem swizzle (32-K chunks, 64B rows of fp16)
// ---------------------------------------------------------------------------
__device__ __forceinline__ uint32_t sw_off(int row, int k) {
    int c = (k >> 3) ^ (row & 3);
    return (uint32_t)((row * 4 + c) << 4);
}

#define STAGE1T 16384
#define KT16 (KDIM / 32)   // 64

__device__ __forceinline__ void load_stage1t(uint32_t S, int buf,
                                             const __half* __restrict__ A,
                                             const __half* __restrict__ B,
                                             int m0, int n0, int k0, int tid) {
    uint32_t st = S + buf * STAGE1T;
#pragma unroll
    for (int l = 0; l < 2; l++) {
        int idx = tid + l * 256;          // 0..511 = 128 rows x 4 chunks
        int row = idx >> 2;
        int c = idx & 3;
        uint32_t spos = sw_off(row, c * 8);
        size_t ga = (size_t)(m0 + row) * KDIM + k0 + c * 8;
        size_t gb = (size_t)(n0 + row) * KDIM + k0 + c * 8;
        cp16(st + spos, A + ga);
        cp16(st + 8192 + spos, B + gb);
    }
    asm volatile("cp.async.commit_group;\n");
}

// Core 128x128x2048 mainloop, leaves result in acc[4][4][4]
#define GEMM_MAINLOOP(A, B, m0, n0)                                                   \
    float acc[4][4][4];                                                               \
    _Pragma("unroll") for (int i = 0; i < 4; i++)                                     \
        _Pragma("unroll") for (int j = 0; j < 4; j++)                                 \
            _Pragma("unroll") for (int r = 0; r < 4; r++) acc[i][j][r] = 0.f;         \
    load_stage1t(S, 0, A, B, m0, n0, 0, tid);                                         \
    load_stage1t(S, 1, A, B, m0, n0, 32, tid);                                        \
    for (int kt = 0; kt < KT16; kt++) {                                               \
        if (kt < KT16 - 1)                                                            \
            asm volatile("cp.async.wait_group 1;\n");                                 \
        else                                                                          \
            asm volatile("cp.async.wait_group 0;\n");                                 \
        __syncthreads();                                                              \
        if (kt + 2 < KT16)                                                            \
            load_stage1t(S, (kt + 2) % 3, A, B, m0, n0, (kt + 2) * 32, tid);          \
        uint32_t aB = S + (kt % 3) * STAGE1T;                                         \
        uint32_t bB = aB + 8192;                                                      \
        _Pragma("unroll") for (int kk = 0; kk < 2; kk++) {                            \
            uint32_t ah[4][4];                                                        \
            _Pragma("unroll") for (int i = 0; i < 4; i++) {                           \
                int m_l = wm * 64 + i * 16 + (mid & 1) * 8 + rin;                     \
                int k_l = kk * 16 + (mid >> 1) * 8;                                   \
                ldsm4(ah[i], aB + sw_off(m_l, k_l));                                  \
            }                                                                         \
            _Pragma("unroll") for (int j2 = 0; j2 < 2; j2++) {                        \
                uint32_t bh[4];                                                       \
                int n_l = wn * 32 + (j2 * 2 + (mid >> 1)) * 8 + rin;                  \
                int k_l = kk * 16 + (mid & 1) * 8;                                    \
                ldsm4(bh, bB + sw_off(n_l, k_l));                                     \
                _Pragma("unroll") for (int jj = 0; jj < 2; jj++) {                    \
                    int j = j2 * 2 + jj;                                              \
                    _Pragma("unroll") for (int i = 0; i < 4; i++)                     \
                        mma16816h(acc[i][j], ah[i], bh[jj * 2], bh[jj * 2 + 1]);      \
                }                                                                     \
            }                                                                         \
        }                                                                             \
    }

// ---------------------------------------------------------------------------
// QKV GEMM with fused RoPE + fp16 head-major epilogue.
// grid (24, 32): bx 0-15 Q heads, 16-19 K heads, 20-23 V heads.
// ---------------------------------------------------------------------------
#define QKV_SMEM 67584

__global__ __launch_bounds__(256, 2) void qkv_gemm_kernel() {
    extern __shared__ char smem_raw[];
    uint32_t S = (uint32_t)__cvta_generic_to_shared(smem_raw);
    int tid = threadIdx.x;
    int lane = tid & 31, wid = tid >> 5;
    int wm = wid & 1, wn = wid >> 1;
    int mid = lane >> 3, rin = lane & 7;

    int bx = blockIdx.x;
    int m0 = blockIdx.y * 128;

    const __half* A = g_Xh;
    const __half* B;
    __half* dstH;
    int head, nhd;
    bool do_rope;
    if (bx < 16) {
        B = g_Wqh; dstH = g_Qb; head = bx; nhd = NH; do_rope = true;
    } else if (bx < 20) {
        B = g_Wkh; dstH = g_Kb; head = bx - 16; nhd = NKV; do_rope = true;
    } else {
        B = g_Wvh; dstH = g_Vb; head = bx - 20; nhd = NKV; do_rope = false;
    }
    int n0 = head * HD;

    GEMM_MAINLOOP(A, B, m0, n0)

    // ---- fused epilogue: stage fp32 tile in smem, rope pairs, fp16 out ----
    __syncthreads();
    float* tile = (float*)smem_raw;
#pragma unroll
    for (int i = 0; i < 4; i++) {
#pragma unroll
        for (int j = 0; j < 4; j++) {
            int r0 = wm * 64 + i * 16 + (lane >> 2);
            int cc = wn * 32 + j * 8 + (lane & 3) * 2;
            *(float2*)&tile[r0 * 132 + cc] = make_float2(acc[i][j][0], acc[i][j][1]);
            *(float2*)&tile[(r0 + 8) * 132 + cc] = make_float2(acc[i][j][2], acc[i][j][3]);
        }
    }
    __syncthreads();

    for (int it = tid; it < 128 * 64; it += 256) {
        int row = it >> 6, d = it & 63;
        int m = m0 + row;
        int s = m & (SS - 1), b = m >> 11;
        float x1 = tile[row * 132 + d];
        float x2 = tile[row * 132 + d + 64];
        float y1 = x1, y2 = x2;
        if (do_rope) {
            float c = g_cos[s * 64 + d], sn = g_sin[s * 64 + d];
            y1 = x1 * c - x2 * sn;
            y2 = x2 * c + x1 * sn;
        }
        size_t dst = ((size_t)(b * nhd + head) * SS + s) * HD + d;
        dstH[dst] = __float2half_rn(y1);
        dstH[dst + 64] = __float2half_rn(y2);
    }
}

// ---------------------------------------------------------------------------
// Output projection (1-term, fp32 out)
// ---------------------------------------------------------------------------
#define GEMM1T_SMEM (3 * STAGE1T)

__global__ __launch_bounds__(256, 2) void out_gemm_kernel(float* __restrict__ out) {
    extern __shared__ char smem_raw[];
    uint32_t S = (uint32_t)__cvta_generic_to_shared(smem_raw);
    int tid = threadIdx.x;
    int lane = tid & 31, wid = tid >> 5;
    int wm = wid & 1, wn = wid >> 1;
    int mid = lane >> 3, rin = lane & 7;
    int m0 = blockIdx.y * 128, n0 = blockIdx.x * 128;

    GEMM_MAINLOOP(g_Ah, g_Woh, m0, n0)

#pragma unroll
    for (int i = 0; i < 4; i++) {
#pragma unroll
        for (int j = 0; j < 4; j++) {
            int r0 = m0 + wm * 64 + i * 16 + (lane >> 2);
            int cc = n0 + wn * 32 + j * 8 + (lane & 3) * 2;
            *(float2*)&out[(size_t)r0 * HH + cc] = make_float2(acc[i][j][0], acc[i][j][1]);
            *(float2*)&out[(size_t)(r0 + 8) * HH + cc] = make_float2(acc[i][j][2], acc[i][j][3]);
        }
    }
}

// ---------------------------------------------------------------------------
// fp16 flash attention (causal), 1-term operands.
// BQ=64, 4 warps, 2 CTAs/SM. Q held in registers; exp2-domain softmax.
// smem: 2 stages x (K 16K | V 16K) = 64 KB
// ---------------------------------------------------------------------------
#define FQ 64
#define FK 64
#define FTHREADS 128
#define FLASH_SMEM (2 * 32768)

__device__ __forceinline__ uint32_t sw256(int row, int chunk) {
    return (uint32_t)(row * 256 + ((chunk ^ (row & 7)) << 4));
}

__device__ __forceinline__ void flash_load_kv(uint32_t sb, int t, int st,
                                              const __half* Kh, const __half* Vh, int tid) {
    uint32_t base = sb + st * 32768;
    size_t g0 = (size_t)t * FK * HD;
#pragma unroll
    for (int l = 0; l < 8; l++) {
        int idx = tid + l * FTHREADS;    // 0..1023 = 64 rows x 16 chunks
        int row = idx >> 4;
        int c = idx & 15;
        uint32_t off = sw256(row, c);
        size_t go = g0 + (size_t)row * HD + c * 8;
        cp16(base + off, Kh + go);
        cp16(base + 16384 + off, Vh + go);
    }
}

__global__ __launch_bounds__(FTHREADS, 2) void flash_tc_kernel() {
    extern __shared__ char smem_raw[];
    uint32_t sb = (uint32_t)__cvta_generic_to_shared(smem_raw);

    int qt = (int)(gridDim.x - 1 - blockIdx.x);   // big tiles first
    int h = blockIdx.y, b = blockIdx.z;
    int q0 = qt * FQ;
    int kh = h / GROUPS;

    int tid = threadIdx.x, lane = tid & 31, wid = tid >> 5;  // wid 0..3
    int mid = lane >> 3, rin = lane & 7;

    const __half* Qg = g_Qb + ((size_t)(b * NH + h) * SS + q0) * HD;
    const __half* Khg = g_Kb + (size_t)(b * NKV + kh) * SS * HD;
    const __half* Vhg = g_Vb + (size_t)(b * NKV + kh) * SS * HD;

    // ---- Stage Q transiently in buf1, pull fragments to registers ----
    uint32_t Qstage = sb + 32768;
#pragma unroll
    for (int l = 0; l < 8; l++) {
        int idx = tid + l * FTHREADS;    // 0..1023 = 64 rows x 16 chunks
        int row = idx >> 4;
        int c = idx & 15;
        cp16(Qstage + sw256(row, c), Qg + (size_t)row * HD + c * 8);
    }
    asm volatile("cp.async.commit_group;\n");
    flash_load_kv(sb, 0, 0, Khg, Vhg, tid);       // KV0 -> buf0
    asm volatile("cp.async.commit_group;\n");

    asm volatile("cp.async.wait_group 1;\n");     // Q done (KV0 may be in flight)
    __syncthreads();
    uint32_t qreg[8][4];
#pragma unroll
    for (int kk = 0; kk < 8; kk++) {
        int m_l = wid * 16 + (mid & 1) * 8 + rin;
        int chnk = kk * 2 + (mid >> 1);
        ldsm4(qreg[kk], Qstage + sw256(m_l, chnk));
    }
    __syncthreads();   // everyone done reading Q before buf1 is overwritten

    float m_lo = -1e30f, m_hi = -1e30f, l_lo = 0.f, l_hi = 0.f;
    float oacc[16][4];
#pragma unroll
    for (int v = 0; v < 16; v++)
#pragma unroll
        for (int r = 0; r < 4; r++) oacc[v][r] = 0.f;

    // exp2 domain: fold log2(e) into the score scale
    const float scale2 = 0.08838834764831845f * 1.4426950408889634f;
    const int ntile = qt + 1;
    const int rlo = q0 + wid * 16 + (lane >> 2);
    const int rhi = rlo + 8;

    for (int t = 0; t < ntile; t++) {
        int buf = t & 1;
        if (t + 1 < ntile) {
            flash_load_kv(sb, t + 1, buf ^ 1, Khg, Vhg, tid);
            asm volatile("cp.async.commit_group;\n");
            asm volatile("cp.async.wait_group 1;\n");
        } else {
            asm volatile("cp.async.wait_group 0;\n");
        }
        __syncthreads();

        uint32_t kb = sb + buf * 32768;
        uint32_t vb = kb + 16384;

        float sacc[8][4];
#pragma unroll
        for (int n = 0; n < 8; n++)
#pragma unroll
            for (int r = 0; r < 4; r++) sacc[n][r] = 0.f;

#pragma unroll
        for (int kk = 0; kk < 8; kk++) {
#pragma unroll
            for (int j2 = 0; j2 < 4; j2++) {
                uint32_t bh[4];
                int n_l = (j2 * 2 + (mid >> 1)) * 8 + rin;
                int chnk = kk * 2 + (mid & 1);
                ldsm4(bh, kb + sw256(n_l, chnk));
#pragma unroll
                for (int jj = 0; jj < 2; jj++) {
                    int j = j2 * 2 + jj;
                    mma16816h(sacc[j], qreg[kk], bh[jj * 2], bh[jj * 2 + 1]);
                }
            }
        }

        int k0 = t * FK;
        bool diag = (t == ntile - 1);
#pragma unroll
        for (int n = 0; n < 8; n++) {
            int c0 = k0 + n * 8 + (lane & 3) * 2;
            sacc[n][0] *= scale2;
            sacc[n][1] *= scale2;
            sacc[n][2] *= scale2;
            sacc[n][3] *= scale2;
            if (diag) {
                if (c0 > rlo) sacc[n][0] = -1e30f;
                if (c0 + 1 > rlo) sacc[n][1] = -1e30f;
                if (c0 > rhi) sacc[n][2] = -1e30f;
                if (c0 + 1 > rhi) sacc[n][3] = -1e30f;
            }
        }

        float mx0 = -1e30f, mx1 = -1e30f;
#pragma unroll
        for (int n = 0; n < 8; n++) {
            mx0 = fmaxf(mx0, fmaxf(sacc[n][0], sacc[n][1]));
            mx1 = fmaxf(mx1, fmaxf(sacc[n][2], sacc[n][3]));
        }
        mx0 = fmaxf(mx0, __shfl_xor_sync(0xffffffffu, mx0, 1));
        mx0 = fmaxf(mx0, __shfl_xor_sync(0xffffffffu, mx0, 2));
        mx1 = fmaxf(mx1, __shfl_xor_sync(0xffffffffu, mx1, 1));
        mx1 = fmaxf(mx1, __shfl_xor_sync(0xffffffffu, mx1, 2));
        float newm0 = fmaxf(m_lo, mx0);
        float newm1 = fmaxf(m_hi, mx1);
        float corr0 = exp2f(m_lo - newm0);
        float corr1 = exp2f(m_hi - newm1);
        m_lo = newm0;
        m_hi = newm1;

        float ls0 = 0.f, ls1 = 0.f;
#pragma unroll
        for (int n = 0; n < 8; n++) {
            sacc[n][0] = exp2f(sacc[n][0] - newm0);
            sacc[n][1] = exp2f(sacc[n][1] - newm0);
            sacc[n][2] = exp2f(sacc[n][2] - newm1);
            sacc[n][3] = exp2f(sacc[n][3] - newm1);
            ls0 += sacc[n][0] + sacc[n][1];
            ls1 += sacc[n][2] + sacc[n][3];
        }
        ls0 += __shfl_xor_sync(0xffffffffu, ls0, 1);
        ls0 += __shfl_xor_sync(0xffffffffu, ls0, 2);
        ls1 += __shfl_xor_sync(0xffffffffu, ls1, 1);
        ls1 += __shfl_xor_sync(0xffffffffu, ls1, 2);
        l_lo = l_lo * corr0 + ls0;
        l_hi = l_hi * corr1 + ls1;

#pragma unroll
        for (int v = 0; v < 16; v++) {
            oacc[v][0] *= corr0;
            oacc[v][1] *= corr0;
            oacc[v][2] *= corr1;
            oacc[v][3] *= corr1;
        }

        // ---- O += P V  (P rounded, V 1-term) ----
#pragma unroll
        for (int kk = 0; kk < 4; kk++) {
            uint32_t aph[4];
            aph[0] = pack_f2h2(sacc[2 * kk][0], sacc[2 * kk][1]);
            aph[1] = pack_f2h2(sacc[2 * kk][2], sacc[2 * kk][3]);
            aph[2] = pack_f2h2(sacc[2 * kk + 1][0], sacc[2 * kk + 1][1]);
            aph[3] = pack_f2h2(sacc[2 * kk + 1][2], sacc[2 * kk + 1][3]);
#pragma unroll
            for (int v2 = 0; v2 < 8; v2++) {
                int g = lane >> 3;
                int row = kk * 16 + (g & 1) * 8 + rin;
                int chnk = v2 * 2 + (g >> 1);
                uint32_t vh[4];
                ldsm4t(vh, vb + sw256(row, chnk));
#pragma unroll
                for (int gg = 0; gg < 2; gg++) {
                    int vnt = v2 * 2 + gg;
                    mma16816h(oacc[vnt], aph, vh[gg * 2], vh[gg * 2 + 1]);
                }
            }
        }
        __syncthreads();
    }

    // epilogue: normalize, write rounded fp16 for the out-proj
    float inv0 = 1.f / l_lo;
    float inv1 = 1.f / l_hi;
    int row0 = b * SS + q0 + wid * 16 + (lane >> 2);
    int row1 = row0 + 8;
#pragma unroll
    for (int v = 0; v < 16; v++) {
        int col = h * HD + v * 8 + (lane & 3) * 2;
        *(uint32_t*)(g_Ah + (size_t)row0 * KDIM + col) =
            pack_f2h2(oacc[v][0] * inv0, oacc[v][1] * inv0);
        *(uint32_t*)(g_Ah + (size_t)row1 * KDIM + col) =
            pack_f2h2(oacc[v][2] * inv1, oacc[v][3] * inv1);
    }
}

// ---------------------------------------------------------------------------
extern "C" void kernel_launch(void* const* d_in, const int* in_sizes, int n_in,
                              void* d_out, int out_size) {
    const float* X = (const float*)d_in[0];
    const float* Wq = (const float*)d_in[1];
    const float* Wk = (const float*)d_in[2];
    const float* Wv = (const float*)d_in[3];
    const float* Wo = (const float*)d_in[4];
    float* out = (float*)d_out;

    // 0. Round inputs to fp16 + RoPE table (fused)
    split_inputs_kernel<<<(SPLIT_TOTAL + 255) / 256, 256>>>(X, Wq, Wk, Wv, Wo);

    // 1. QKV projections with fused RoPE + head-major fp16 epilogue
    cudaFuncSetAttribute(qkv_gemm_kernel, cudaFuncAttributeMaxDynamicSharedMemorySize,
                         QKV_SMEM);
    qkv_gemm_kernel<<<dim3(24, 32), 256, QKV_SMEM>>>();

    // 2. fp16 flash attention (Q in regs, exp2 softmax, 2 CTAs/SM)
    cudaFuncSetAttribute(flash_tc_kernel, cudaFuncAttributeMaxDynamicSharedMemorySize,
                         FLASH_SMEM);
    flash_tc_kernel<<<dim3(SS / FQ, NH, BB), FTHREADS, FLASH_SMEM>>>();

    // 3. Output projection
    cudaFuncSetAttribute(out_gemm_kernel, cudaFuncAttributeMaxDynamicSharedMemorySize,
                         GEMM1T_SMEM);
    out_gemm_kernel<<<dim3(16, 32), 256, GEMM1T_SMEM>>>(out);
}

// round 11
// speedup vs baseline: 10.8608x; 1.2778x over previous
#include <cuda_runtime.h>
#include <cuda_fp16.h>
#include <math.h>
#include <stdint.h>

// Problem constants
#define BB 2
#define SS 2048
#define HH 2048
#define NH 16
#define NKV 4
#define HD 128
#define GROUPS (NH / NKV)        // 4
#define M_TOT (BB * SS)          // 4096
#define QDIM (NH * HD)           // 2048
#define KVDIM (NKV * HD)         // 512
#define KDIM 2048                // GEMM reduction dim

__device__ float g_cos[SS * 64];
__device__ float g_sin[SS * 64];

// fp16 buffers
__device__ __align__(16) __half g_Xh[M_TOT * KDIM];
__device__ __align__(16) __half g_Wqh[QDIM * KDIM];
__device__ __align__(16) __half g_Wkh[KVDIM * KDIM];
__device__ __align__(16) __half g_Wvh[KVDIM * KDIM];
__device__ __align__(16) __half g_Woh[HH * KDIM];
__device__ __align__(16) __half g_Ah[M_TOT * KDIM];     // flash out (rounded)

// fp16 head-major buffers for flash: [b, h, s, d]
__device__ __align__(16) __half g_Qb[M_TOT * QDIM];
__device__ __align__(16) __half g_Kb[M_TOT * KVDIM];
__device__ __align__(16) __half g_Vb[M_TOT * KVDIM];

// ---------------------------------------------------------------------------
// Helpers
// ---------------------------------------------------------------------------
__device__ __forceinline__ uint32_t pack_f2h2(float a, float b) {
    __half2 t(__float2half_rn(a), __float2half_rn(b));
    return *(uint32_t*)&t;
}
__device__ __forceinline__ void cp16(uint32_t saddr, const void* gaddr) {
    asm volatile("cp.async.cg.shared.global [%0], [%1], 16;\n" ::"r"(saddr), "l"(gaddr));
}
__device__ __forceinline__ void ldsm4(uint32_t* r, uint32_t addr) {
    asm volatile("ldmatrix.sync.aligned.m8n8.x4.shared.b16 {%0,%1,%2,%3}, [%4];\n"
                 : "=r"(r[0]), "=r"(r[1]), "=r"(r[2]), "=r"(r[3]) : "r"(addr));
}
__device__ __forceinline__ void ldsm4t(uint32_t* r, uint32_t addr) {
    asm volatile("ldmatrix.sync.aligned.m8n8.x4.trans.shared.b16 {%0,%1,%2,%3}, [%4];\n"
                 : "=r"(r[0]), "=r"(r[1]), "=r"(r[2]), "=r"(r[3]) : "r"(addr));
}
__device__ __forceinline__ void mma16816h(float* c, const uint32_t* a, uint32_t b0, uint32_t b1) {
    asm volatile("mma.sync.aligned.m16n8k16.row.col.f32.f16.f16.f32 "
                 "{%0,%1,%2,%3}, {%4,%5,%6,%7}, {%8,%9}, {%0,%1,%2,%3};\n"
                 : "+f"(c[0]), "+f"(c[1]), "+f"(c[2]), "+f"(c[3])
                 : "r"(a[0]), "r"(a[1]), "r"(a[2]), "r"(a[3]), "r"(b0), "r"(b1));
}

// ---------------------------------------------------------------------------
// Input split: X -> fp16, weights -> fp16 (all rounded) + RoPE table (fused)
// ---------------------------------------------------------------------------
#define N4_X  ((M_TOT * KDIM) / 4)
#define N4_WQ ((QDIM * KDIM) / 4)
#define N4_WKV ((KVDIM * KDIM) / 4)
#define N4_WO ((HH * KDIM) / 4)
#define N4_TOTAL (N4_X + N4_WQ + 2 * N4_WKV + N4_WO)
#define NT_ROPE (SS * 64)
#define SPLIT_TOTAL (N4_TOTAL + NT_ROPE)

__global__ void split_inputs_kernel(const float* __restrict__ X,
                                    const float* __restrict__ Wq,
                                    const float* __restrict__ Wk,
                                    const float* __restrict__ Wv,
                                    const float* __restrict__ Wo) {
    int i = blockIdx.x * blockDim.x + threadIdx.x;
    if (i >= SPLIT_TOTAL) return;
    if (i >= N4_TOTAL) {
        int idx = i - N4_TOTAL;           // rope table entry
        int pos = idx >> 6;
        int d = idx & 63;
        double inv = pow(10000.0, -(double)d / 64.0);
        double ang = (double)pos * inv;
        double sd, cd;
        sincos(ang, &sd, &cd);
        g_cos[idx] = (float)cd;
        g_sin[idx] = (float)sd;
        return;
    }
    const float* src;
    __half* dst;
    int off;
    if (i < N4_X) {
        src = X; dst = g_Xh; off = i;
    } else if (i < N4_X + N4_WQ) {
        src = Wq; dst = g_Wqh; off = i - N4_X;
    } else if (i < N4_X + N4_WQ + N4_WKV) {
        src = Wk; dst = g_Wkh; off = i - N4_X - N4_WQ;
    } else if (i < N4_X + N4_WQ + 2 * N4_WKV) {
        src = Wv; dst = g_Wvh; off = i - N4_X - N4_WQ - N4_WKV;
    } else {
        src = Wo; dst = g_Woh; off = i - N4_X - N4_WQ - 2 * N4_WKV;
    }
    float4 v = *(const float4*)(src + (size_t)off * 4);
    *(uint32_t*)(dst + (size_t)off * 4 + 0) = pack_f2h2(v.x, v.y);
    *(uint32_t*)(dst + (size_t)off * 4 + 2) = pack_f2h2(v.z, v.w);
}

// ---------------------------------------------------------------------------
// GEMM: K-chunk 64, 3-stage pipeline. Stage: A 16K | B 16K = 32K.
// 128B rows (64 fp16), XOR swizzle over 8 chunks of 16B.
// ---------------------------------------------------------------------------
__device__ __forceinline__ uint32_t sw128b(int row, int chunk) {
    return (uint32_t)(row * 128 + ((chunk ^ (row & 7)) << 4));
}

#define STAGE64 32768
#define GEMM_SMEM (3 * STAGE64)          // 96 KB
#define KT64 (KDIM / 64)                 // 32

__device__ __forceinline__ void load_stage64(uint32_t S, int buf,
                                             const __half* __restrict__ A,
                                             const __half* __restrict__ B,
                                             int m0, int n0, int k0, int tid) {
    uint32_t st = S + buf * STAGE64;
#pragma unroll
    for (int l = 0; l < 4; l++) {
        int idx = tid + l * 256;          // 0..1023 = 128 rows x 8 chunks
        int row = idx >> 3;
        int c = idx & 7;
        uint32_t spos = sw128b(row, c);
        cp16(st + spos, A + (size_t)(m0 + row) * KDIM + k0 + c * 8);
        cp16(st + 16384 + spos, B + (size_t)(n0 + row) * KDIM + k0 + c * 8);
    }
    asm volatile("cp.async.commit_group;\n");
}

// Core 128x128x2048 mainloop (K-chunk 64), leaves result in acc[4][4][4]
#define GEMM_MAINLOOP(A, B, m0, n0)                                                   \
    float acc[4][4][4];                                                               \
    _Pragma("unroll") for (int i = 0; i < 4; i++)                                     \
        _Pragma("unroll") for (int j = 0; j < 4; j++)                                 \
            _Pragma("unroll") for (int r = 0; r < 4; r++) acc[i][j][r] = 0.f;         \
    load_stage64(S, 0, A, B, m0, n0, 0, tid);                                         \
    load_stage64(S, 1, A, B, m0, n0, 64, tid);                                        \
    for (int kt = 0; kt < KT64; kt++) {                                               \
        if (kt < KT64 - 1)                                                            \
            asm volatile("cp.async.wait_group 1;\n");                                 \
        else                                                                          \
            asm volatile("cp.async.wait_group 0;\n");                                 \
        __syncthreads();                                                              \
        if (kt + 2 < KT64)                                                            \
            load_stage64(S, (kt + 2) % 3, A, B, m0, n0, (kt + 2) * 64, tid);          \
        uint32_t aB = S + (kt % 3) * STAGE64;                                         \
        uint32_t bB = aB + 16384;                                                     \
        _Pragma("unroll") for (int kk = 0; kk < 4; kk++) {                            \
            uint32_t ah[4][4];                                                        \
            _Pragma("unroll") for (int i = 0; i < 4; i++) {                           \
                int m_l = wm * 64 + i * 16 + (mid & 1) * 8 + rin;                     \
                int chnk = kk * 2 + (mid >> 1);                                       \
                ldsm4(ah[i], aB + sw128b(m_l, chnk));                                 \
            }                                                                         \
            _Pragma("unroll") for (int j2 = 0; j2 < 2; j2++) {                        \
                uint32_t bh[4];                                                       \
                int n_l = wn * 32 + (j2 * 2 + (mid >> 1)) * 8 + rin;                  \
                int chnk = kk * 2 + (mid & 1);                                        \
                ldsm4(bh, bB + sw128b(n_l, chnk));                                    \
                _Pragma("unroll") for (int jj = 0; jj < 2; jj++) {                    \
                    int j = j2 * 2 + jj;                                              \
                    _Pragma("unroll") for (int i = 0; i < 4; i++)                     \
                        mma16816h(acc[i][j], ah[i], bh[jj * 2], bh[jj * 2 + 1]);      \
                }                                                                     \
            }                                                                         \
        }                                                                             \
    }

// ---------------------------------------------------------------------------
// QKV GEMM with fused RoPE + fp16 head-major epilogue.
// grid (24, 32): bx 0-15 Q heads, 16-19 K heads, 20-23 V heads.
// ---------------------------------------------------------------------------
#define QKV_SMEM GEMM_SMEM    // 96K (epilogue tile 66K fits inside)

__global__ __launch_bounds__(256, 2) void qkv_gemm_kernel() {
    extern __shared__ char smem_raw[];
    uint32_t S = (uint32_t)__cvta_generic_to_shared(smem_raw);
    int tid = threadIdx.x;
    int lane = tid & 31, wid = tid >> 5;
    int wm = wid & 1, wn = wid >> 1;
    int mid = lane >> 3, rin = lane & 7;

    int bx = blockIdx.x;
    int m0 = blockIdx.y * 128;

    const __half* A = g_Xh;
    const __half* B;
    __half* dstH;
    int head, nhd;
    bool do_rope;
    if (bx < 16) {
        B = g_Wqh; dstH = g_Qb; head = bx; nhd = NH; do_rope = true;
    } else if (bx < 20) {
        B = g_Wkh; dstH = g_Kb; head = bx - 16; nhd = NKV; do_rope = true;
    } else {
        B = g_Wvh; dstH = g_Vb; head = bx - 20; nhd = NKV; do_rope = false;
    }
    int n0 = head * HD;

    GEMM_MAINLOOP(A, B, m0, n0)

    // ---- fused epilogue: stage fp32 tile in smem, rope pairs, fp16 out ----
    __syncthreads();
    float* tile = (float*)smem_raw;
#pragma unroll
    for (int i = 0; i < 4; i++) {
#pragma unroll
        for (int j = 0; j < 4; j++) {
            int r0 = wm * 64 + i * 16 + (lane >> 2);
            int cc = wn * 32 + j * 8 + (lane & 3) * 2;
            *(float2*)&tile[r0 * 132 + cc] = make_float2(acc[i][j][0], acc[i][j][1]);
            *(float2*)&tile[(r0 + 8) * 132 + cc] = make_float2(acc[i][j][2], acc[i][j][3]);
        }
    }
    __syncthreads();

    for (int it = tid; it < 128 * 64; it += 256) {
        int row = it >> 6, d = it & 63;
        int m = m0 + row;
        int s = m & (SS - 1), b = m >> 11;
        float x1 = tile[row * 132 + d];
        float x2 = tile[row * 132 + d + 64];
        float y1 = x1, y2 = x2;
        if (do_rope) {
            float c = g_cos[s * 64 + d], sn = g_sin[s * 64 + d];
            y1 = x1 * c - x2 * sn;
            y2 = x2 * c + x1 * sn;
        }
        size_t dst = ((size_t)(b * nhd + head) * SS + s) * HD + d;
        dstH[dst] = __float2half_rn(y1);
        dstH[dst + 64] = __float2half_rn(y2);
    }
}

// ---------------------------------------------------------------------------
// Output projection (1-term, fp32 out)
// ---------------------------------------------------------------------------
__global__ __launch_bounds__(256, 2) void out_gemm_kernel(float* __restrict__ out) {
    extern __shared__ char smem_raw[];
    uint32_t S = (uint32_t)__cvta_generic_to_shared(smem_raw);
    int tid = threadIdx.x;
    int lane = tid & 31, wid = tid >> 5;
    int wm = wid & 1, wn = wid >> 1;
    int mid = lane >> 3, rin = lane & 7;
    int m0 = blockIdx.y * 128, n0 = blockIdx.x * 128;

    GEMM_MAINLOOP(g_Ah, g_Woh, m0, n0)

#pragma unroll
    for (int i = 0; i < 4; i++) {
#pragma unroll
        for (int j = 0; j < 4; j++) {
            int r0 = m0 + wm * 64 + i * 16 + (lane >> 2);
            int cc = n0 + wn * 32 + j * 8 + (lane & 3) * 2;
            *(float2*)&out[(size_t)r0 * HH + cc] = make_float2(acc[i][j][0], acc[i][j][1]);
            *(float2*)&out[(size_t)(r0 + 8) * HH + cc] = make_float2(acc[i][j][2], acc[i][j][3]);
        }
    }
}

// ---------------------------------------------------------------------------
// fp16 flash attention (causal), 1-term operands.
// BQ=64, 4 warps, 2 CTAs/SM. Q held in registers; exp2-domain softmax.
// smem: 2 stages x (K 16K | V 16K) = 64 KB
// ---------------------------------------------------------------------------
#define FQ 64
#define FK 64
#define FTHREADS 128
#define FLASH_SMEM (2 * 32768)

__device__ __forceinline__ uint32_t sw256(int row, int chunk) {
    return (uint32_t)(row * 256 + ((chunk ^ (row & 7)) << 4));
}

__device__ __forceinline__ void flash_load_kv(uint32_t sb, int t, int st,
                                              const __half* Kh, const __half* Vh, int tid) {
    uint32_t base = sb + st * 32768;
    size_t g0 = (size_t)t * FK * HD;
#pragma unroll
    for (int l = 0; l < 8; l++) {
        int idx = tid + l * FTHREADS;    // 0..1023 = 64 rows x 16 chunks
        int row = idx >> 4;
        int c = idx & 15;
        uint32_t off = sw256(row, c);
        size_t go = g0 + (size_t)row * HD + c * 8;
        cp16(base + off, Kh + go);
        cp16(base + 16384 + off, Vh + go);
    }
}

__global__ __launch_bounds__(FTHREADS, 2) void flash_tc_kernel() {
    extern __shared__ char smem_raw[];
    uint32_t sb = (uint32_t)__cvta_generic_to_shared(smem_raw);

    int qt = (int)(gridDim.x - 1 - blockIdx.x);   // big tiles first
    int h = blockIdx.y, b = blockIdx.z;
    int q0 = qt * FQ;
    int kh = h / GROUPS;

    int tid = threadIdx.x, lane = tid & 31, wid = tid >> 5;  // wid 0..3
    int mid = lane >> 3, rin = lane & 7;

    const __half* Qg = g_Qb + ((size_t)(b * NH + h) * SS + q0) * HD;
    const __half* Khg = g_Kb + (size_t)(b * NKV + kh) * SS * HD;
    const __half* Vhg = g_Vb + (size_t)(b * NKV + kh) * SS * HD;

    // ---- Stage Q transiently in buf1, pull fragments to registers ----
    uint32_t Qstage = sb + 32768;
#pragma unroll
    for (int l = 0; l < 8; l++) {
        int idx = tid + l * FTHREADS;
        int row = idx >> 4;
        int c = idx & 15;
        cp16(Qstage + sw256(row, c), Qg + (size_t)row * HD + c * 8);
    }
    asm volatile("cp.async.commit_group;\n");
    flash_load_kv(sb, 0, 0, Khg, Vhg, tid);       // KV0 -> buf0
    asm volatile("cp.async.commit_group;\n");

    asm volatile("cp.async.wait_group 1;\n");     // Q done (KV0 may be in flight)
    __syncthreads();
    uint32_t qreg[8][4];
#pragma unroll
    for (int kk = 0; kk < 8; kk++) {
        int m_l = wid * 16 + (mid & 1) * 8 + rin;
        int chnk = kk * 2 + (mid >> 1);
        ldsm4(qreg[kk], Qstage + sw256(m_l, chnk));
    }
    __syncthreads();   // everyone done reading Q before buf1 is overwritten

    float m_lo = -1e30f, m_hi = -1e30f, l_lo = 0.f, l_hi = 0.f;
    float oacc[16][4];
#pragma unroll
    for (int v = 0; v < 16; v++)
#pragma unroll
        for (int r = 0; r < 4; r++) oacc[v][r] = 0.f;

    // exp2 domain: fold log2(e) into the score scale
    const float scale2 = 0.08838834764831845f * 1.4426950408889634f;
    const int ntile = qt + 1;
    const int rlo = q0 + wid * 16 + (lane >> 2);
    const int rhi = rlo + 8;

    for (int t = 0; t < ntile; t++) {
        int buf = t & 1;
        if (t + 1 < ntile) {
            flash_load_kv(sb, t + 1, buf ^ 1, Khg, Vhg, tid);
            asm volatile("cp.async.commit_group;\n");
            asm volatile("cp.async.wait_group 1;\n");
        } else {
            asm volatile("cp.async.wait_group 0;\n");
        }
        __syncthreads();

        uint32_t kb = sb + buf * 32768;
        uint32_t vb = kb + 16384;

        float sacc[8][4];
#pragma unroll
        for (int n = 0; n < 8; n++)
#pragma unroll
            for (int r = 0; r < 4; r++) sacc[n][r] = 0.f;

#pragma unroll
        for (int kk = 0; kk < 8; kk++) {
#pragma unroll
            for (int j2 = 0; j2 < 4; j2++) {
                uint32_t bh[4];
                int n_l = (j2 * 2 + (mid >> 1)) * 8 + rin;
                int chnk = kk * 2 + (mid & 1);
                ldsm4(bh, kb + sw256(n_l, chnk));
#pragma unroll
                for (int jj = 0; jj < 2; jj++) {
                    int j = j2 * 2 + jj;
                    mma16816h(sacc[j], qreg[kk], bh[jj * 2], bh[jj * 2 + 1]);
                }
            }
        }

        int k0 = t * FK;
        bool diag = (t == ntile - 1);
#pragma unroll
        for (int n = 0; n < 8; n++) {
            int c0 = k0 + n * 8 + (lane & 3) * 2;
            sacc[n][0] *= scale2;
            sacc[n][1] *= scale2;
            sacc[n][2] *= scale2;
            sacc[n][3] *= scale2;
            if (diag) {
                if (c0 > rlo) sacc[n][0] = -1e30f;
                if (c0 + 1 > rlo) sacc[n][1] = -1e30f;
                if (c0 > rhi) sacc[n][2] = -1e30f;
                if (c0 + 1 > rhi) sacc[n][3] = -1e30f;
            }
        }

        float mx0 = -1e30f, mx1 = -1e30f;
#pragma unroll
        for (int n = 0; n < 8; n++) {
            mx0 = fmaxf(mx0, fmaxf(sacc[n][0], sacc[n][1]));
            mx1 = fmaxf(mx1, fmaxf(sacc[n][2], sacc[n][3]));
        }
        mx0 = fmaxf(mx0, __shfl_xor_sync(0xffffffffu, mx0, 1));
        mx0 = fmaxf(mx0, __shfl_xor_sync(0xffffffffu, mx0, 2));
        mx1 = fmaxf(mx1, __shfl_xor_sync(0xffffffffu, mx1, 1));
        mx1 = fmaxf(mx1, __shfl_xor_sync(0xffffffffu, mx1, 2));
        float newm0 = fmaxf(m_lo, mx0);
        float newm1 = fmaxf(m_hi, mx1);
        float corr0 = exp2f(m_lo - newm0);
        float corr1 = exp2f(m_hi - newm1);
        m_lo = newm0;
        m_hi = newm1;

        float ls0 = 0.f, ls1 = 0.f;
#pragma unroll
        for (int n = 0; n < 8; n++) {
            sacc[n][0] = exp2f(sacc[n][0] - newm0);
            sacc[n][1] = exp2f(sacc[n][1] - newm0);
            sacc[n][2] = exp2f(sacc[n][2] - newm1);
            sacc[n][3] = exp2f(sacc[n][3] - newm1);
            ls0 += sacc[n][0] + sacc[n][1];
            ls1 += sacc[n][2] + sacc[n][3];
        }
        ls0 += __shfl_xor_sync(0xffffffffu, ls0, 1);
        ls0 += __shfl_xor_sync(0xffffffffu, ls0, 2);
        ls1 += __shfl_xor_sync(0xffffffffu, ls1, 1);
        ls1 += __shfl_xor_sync(0xffffffffu, ls1, 2);
        l_lo = l_lo * corr0 + ls0;
        l_hi = l_hi * corr1 + ls1;

#pragma unroll
        for (int v = 0; v < 16; v++) {
            oacc[v][0] *= corr0;
            oacc[v][1] *= corr0;
            oacc[v][2] *= corr1;
            oacc[v][3] *= corr1;
        }

        // ---- O += P V  (P rounded, V 1-term) ----
#pragma unroll
        for (int kk = 0; kk < 4; kk++) {
            uint32_t aph[4];
            aph[0] = pack_f2h2(sacc[2 * kk][0], sacc[2 * kk][1]);
            aph[1] = pack_f2h2(sacc[2 * kk][2], sacc[2 * kk][3]);
            aph[2] = pack_f2h2(sacc[2 * kk + 1][0], sacc[2 * kk + 1][1]);
            aph[3] = pack_f2h2(sacc[2 * kk + 1][2], sacc[2 * kk + 1][3]);
#pragma unroll
            for (int v2 = 0; v2 < 8; v2++) {
                int g = lane >> 3;
                int row = kk * 16 + (g & 1) * 8 + rin;
                int chnk = v2 * 2 + (g >> 1);
                uint32_t vh[4];
                ldsm4t(vh, vb + sw256(row, chnk));
#pragma unroll
                for (int gg = 0; gg < 2; gg++) {
                    int vnt = v2 * 2 + gg;
                    mma16816h(oacc[vnt], aph, vh[gg * 2], vh[gg * 2 + 1]);
                }
            }
        }
        __syncthreads();
    }

    // epilogue: normalize, write rounded fp16 for the out-proj
    float inv0 = 1.f / l_lo;
    float inv1 = 1.f / l_hi;
    int row0 = b * SS + q0 + wid * 16 + (lane >> 2);
    int row1 = row0 + 8;
#pragma unroll
    for (int v = 0; v < 16; v++) {
        int col = h * HD + v * 8 + (lane & 3) * 2;
        *(uint32_t*)(g_Ah + (size_t)row0 * KDIM + col) =
            pack_f2h2(oacc[v][0] * inv0, oacc[v][1] * inv0);
        *(uint32_t*)(g_Ah + (size_t)row1 * KDIM + col) =
            pack_f2h2(oacc[v][2] * inv1, oacc[v][3] * inv1);
    }
}

// ---------------------------------------------------------------------------
extern "C" void kernel_launch(void* const* d_in, const int* in_sizes, int n_in,
                              void* d_out, int out_size) {
    const float* X = (const float*)d_in[0];
    const float* Wq = (const float*)d_in[1];
    const float* Wk = (const float*)d_in[2];
    const float* Wv = (const float*)d_in[3];
    const float* Wo = (const float*)d_in[4];
    float* out = (float*)d_out;

    // 0. Round inputs to fp16 + RoPE table (fused)
    split_inputs_kernel<<<(SPLIT_TOTAL + 255) / 256, 256>>>(X, Wq, Wk, Wv, Wo);

    // 1. QKV projections with fused RoPE + head-major fp16 epilogue
    cudaFuncSetAttribute(qkv_gemm_kernel, cudaFuncAttributeMaxDynamicSharedMemorySize,
                         QKV_SMEM);
    qkv_gemm_kernel<<<dim3(24, 32), 256, QKV_SMEM>>>();

    // 2. fp16 flash attention (Q in regs, exp2 softmax, 2 CTAs/SM)
    cudaFuncSetAttribute(flash_tc_kernel, cudaFuncAttributeMaxDynamicSharedMemorySize,
                         FLASH_SMEM);
    flash_tc_kernel<<<dim3(SS / FQ, NH, BB), FTHREADS, FLASH_SMEM>>>();

    // 3. Output projection
    cudaFuncSetAttribute(out_gemm_kernel, cudaFuncAttributeMaxDynamicSharedMemorySize,
                         GEMM_SMEM);
    out_gemm_kernel<<<dim3(16, 32), 256, GEMM_SMEM>>>(out);
}

// round 14
// speedup vs baseline: 11.0165x; 1.0143x over previous
#include <cuda_runtime.h>
#include <cuda_fp16.h>
#include <math.h>
#include <stdint.h>

// Problem constants
#define BB 2
#define SS 2048
#define HH 2048
#define NH 16
#define NKV 4
#define HD 128
#define GROUPS (NH / NKV)        // 4
#define M_TOT (BB * SS)          // 4096
#define QDIM (NH * HD)           // 2048
#define KVDIM (NKV * HD)         // 512
#define KDIM 2048                // GEMM reduction dim

__device__ float g_cos[SS * 64];
__device__ float g_sin[SS * 64];

// fp16 buffers
__device__ __align__(16) __half g_Xh[M_TOT * KDIM];
__device__ __align__(16) __half g_Wqh[QDIM * KDIM];
__device__ __align__(16) __half g_Wkh[KVDIM * KDIM];
__device__ __align__(16) __half g_Wvh[KVDIM * KDIM];
__device__ __align__(16) __half g_Woh[HH * KDIM];
__device__ __align__(16) __half g_Ah[M_TOT * KDIM];     // flash out (rounded)

// fp16 head-major buffers for flash: [b, h, s, d]
__device__ __align__(16) __half g_Qb[M_TOT * QDIM];
__device__ __align__(16) __half g_Kb[M_TOT * KVDIM];
__device__ __align__(16) __half g_Vb[M_TOT * KVDIM];

// ---------------------------------------------------------------------------
// Helpers
// ---------------------------------------------------------------------------
__device__ __forceinline__ uint32_t pack_f2h2(float a, float b) {
    __half2 t(__float2half_rn(a), __float2half_rn(b));
    return *(uint32_t*)&t;
}
__device__ __forceinline__ void cp16(uint32_t saddr, const void* gaddr) {
    asm volatile("cp.async.cg.shared.global [%0], [%1], 16;\n" ::"r"(saddr), "l"(gaddr));
}
__device__ __forceinline__ void ldsm4(uint32_t* r, uint32_t addr) {
    asm volatile("ldmatrix.sync.aligned.m8n8.x4.shared.b16 {%0,%1,%2,%3}, [%4];\n"
                 : "=r"(r[0]), "=r"(r[1]), "=r"(r[2]), "=r"(r[3]) : "r"(addr));
}
__device__ __forceinline__ void ldsm4t(uint32_t* r, uint32_t addr) {
    asm volatile("ldmatrix.sync.aligned.m8n8.x4.trans.shared.b16 {%0,%1,%2,%3}, [%4];\n"
                 : "=r"(r[0]), "=r"(r[1]), "=r"(r[2]), "=r"(r[3]) : "r"(addr));
}
__device__ __forceinline__ void mma16816h(float* c, const uint32_t* a, uint32_t b0, uint32_t b1) {
    asm volatile("mma.sync.aligned.m16n8k16.row.col.f32.f16.f16.f32 "
                 "{%0,%1,%2,%3}, {%4,%5,%6,%7}, {%8,%9}, {%0,%1,%2,%3};\n"
                 : "+f"(c[0]), "+f"(c[1]), "+f"(c[2]), "+f"(c[3])
                 : "r"(a[0]), "r"(a[1]), "r"(a[2]), "r"(a[3]), "r"(b0), "r"(b1));
}

// ---------------------------------------------------------------------------
// Input split: X -> fp16, weights -> fp16 (rounded), 8 floats/thread + RoPE
// ---------------------------------------------------------------------------
#define N8_X  ((M_TOT * KDIM) / 8)
#define N8_WQ ((QDIM * KDIM) / 8)
#define N8_WKV ((KVDIM * KDIM) / 8)
#define N8_WO ((HH * KDIM) / 8)
#define N8_TOTAL (N8_X + N8_WQ + 2 * N8_WKV + N8_WO)
#define NT_ROPE (SS * 64)
#define SPLIT_TOTAL (N8_TOTAL + NT_ROPE)

__global__ void split_inputs_kernel(const float* __restrict__ X,
                                    const float* __restrict__ Wq,
                                    const float* __restrict__ Wk,
                                    const float* __restrict__ Wv,
                                    const float* __restrict__ Wo) {
    int i = blockIdx.x * blockDim.x + threadIdx.x;
    if (i >= SPLIT_TOTAL) return;
    if (i >= N8_TOTAL) {
        int idx = i - N8_TOTAL;           // rope table entry
        int pos = idx >> 6;
        int d = idx & 63;
        double inv = pow(10000.0, -(double)d / 64.0);
        double ang = (double)pos * inv;
        double sd, cd;
        sincos(ang, &sd, &cd);
        g_cos[idx] = (float)cd;
        g_sin[idx] = (float)sd;
        return;
    }
    const float* src;
    __half* dst;
    int off;
    if (i < N8_X) {
        src = X; dst = g_Xh; off = i;
    } else if (i < N8_X + N8_WQ) {
        src = Wq; dst = g_Wqh; off = i - N8_X;
    } else if (i < N8_X + N8_WQ + N8_WKV) {
        src = Wk; dst = g_Wkh; off = i - N8_X - N8_WQ;
    } else if (i < N8_X + N8_WQ + 2 * N8_WKV) {
        src = Wv; dst = g_Wvh; off = i - N8_X - N8_WQ - N8_WKV;
    } else {
        src = Wo; dst = g_Woh; off = i - N8_X - N8_WQ - 2 * N8_WKV;
    }
    float4 v0 = *(const float4*)(src + (size_t)off * 8);
    float4 v1 = *(const float4*)(src + (size_t)off * 8 + 4);
    uint4 o;
    o.x = pack_f2h2(v0.x, v0.y);
    o.y = pack_f2h2(v0.z, v0.w);
    o.z = pack_f2h2(v1.x, v1.y);
    o.w = pack_f2h2(v1.z, v1.w);
    *(uint4*)(dst + (size_t)off * 8) = o;
}

// ---------------------------------------------------------------------------
// GEMM: K-chunk 64, 3-stage pipeline. Stage: A 16K | B 16K = 32K.
// ---------------------------------------------------------------------------
__device__ __forceinline__ uint32_t sw128b(int row, int chunk) {
    return (uint32_t)(row * 128 + ((chunk ^ (row & 7)) << 4));
}

#define STAGE64 32768
#define GEMM_SMEM (3 * STAGE64)          // 96 KB
#define KT64 (KDIM / 64)                 // 32

__device__ __forceinline__ void load_stage64(uint32_t S, int buf,
                                             const __half* __restrict__ A,
                                             const __half* __restrict__ B,
                                             int m0, int n0, int k0, int tid) {
    uint32_t st = S + buf * STAGE64;
#pragma unroll
    for (int l = 0; l < 4; l++) {
        int idx = tid + l * 256;          // 0..1023 = 128 rows x 8 chunks
        int row = idx >> 3;
        int c = idx & 7;
        uint32_t spos = sw128b(row, c);
        cp16(st + spos, A + (size_t)(m0 + row) * KDIM + k0 + c * 8);
        cp16(st + 16384 + spos, B + (size_t)(n0 + row) * KDIM + k0 + c * 8);
    }
    asm volatile("cp.async.commit_group;\n");
}

// Core 128x128x2048 mainloop (K-chunk 64), leaves result in acc[4][4][4]
#define GEMM_MAINLOOP(A, B, m0, n0)                                                   \
    float acc[4][4][4];                                                               \
    _Pragma("unroll") for (int i = 0; i < 4; i++)                                     \
        _Pragma("unroll") for (int j = 0; j < 4; j++)                                 \
            _Pragma("unroll") for (int r = 0; r < 4; r++) acc[i][j][r] = 0.f;         \
    load_stage64(S, 0, A, B, m0, n0, 0, tid);                                         \
    load_stage64(S, 1, A, B, m0, n0, 64, tid);                                        \
    for (int kt = 0; kt < KT64; kt++) {                                               \
        if (kt < KT64 - 1)                                                            \
            asm volatile("cp.async.wait_group 1;\n");                                 \
        else                                                                          \
            asm volatile("cp.async.wait_group 0;\n");                                 \
        __syncthreads();                                                              \
        if (kt + 2 < KT64)                                                            \
            load_stage64(S, (kt + 2) % 3, A, B, m0, n0, (kt + 2) * 64, tid);          \
        uint32_t aB = S + (kt % 3) * STAGE64;                                         \
        uint32_t bB = aB + 16384;                                                     \
        _Pragma("unroll") for (int kk = 0; kk < 4; kk++) {                            \
            uint32_t ah[4][4];                                                        \
            _Pragma("unroll") for (int i = 0; i < 4; i++) {                           \
                int m_l = wm * 64 + i * 16 + (mid & 1) * 8 + rin;                     \
                int chnk = kk * 2 + (mid >> 1);                                       \
                ldsm4(ah[i], aB + sw128b(m_l, chnk));                                 \
            }                                                                         \
            _Pragma("unroll") for (int j2 = 0; j2 < 2; j2++) {                        \
                uint32_t bh[4];                                                       \
                int n_l = wn * 32 + (j2 * 2 + (mid >> 1)) * 8 + rin;                  \
                int chnk = kk * 2 + (mid & 1);                                        \
                ldsm4(bh, bB + sw128b(n_l, chnk));                                    \
                _Pragma("unroll") for (int jj = 0; jj < 2; jj++) {                    \
                    int j = j2 * 2 + jj;                                              \
                    _Pragma("unroll") for (int i = 0; i < 4; i++)                     \
                        mma16816h(acc[i][j], ah[i], bh[jj * 2], bh[jj * 2 + 1]);      \
                }                                                                     \
            }                                                                         \
        }                                                                             \
    }

// ---------------------------------------------------------------------------
// QKV GEMM with fused RoPE + fp16 head-major epilogue.
// ---------------------------------------------------------------------------
#define QKV_SMEM GEMM_SMEM    // 96K (epilogue tile 66K fits inside)

__global__ __launch_bounds__(256, 2) void qkv_gemm_kernel() {
    extern __shared__ char smem_raw[];
    uint32_t S = (uint32_t)__cvta_generic_to_shared(smem_raw);
    int tid = threadIdx.x;
    int lane = tid & 31, wid = tid >> 5;
    int wm = wid & 1, wn = wid >> 1;
    int mid = lane >> 3, rin = lane & 7;

    int bx = blockIdx.x;
    int m0 = blockIdx.y * 128;

    const __half* A = g_Xh;
    const __half* B;
    __half* dstH;
    int head, nhd;
    bool do_rope;
    if (bx < 16) {
        B = g_Wqh; dstH = g_Qb; head = bx; nhd = NH; do_rope = true;
    } else if (bx < 20) {
        B = g_Wkh; dstH = g_Kb; head = bx - 16; nhd = NKV; do_rope = true;
    } else {
        B = g_Wvh; dstH = g_Vb; head = bx - 20; nhd = NKV; do_rope = false;
    }
    int n0 = head * HD;

    GEMM_MAINLOOP(A, B, m0, n0)

    // ---- fused epilogue: stage fp32 tile in smem, rope pairs, fp16 out ----
    __syncthreads();
    float* tile = (float*)smem_raw;
#pragma unroll
    for (int i = 0; i < 4; i++) {
#pragma unroll
        for (int j = 0; j < 4; j++) {
            int r0 = wm * 64 + i * 16 + (lane >> 2);
            int cc = wn * 32 + j * 8 + (lane & 3) * 2;
            *(float2*)&tile[r0 * 132 + cc] = make_float2(acc[i][j][0], acc[i][j][1]);
            *(float2*)&tile[(r0 + 8) * 132 + cc] = make_float2(acc[i][j][2], acc[i][j][3]);
        }
    }
    __syncthreads();

    for (int it = tid; it < 128 * 64; it += 256) {
        int row = it >> 6, d = it & 63;
        int m = m0 + row;
        int s = m & (SS - 1), b = m >> 11;
        float x1 = tile[row * 132 + d];
        float x2 = tile[row * 132 + d + 64];
        float y1 = x1, y2 = x2;
        if (do_rope) {
            float c = g_cos[s * 64 + d], sn = g_sin[s * 64 + d];
            y1 = x1 * c - x2 * sn;
            y2 = x2 * c + x1 * sn;
        }
        size_t dst = ((size_t)(b * nhd + head) * SS + s) * HD + d;
        dstH[dst] = __float2half_rn(y1);
        dstH[dst + 64] = __float2half_rn(y2);
    }
}

// ---------------------------------------------------------------------------
// Output projection (1-term, fp32 out)
// ---------------------------------------------------------------------------
__global__ __launch_bounds__(256, 2) void out_gemm_kernel(float* __restrict__ out) {
    extern __shared__ char smem_raw[];
    uint32_t S = (uint32_t)__cvta_generic_to_shared(smem_raw);
    int tid = threadIdx.x;
    int lane = tid & 31, wid = tid >> 5;
    int wm = wid & 1, wn = wid >> 1;
    int mid = lane >> 3, rin = lane & 7;
    int m0 = blockIdx.y * 128, n0 = blockIdx.x * 128;

    GEMM_MAINLOOP(g_Ah, g_Woh, m0, n0)

#pragma unroll
    for (int i = 0; i < 4; i++) {
#pragma unroll
        for (int j = 0; j < 4; j++) {
            int r0 = m0 + wm * 64 + i * 16 + (lane >> 2);
            int cc = n0 + wn * 32 + j * 8 + (lane & 3) * 2;
            *(float2*)&out[(size_t)r0 * HH + cc] = make_float2(acc[i][j][0], acc[i][j][1]);
            *(float2*)&out[(size_t)(r0 + 8) * HH + cc] = make_float2(acc[i][j][2], acc[i][j][3]);
        }
    }
}

// ---------------------------------------------------------------------------
// fp16 flash attention (causal), 1-term operands.
// BQ=64, 4 warps, 2 CTAs/SM. Q in registers; exp2 softmax.
// 3-stage KV pipeline, ONE sync per tile. smem: 3 x (K 16K | V 16K) = 96 KB
// ---------------------------------------------------------------------------
#define FQ 64
#define FK 64
#define FTHREADS 128
#define FLASH_SMEM (3 * 32768)

__device__ __forceinline__ uint32_t sw256(int row, int chunk) {
    return (uint32_t)(row * 256 + ((chunk ^ (row & 7)) << 4));
}

__device__ __forceinline__ void flash_load_kv(uint32_t sb, int t, int st,
                                              const __half* Kh, const __half* Vh, int tid) {
    uint32_t base = sb + st * 32768;
    size_t g0 = (size_t)t * FK * HD;
#pragma unroll
    for (int l = 0; l < 8; l++) {
        int idx = tid + l * FTHREADS;    // 0..1023 = 64 rows x 16 chunks
        int row = idx >> 4;
        int c = idx & 15;
        uint32_t off = sw256(row, c);
        size_t go = g0 + (size_t)row * HD + c * 8;
        cp16(base + off, Kh + go);
        cp16(base + 16384 + off, Vh + go);
    }
    asm volatile("cp.async.commit_group;\n");
}

__global__ __launch_bounds__(FTHREADS, 2) void flash_tc_kernel() {
    extern __shared__ char smem_raw[];
    uint32_t sb = (uint32_t)__cvta_generic_to_shared(smem_raw);

    int qt = (int)(gridDim.x - 1 - blockIdx.x);   // big tiles first
    int h = blockIdx.y, b = blockIdx.z;
    int q0 = qt * FQ;
    int kh = h / GROUPS;

    int tid = threadIdx.x, lane = tid & 31, wid = tid >> 5;  // wid 0..3
    int mid = lane >> 3, rin = lane & 7;

    const __half* Qg = g_Qb + ((size_t)(b * NH + h) * SS + q0) * HD;
    const __half* Khg = g_Kb + (size_t)(b * NKV + kh) * SS * HD;
    const __half* Vhg = g_Vb + (size_t)(b * NKV + kh) * SS * HD;

    // ---- Stage Q transiently in buf2; preload KV0, KV1 ----
    uint32_t Qstage = sb + 2 * 32768;
#pragma unroll
    for (int l = 0; l < 8; l++) {
        int idx = tid + l * FTHREADS;
        int row = idx >> 4;
        int c = idx & 15;
        cp16(Qstage + sw256(row, c), Qg + (size_t)row * HD + c * 8);
    }
    asm volatile("cp.async.commit_group;\n");
    const int ntile = qt + 1;
    flash_load_kv(sb, 0, 0, Khg, Vhg, tid);
    if (ntile > 1) {
        flash_load_kv(sb, 1, 1, Khg, Vhg, tid);
        // pending: {Q, KV0, KV1}; allow 2 newest (KV0,KV1) pending -> Q complete
        asm volatile("cp.async.wait_group 2;\n");
    } else {
        // pending: {Q, KV0}; allow 1 newest (KV0) pending -> Q complete
        asm volatile("cp.async.wait_group 1;\n");
    }
    __syncthreads();                              // ALL threads' Q copies visible
    uint32_t qreg[8][4];
#pragma unroll
    for (int kk = 0; kk < 8; kk++) {
        int m_l = wid * 16 + (mid & 1) * 8 + rin;
        int chnk = kk * 2 + (mid >> 1);
        ldsm4(qreg[kk], Qstage + sw256(m_l, chnk));
    }
    // No second sync needed: the loop's first barrier (iteration 0) happens
    // after every warp's Q ldsm (program order), and the earliest write into
    // buf2 is the tile-2 prefetch issued after that barrier.

    float m_lo = -1e30f, m_hi = -1e30f, l_lo = 0.f, l_hi = 0.f;
    float oacc[16][4];
#pragma unroll
    for (int v = 0; v < 16; v++)
#pragma unroll
        for (int r = 0; r < 4; r++) oacc[v][r] = 0.f;

    const float scale2 = 0.08838834764831845f * 1.4426950408889634f;
    const int rlo = q0 + wid * 16 + (lane >> 2);
    const int rhi = rlo + 8;

    for (int t = 0; t < ntile; t++) {
        if (t + 1 < ntile)
            asm volatile("cp.async.wait_group 1;\n");   // tile t ready, t+1 in flight
        else
            asm volatile("cp.async.wait_group 0;\n");
        __syncthreads();   // single barrier per tile: data ready + prev reads done

        if (t + 2 < ntile)
            flash_load_kv(sb, t + 2, (t + 2) % 3, Khg, Vhg, tid);

        uint32_t kb = sb + (t % 3) * 32768;
        uint32_t vb = kb + 16384;

        float sacc[8][4];
#pragma unroll
        for (int n = 0; n < 8; n++)
#pragma unroll
            for (int r = 0; r < 4; r++) sacc[n][r] = 0.f;

#pragma unroll
        for (int kk = 0; kk < 8; kk++) {
#pragma unroll
            for (int j2 = 0; j2 < 4; j2++) {
                uint32_t bh[4];
                int n_l = (j2 * 2 + (mid >> 1)) * 8 + rin;
                int chnk = kk * 2 + (mid & 1);
                ldsm4(bh, kb + sw256(n_l, chnk));
#pragma unroll
                for (int jj = 0; jj < 2; jj++) {
                    int j = j2 * 2 + jj;
                    mma16816h(sacc[j], qreg[kk], bh[jj * 2], bh[jj * 2 + 1]);
                }
            }
        }

        int k0 = t * FK;
        bool diag = (t == ntile - 1);
#pragma unroll
        for (int n = 0; n < 8; n++) {
            int c0 = k0 + n * 8 + (lane & 3) * 2;
            sacc[n][0] *= scale2;
            sacc[n][1] *= scale2;
            sacc[n][2] *= scale2;
            sacc[n][3] *= scale2;
            if (diag) {
                if (c0 > rlo) sacc[n][0] = -1e30f;
                if (c0 + 1 > rlo) sacc[n][1] = -1e30f;
                if (c0 > rhi) sacc[n][2] = -1e30f;
                if (c0 + 1 > rhi) sacc[n][3] = -1e30f;
            }
        }

        float mx0 = -1e30f, mx1 = -1e30f;
#pragma unroll
        for (int n = 0; n < 8; n++) {
            mx0 = fmaxf(mx0, fmaxf(sacc[n][0], sacc[n][1]));
            mx1 = fmaxf(mx1, fmaxf(sacc[n][2], sacc[n][3]));
        }
        mx0 = fmaxf(mx0, __shfl_xor_sync(0xffffffffu, mx0, 1));
        mx0 = fmaxf(mx0, __shfl_xor_sync(0xffffffffu, mx0, 2));
        mx1 = fmaxf(mx1, __shfl_xor_sync(0xffffffffu, mx1, 1));
        mx1 = fmaxf(mx1, __shfl_xor_sync(0xffffffffu, mx1, 2));
        float newm0 = fmaxf(m_lo, mx0);
        float newm1 = fmaxf(m_hi, mx1);
        float corr0 = exp2f(m_lo - newm0);
        float corr1 = exp2f(m_hi - newm1);
        m_lo = newm0;
        m_hi = newm1;

        float ls0 = 0.f, ls1 = 0.f;
#pragma unroll
        for (int n = 0; n < 8; n++) {
            sacc[n][0] = exp2f(sacc[n][0] - newm0);
            sacc[n][1] = exp2f(sacc[n][1] - newm0);
            sacc[n][2] = exp2f(sacc[n][2] - newm1);
            sacc[n][3] = exp2f(sacc[n][3] - newm1);
            ls0 += sacc[n][0] + sacc[n][1];
            ls1 += sacc[n][2] + sacc[n][3];
        }
        ls0 += __shfl_xor_sync(0xffffffffu, ls0, 1);
        ls0 += __shfl_xor_sync(0xffffffffu, ls0, 2);
        ls1 += __shfl_xor_sync(0xffffffffu, ls1, 1);
        ls1 += __shfl_xor_sync(0xffffffffu, ls1, 2);
        l_lo = l_lo * corr0 + ls0;
        l_hi = l_hi * corr1 + ls1;

#pragma unroll
        for (int v = 0; v < 16; v++) {
            oacc[v][0] *= corr0;
            oacc[v][1] *= corr0;
            oacc[v][2] *= corr1;
            oacc[v][3] *= corr1;
        }

        // ---- O += P V  (P rounded, V 1-term) ----
#pragma unroll
        for (int kk = 0; kk < 4; kk++) {
            uint32_t aph[4];
            aph[0] = pack_f2h2(sacc[2 * kk][0], sacc[2 * kk][1]);
            aph[1] = pack_f2h2(sacc[2 * kk][2], sacc[2 * kk][3]);
            aph[2] = pack_f2h2(sacc[2 * kk + 1][0], sacc[2 * kk + 1][1]);
            aph[3] = pack_f2h2(sacc[2 * kk + 1][2], sacc[2 * kk + 1][3]);
#pragma unroll
            for (int v2 = 0; v2 < 8; v2++) {
                int g = lane >> 3;
                int row = kk * 16 + (g & 1) * 8 + rin;
                int chnk = v2 * 2 + (g >> 1);
                uint32_t vh[4];
                ldsm4t(vh, vb + sw256(row, chnk));
#pragma unroll
                for (int gg = 0; gg < 2; gg++) {
                    int vnt = v2 * 2 + gg;
                    mma16816h(oacc[vnt], aph, vh[gg * 2], vh[gg * 2 + 1]);
                }
            }
        }
        // no trailing sync: next iteration's barrier protects buffer reuse
    }

    // epilogue: normalize, write rounded fp16 for the out-proj
    float inv0 = 1.f / l_lo;
    float inv1 = 1.f / l_hi;
    int row0 = b * SS + q0 + wid * 16 + (lane >> 2);
    int row1 = row0 + 8;
#pragma unroll
    for (int v = 0; v < 16; v++) {
        int col = h * HD + v * 8 + (lane & 3) * 2;
        *(uint32_t*)(g_Ah + (size_t)row0 * KDIM + col) =
            pack_f2h2(oacc[v][0] * inv0, oacc[v][1] * inv0);
        *(uint32_t*)(g_Ah + (size_t)row1 * KDIM + col) =
            pack_f2h2(oacc[v][2] * inv1, oacc[v][3] * inv1);
    }
}

// ---------------------------------------------------------------------------
extern "C" void kernel_launch(void* const* d_in, const int* in_sizes, int n_in,
                              void* d_out, int out_size) {
    const float* X = (const float*)d_in[0];
    const float* Wq = (const float*)d_in[1];
    const float* Wk = (const float*)d_in[2];
    const float* Wv = (const float*)d_in[3];
    const float* Wo = (const float*)d_in[4];
    float* out = (float*)d_out;

    // 0. Round inputs to fp16 + RoPE table (fused)
    split_inputs_kernel<<<(SPLIT_TOTAL + 255) / 256, 256>>>(X, Wq, Wk, Wv, Wo);

    // 1. QKV projections with fused RoPE + head-major fp16 epilogue
    cudaFuncSetAttribute(qkv_gemm_kernel, cudaFuncAttributeMaxDynamicSharedMemorySize,
                         QKV_SMEM);
    qkv_gemm_kernel<<<dim3(24, 32), 256, QKV_SMEM>>>();

    // 2. fp16 flash attention (3-stage KV, one sync/tile, 2 CTAs/SM)
    cudaFuncSetAttribute(flash_tc_kernel, cudaFuncAttributeMaxDynamicSharedMemorySize,
                         FLASH_SMEM);
    flash_tc_kernel<<<dim3(SS / FQ, NH, BB), FTHREADS, FLASH_SMEM>>>();

    // 3. Output projection
    cudaFuncSetAttribute(out_gemm_kernel, cudaFuncAttributeMaxDynamicSharedMemorySize,
                         GEMM_SMEM);
    out_gemm_kernel<<<dim3(16, 32), 256, GEMM_SMEM>>>(out);
}

// round 15
// speedup vs baseline: 11.0550x; 1.0035x over previous
#include <cuda_runtime.h>
#include <cuda_fp16.h>
#include <math.h>
#include <stdint.h>

// Problem constants
#define BB 2
#define SS 2048
#define HH 2048
#define NH 16
#define NKV 4
#define HD 128
#define GROUPS (NH / NKV)        // 4
#define M_TOT (BB * SS)          // 4096
#define QDIM (NH * HD)           // 2048
#define KVDIM (NKV * HD)         // 512
#define KDIM 2048                // GEMM reduction dim

// scale/sqrt(HD) * log2(e): folded into Q at the QKV epilogue
#define SCALE2F (0.08838834764831845f * 1.4426950408889634f)

__device__ float g_cos[SS * 64];
__device__ float g_sin[SS * 64];

// fp16 buffers
__device__ __align__(16) __half g_Xh[M_TOT * KDIM];
__device__ __align__(16) __half g_Wqh[QDIM * KDIM];
__device__ __align__(16) __half g_Wkh[KVDIM * KDIM];
__device__ __align__(16) __half g_Wvh[KVDIM * KDIM];
__device__ __align__(16) __half g_Woh[HH * KDIM];
__device__ __align__(16) __half g_Ah[M_TOT * KDIM];     // flash out (rounded)

// fp16 head-major buffers for flash: [b, h, s, d]
__device__ __align__(16) __half g_Qb[M_TOT * QDIM];     // pre-scaled by SCALE2F
__device__ __align__(16) __half g_Kb[M_TOT * KVDIM];
__device__ __align__(16) __half g_Vb[M_TOT * KVDIM];

// ---------------------------------------------------------------------------
// Helpers
// ---------------------------------------------------------------------------
__device__ __forceinline__ uint32_t pack_f2h2(float a, float b) {
    __half2 t(__float2half_rn(a), __float2half_rn(b));
    return *(uint32_t*)&t;
}
__device__ __forceinline__ void cp16(uint32_t saddr, const void* gaddr) {
    asm volatile("cp.async.cg.shared.global [%0], [%1], 16;\n" ::"r"(saddr), "l"(gaddr));
}
__device__ __forceinline__ void ldsm4(uint32_t* r, uint32_t addr) {
    asm volatile("ldmatrix.sync.aligned.m8n8.x4.shared.b16 {%0,%1,%2,%3}, [%4];\n"
                 : "=r"(r[0]), "=r"(r[1]), "=r"(r[2]), "=r"(r[3]) : "r"(addr));
}
__device__ __forceinline__ void ldsm4t(uint32_t* r, uint32_t addr) {
    asm volatile("ldmatrix.sync.aligned.m8n8.x4.trans.shared.b16 {%0,%1,%2,%3}, [%4];\n"
                 : "=r"(r[0]), "=r"(r[1]), "=r"(r[2]), "=r"(r[3]) : "r"(addr));
}
__device__ __forceinline__ void mma16816h(float* c, const uint32_t* a, uint32_t b0, uint32_t b1) {
    asm volatile("mma.sync.aligned.m16n8k16.row.col.f32.f16.f16.f32 "
                 "{%0,%1,%2,%3}, {%4,%5,%6,%7}, {%8,%9}, {%0,%1,%2,%3};\n"
                 : "+f"(c[0]), "+f"(c[1]), "+f"(c[2]), "+f"(c[3])
                 : "r"(a[0]), "r"(a[1]), "r"(a[2]), "r"(a[3]), "r"(b0), "r"(b1));
}

// ---------------------------------------------------------------------------
// Input split: X -> fp16, weights -> fp16 (rounded), 8 floats/thread + RoPE
// ---------------------------------------------------------------------------
#define N8_X  ((M_TOT * KDIM) / 8)
#define N8_WQ ((QDIM * KDIM) / 8)
#define N8_WKV ((KVDIM * KDIM) / 8)
#define N8_WO ((HH * KDIM) / 8)
#define N8_TOTAL (N8_X + N8_WQ + 2 * N8_WKV + N8_WO)
#define NT_ROPE (SS * 64)
#define SPLIT_TOTAL (N8_TOTAL + NT_ROPE)

__global__ void split_inputs_kernel(const float* __restrict__ X,
                                    const float* __restrict__ Wq,
                                    const float* __restrict__ Wk,
                                    const float* __restrict__ Wv,
                                    const float* __restrict__ Wo) {
    int i = blockIdx.x * blockDim.x + threadIdx.x;
    if (i >= SPLIT_TOTAL) return;
    if (i >= N8_TOTAL) {
        int idx = i - N8_TOTAL;           // rope table entry
        int pos = idx >> 6;
        int d = idx & 63;
        double inv = pow(10000.0, -(double)d / 64.0);
        double ang = (double)pos * inv;
        double sd, cd;
        sincos(ang, &sd, &cd);
        g_cos[idx] = (float)cd;
        g_sin[idx] = (float)sd;
        return;
    }
    const float* src;
    __half* dst;
    int off;
    if (i < N8_X) {
        src = X; dst = g_Xh; off = i;
    } else if (i < N8_X + N8_WQ) {
        src = Wq; dst = g_Wqh; off = i - N8_X;
    } else if (i < N8_X + N8_WQ + N8_WKV) {
        src = Wk; dst = g_Wkh; off = i - N8_X - N8_WQ;
    } else if (i < N8_X + N8_WQ + 2 * N8_WKV) {
        src = Wv; dst = g_Wvh; off = i - N8_X - N8_WQ - N8_WKV;
    } else {
        src = Wo; dst = g_Woh; off = i - N8_X - N8_WQ - 2 * N8_WKV;
    }
    float4 v0 = *(const float4*)(src + (size_t)off * 8);
    float4 v1 = *(const float4*)(src + (size_t)off * 8 + 4);
    uint4 o;
    o.x = pack_f2h2(v0.x, v0.y);
    o.y = pack_f2h2(v0.z, v0.w);
    o.z = pack_f2h2(v1.x, v1.y);
    o.w = pack_f2h2(v1.z, v1.w);
    *(uint4*)(dst + (size_t)off * 8) = o;
}

// ---------------------------------------------------------------------------
// GEMM: K-chunk 64, 3-stage pipeline. Stage: A 16K | B 16K = 32K.
// ---------------------------------------------------------------------------
__device__ __forceinline__ uint32_t sw128b(int row, int chunk) {
    return (uint32_t)(row * 128 + ((chunk ^ (row & 7)) << 4));
}

#define STAGE64 32768
#define GEMM_SMEM (3 * STAGE64)          // 96 KB
#define KT64 (KDIM / 64)                 // 32

__device__ __forceinline__ void load_stage64(uint32_t S, int buf,
                                             const __half* __restrict__ A,
                                             const __half* __restrict__ B,
                                             int m0, int n0, int k0, int tid) {
    uint32_t st = S + buf * STAGE64;
#pragma unroll
    for (int l = 0; l < 4; l++) {
        int idx = tid + l * 256;          // 0..1023 = 128 rows x 8 chunks
        int row = idx >> 3;
        int c = idx & 7;
        uint32_t spos = sw128b(row, c);
        cp16(st + spos, A + (size_t)(m0 + row) * KDIM + k0 + c * 8);
        cp16(st + 16384 + spos, B + (size_t)(n0 + row) * KDIM + k0 + c * 8);
    }
    asm volatile("cp.async.commit_group;\n");
}

// Core 128x128x2048 mainloop (K-chunk 64), leaves result in acc[4][4][4]
#define GEMM_MAINLOOP(A, B, m0, n0)                                                   \
    float acc[4][4][4];                                                               \
    _Pragma("unroll") for (int i = 0; i < 4; i++)                                     \
        _Pragma("unroll") for (int j = 0; j < 4; j++)                                 \
            _Pragma("unroll") for (int r = 0; r < 4; r++) acc[i][j][r] = 0.f;         \
    load_stage64(S, 0, A, B, m0, n0, 0, tid);                                         \
    load_stage64(S, 1, A, B, m0, n0, 64, tid);                                        \
    for (int kt = 0; kt < KT64; kt++) {                                               \
        if (kt < KT64 - 1)                                                            \
            asm volatile("cp.async.wait_group 1;\n");                                 \
        else                                                                          \
            asm volatile("cp.async.wait_group 0;\n");                                 \
        __syncthreads();                                                              \
        if (kt + 2 < KT64)                                                            \
            load_stage64(S, (kt + 2) % 3, A, B, m0, n0, (kt + 2) * 64, tid);          \
        uint32_t aB = S + (kt % 3) * STAGE64;                                         \
        uint32_t bB = aB + 16384;                                                     \
        _Pragma("unroll") for (int kk = 0; kk < 4; kk++) {                            \
            uint32_t ah[4][4];                                                        \
            _Pragma("unroll") for (int i = 0; i < 4; i++) {                           \
                int m_l = wm * 64 + i * 16 + (mid & 1) * 8 + rin;                     \
                int chnk = kk * 2 + (mid >> 1);                                       \
                ldsm4(ah[i], aB + sw128b(m_l, chnk));                                 \
            }                                                                         \
            _Pragma("unroll") for (int j2 = 0; j2 < 2; j2++) {                        \
                uint32_t bh[4];                                                       \
                int n_l = wn * 32 + (j2 * 2 + (mid >> 1)) * 8 + rin;                  \
                int chnk = kk * 2 + (mid & 1);                                        \
                ldsm4(bh, bB + sw128b(n_l, chnk));                                    \
                _Pragma("unroll") for (int jj = 0; jj < 2; jj++) {                    \
                    int j = j2 * 2 + jj;                                              \
                    _Pragma("unroll") for (int i = 0; i < 4; i++)                     \
                        mma16816h(acc[i][j], ah[i], bh[jj * 2], bh[jj * 2 + 1]);      \
                }                                                                     \
            }                                                                         \
        }                                                                             \
    }

// ---------------------------------------------------------------------------
// QKV GEMM with fused RoPE + fp16 head-major epilogue (Q pre-scaled).
// ---------------------------------------------------------------------------
#define QKV_SMEM GEMM_SMEM    // 96K (epilogue tile 66K fits inside)

__global__ __launch_bounds__(256, 2) void qkv_gemm_kernel() {
    extern __shared__ char smem_raw[];
    uint32_t S = (uint32_t)__cvta_generic_to_shared(smem_raw);
    int tid = threadIdx.x;
    int lane = tid & 31, wid = tid >> 5;
    int wm = wid & 1, wn = wid >> 1;
    int mid = lane >> 3, rin = lane & 7;

    int bx = blockIdx.x;
    int m0 = blockIdx.y * 128;

    const __half* A = g_Xh;
    const __half* B;
    __half* dstH;
    int head, nhd;
    bool do_rope;
    float outmul;
    if (bx < 16) {
        B = g_Wqh; dstH = g_Qb; head = bx; nhd = NH; do_rope = true; outmul = SCALE2F;
    } else if (bx < 20) {
        B = g_Wkh; dstH = g_Kb; head = bx - 16; nhd = NKV; do_rope = true; outmul = 1.f;
    } else {
        B = g_Wvh; dstH = g_Vb; head = bx - 20; nhd = NKV; do_rope = false; outmul = 1.f;
    }
    int n0 = head * HD;

    GEMM_MAINLOOP(A, B, m0, n0)

    // ---- fused epilogue: stage fp32 tile in smem, rope pairs, fp16 out ----
    __syncthreads();
    float* tile = (float*)smem_raw;
#pragma unroll
    for (int i = 0; i < 4; i++) {
#pragma unroll
        for (int j = 0; j < 4; j++) {
            int r0 = wm * 64 + i * 16 + (lane >> 2);
            int cc = wn * 32 + j * 8 + (lane & 3) * 2;
            *(float2*)&tile[r0 * 132 + cc] = make_float2(acc[i][j][0], acc[i][j][1]);
            *(float2*)&tile[(r0 + 8) * 132 + cc] = make_float2(acc[i][j][2], acc[i][j][3]);
        }
    }
    __syncthreads();

    for (int it = tid; it < 128 * 64; it += 256) {
        int row = it >> 6, d = it & 63;
        int m = m0 + row;
        int s = m & (SS - 1), b = m >> 11;
        float x1 = tile[row * 132 + d];
        float x2 = tile[row * 132 + d + 64];
        float y1 = x1, y2 = x2;
        if (do_rope) {
            float c = g_cos[s * 64 + d], sn = g_sin[s * 64 + d];
            y1 = x1 * c - x2 * sn;
            y2 = x2 * c + x1 * sn;
        }
        y1 *= outmul;
        y2 *= outmul;
        size_t dst = ((size_t)(b * nhd + head) * SS + s) * HD + d;
        dstH[dst] = __float2half_rn(y1);
        dstH[dst + 64] = __float2half_rn(y2);
    }
}

// ---------------------------------------------------------------------------
// Output projection (1-term, fp32 out)
// ---------------------------------------------------------------------------
__global__ __launch_bounds__(256, 2) void out_gemm_kernel(float* __restrict__ out) {
    extern __shared__ char smem_raw[];
    uint32_t S = (uint32_t)__cvta_generic_to_shared(smem_raw);
    int tid = threadIdx.x;
    int lane = tid & 31, wid = tid >> 5;
    int wm = wid & 1, wn = wid >> 1;
    int mid = lane >> 3, rin = lane & 7;
    int m0 = blockIdx.y * 128, n0 = blockIdx.x * 128;

    GEMM_MAINLOOP(g_Ah, g_Woh, m0, n0)

#pragma unroll
    for (int i = 0; i < 4; i++) {
#pragma unroll
        for (int j = 0; j < 4; j++) {
            int r0 = m0 + wm * 64 + i * 16 + (lane >> 2);
            int cc = n0 + wn * 32 + j * 8 + (lane & 3) * 2;
            *(float2*)&out[(size_t)r0 * HH + cc] = make_float2(acc[i][j][0], acc[i][j][1]);
            *(float2*)&out[(size_t)(r0 + 8) * HH + cc] = make_float2(acc[i][j][2], acc[i][j][3]);
        }
    }
}

// ---------------------------------------------------------------------------
// fp16 flash attention (causal), 1-term operands, Q pre-scaled (log2 domain).
// BQ=64, 4 warps, 2 CTAs/SM. Q in registers; exp2 softmax.
// 3-stage KV pipeline, ONE sync per tile. smem: 3 x (K 16K | V 16K) = 96 KB
// ---------------------------------------------------------------------------
#define FQ 64
#define FK 64
#define FTHREADS 128
#define FLASH_SMEM (3 * 32768)

__device__ __forceinline__ uint32_t sw256(int row, int chunk) {
    return (uint32_t)(row * 256 + ((chunk ^ (row & 7)) << 4));
}

__device__ __forceinline__ void flash_load_kv(uint32_t sb, int t, int st,
                                              const __half* Kh, const __half* Vh, int tid) {
    uint32_t base = sb + st * 32768;
    size_t g0 = (size_t)t * FK * HD;
#pragma unroll
    for (int l = 0; l < 8; l++) {
        int idx = tid + l * FTHREADS;    // 0..1023 = 64 rows x 16 chunks
        int row = idx >> 4;
        int c = idx & 15;
        uint32_t off = sw256(row, c);
        size_t go = g0 + (size_t)row * HD + c * 8;
        cp16(base + off, Kh + go);
        cp16(base + 16384 + off, Vh + go);
    }
    asm volatile("cp.async.commit_group;\n");
}

__global__ __launch_bounds__(FTHREADS, 2) void flash_tc_kernel() {
    extern __shared__ char smem_raw[];
    uint32_t sb = (uint32_t)__cvta_generic_to_shared(smem_raw);

    int qt = (int)(gridDim.x - 1 - blockIdx.x);   // big tiles first
    int h = blockIdx.y, b = blockIdx.z;
    int q0 = qt * FQ;
    int kh = h / GROUPS;

    int tid = threadIdx.x, lane = tid & 31, wid = tid >> 5;  // wid 0..3
    int mid = lane >> 3, rin = lane & 7;

    const __half* Qg = g_Qb + ((size_t)(b * NH + h) * SS + q0) * HD;
    const __half* Khg = g_Kb + (size_t)(b * NKV + kh) * SS * HD;
    const __half* Vhg = g_Vb + (size_t)(b * NKV + kh) * SS * HD;

    // ---- Stage Q transiently in buf2; preload KV0, KV1 ----
    uint32_t Qstage = sb + 2 * 32768;
#pragma unroll
    for (int l = 0; l < 8; l++) {
        int idx = tid + l * FTHREADS;
        int row = idx >> 4;
        int c = idx & 15;
        cp16(Qstage + sw256(row, c), Qg + (size_t)row * HD + c * 8);
    }
    asm volatile("cp.async.commit_group;\n");
    const int ntile = qt + 1;
    flash_load_kv(sb, 0, 0, Khg, Vhg, tid);
    if (ntile > 1) {
        flash_load_kv(sb, 1, 1, Khg, Vhg, tid);
        asm volatile("cp.async.wait_group 2;\n");   // pending {Q,KV0,KV1}: Q done
    } else {
        asm volatile("cp.async.wait_group 1;\n");   // pending {Q,KV0}: Q done
    }
    __syncthreads();                              // ALL threads' Q copies visible
    uint32_t qreg[8][4];
#pragma unroll
    for (int kk = 0; kk < 8; kk++) {
        int m_l = wid * 16 + (mid & 1) * 8 + rin;
        int chnk = kk * 2 + (mid >> 1);
        ldsm4(qreg[kk], Qstage + sw256(m_l, chnk));
    }
    // Loop's first barrier (iteration 0) orders all Q ldsm before the tile-2
    // prefetch that overwrites buf2.

    float m_lo = -1e30f, m_hi = -1e30f, l_lo = 0.f, l_hi = 0.f;
    float oacc[16][4];
#pragma unroll
    for (int v = 0; v < 16; v++)
#pragma unroll
        for (int r = 0; r < 4; r++) oacc[v][r] = 0.f;

    const int rlo = q0 + wid * 16 + (lane >> 2);
    const int rhi = rlo + 8;

    for (int t = 0; t < ntile; t++) {
        if (t + 1 < ntile)
            asm volatile("cp.async.wait_group 1;\n");   // tile t ready, t+1 in flight
        else
            asm volatile("cp.async.wait_group 0;\n");
        __syncthreads();   // single barrier per tile: data ready + prev reads done

        if (t + 2 < ntile)
            flash_load_kv(sb, t + 2, (t + 2) % 3, Khg, Vhg, tid);

        uint32_t kb = sb + (t % 3) * 32768;
        uint32_t vb = kb + 16384;

        float sacc[8][4];
#pragma unroll
        for (int n = 0; n < 8; n++)
#pragma unroll
            for (int r = 0; r < 4; r++) sacc[n][r] = 0.f;

#pragma unroll
        for (int kk = 0; kk < 8; kk++) {
#pragma unroll
            for (int j2 = 0; j2 < 4; j2++) {
                uint32_t bh[4];
                int n_l = (j2 * 2 + (mid >> 1)) * 8 + rin;
                int chnk = kk * 2 + (mid & 1);
                ldsm4(bh, kb + sw256(n_l, chnk));
#pragma unroll
                for (int jj = 0; jj < 2; jj++) {
                    int j = j2 * 2 + jj;
                    mma16816h(sacc[j], qreg[kk], bh[jj * 2], bh[jj * 2 + 1]);
                }
            }
        }

        // scores already in exp2 domain (Q pre-scaled); mask only on diag tile
        if (t == ntile - 1) {
            int k0 = t * FK;
#pragma unroll
            for (int n = 0; n < 8; n++) {
                int c0 = k0 + n * 8 + (lane & 3) * 2;
                if (c0 > rlo) sacc[n][0] = -1e30f;
                if (c0 + 1 > rlo) sacc[n][1] = -1e30f;
                if (c0 > rhi) sacc[n][2] = -1e30f;
                if (c0 + 1 > rhi) sacc[n][3] = -1e30f;
            }
        }

        float mx0 = -1e30f, mx1 = -1e30f;
#pragma unroll
        for (int n = 0; n < 8; n++) {
            mx0 = fmaxf(mx0, fmaxf(sacc[n][0], sacc[n][1]));
            mx1 = fmaxf(mx1, fmaxf(sacc[n][2], sacc[n][3]));
        }
        mx0 = fmaxf(mx0, __shfl_xor_sync(0xffffffffu, mx0, 1));
        mx0 = fmaxf(mx0, __shfl_xor_sync(0xffffffffu, mx0, 2));
        mx1 = fmaxf(mx1, __shfl_xor_sync(0xffffffffu, mx1, 1));
        mx1 = fmaxf(mx1, __shfl_xor_sync(0xffffffffu, mx1, 2));
        float newm0 = fmaxf(m_lo, mx0);
        float newm1 = fmaxf(m_hi, mx1);
        float corr0 = exp2f(m_lo - newm0);
        float corr1 = exp2f(m_hi - newm1);
        m_lo = newm0;
        m_hi = newm1;

        float ls0 = 0.f, ls1 = 0.f;
#pragma unroll
        for (int n = 0; n < 8; n++) {
            sacc[n][0] = exp2f(sacc[n][0] - newm0);
            sacc[n][1] = exp2f(sacc[n][1] - newm0);
            sacc[n][2] = exp2f(sacc[n][2] - newm1);
            sacc[n][3] = exp2f(sacc[n][3] - newm1);
            ls0 += sacc[n][0] + sacc[n][1];
            ls1 += sacc[n][2] + sacc[n][3];
        }
        ls0 += __shfl_xor_sync(0xffffffffu, ls0, 1);
        ls0 += __shfl_xor_sync(0xffffffffu, ls0, 2);
        ls1 += __shfl_xor_sync(0xffffffffu, ls1, 1);
        ls1 += __shfl_xor_sync(0xffffffffu, ls1, 2);
        l_lo = l_lo * corr0 + ls0;
        l_hi = l_hi * corr1 + ls1;

#pragma unroll
        for (int v = 0; v < 16; v++) {
            oacc[v][0] *= corr0;
            oacc[v][1] *= corr0;
            oacc[v][2] *= corr1;
            oacc[v][3] *= corr1;
        }

        // ---- O += P V  (P rounded, V 1-term) ----
#pragma unroll
        for (int kk = 0; kk < 4; kk++) {
            uint32_t aph[4];
            aph[0] = pack_f2h2(sacc[2 * kk][0], sacc[2 * kk][1]);
            aph[1] = pack_f2h2(sacc[2 * kk][2], sacc[2 * kk][3]);
            aph[2] = pack_f2h2(sacc[2 * kk + 1][0], sacc[2 * kk + 1][1]);
            aph[3] = pack_f2h2(sacc[2 * kk + 1][2], sacc[2 * kk + 1][3]);
#pragma unroll
            for (int v2 = 0; v2 < 8; v2++) {
                int g = lane >> 3;
                int row = kk * 16 + (g & 1) * 8 + rin;
                int chnk = v2 * 2 + (g >> 1);
                uint32_t vh[4];
                ldsm4t(vh, vb + sw256(row, chnk));
#pragma unroll
                for (int gg = 0; gg < 2; gg++) {
                    int vnt = v2 * 2 + gg;
                    mma16816h(oacc[vnt], aph, vh[gg * 2], vh[gg * 2 + 1]);
                }
            }
        }
        // no trailing sync: next iteration's barrier protects buffer reuse
    }

    // epilogue: normalize, write rounded fp16 for the out-proj
    float inv0 = 1.f / l_lo;
    float inv1 = 1.f / l_hi;
    int row0 = b * SS + q0 + wid * 16 + (lane >> 2);
    int row1 = row0 + 8;
#pragma unroll
    for (int v = 0; v < 16; v++) {
        int col = h * HD + v * 8 + (lane & 3) * 2;
        *(uint32_t*)(g_Ah + (size_t)row0 * KDIM + col) =
            pack_f2h2(oacc[v][0] * inv0, oacc[v][1] * inv0);
        *(uint32_t*)(g_Ah + (size_t)row1 * KDIM + col) =
            pack_f2h2(oacc[v][2] * inv1, oacc[v][3] * inv1);
    }
}

// ---------------------------------------------------------------------------
extern "C" void kernel_launch(void* const* d_in, const int* in_sizes, int n_in,
                              void* d_out, int out_size) {
    const float* X = (const float*)d_in[0];
    const float* Wq = (const float*)d_in[1];
    const float* Wk = (const float*)d_in[2];
    const float* Wv = (const float*)d_in[3];
    const float* Wo = (const float*)d_in[4];
    float* out = (float*)d_out;

    // 0. Round inputs to fp16 + RoPE table (fused)
    split_inputs_kernel<<<(SPLIT_TOTAL + 255) / 256, 256>>>(X, Wq, Wk, Wv, Wo);

    // 1. QKV projections with fused RoPE + head-major fp16 epilogue
    cudaFuncSetAttribute(qkv_gemm_kernel, cudaFuncAttributeMaxDynamicSharedMemorySize,
                         QKV_SMEM);
    qkv_gemm_kernel<<<dim3(24, 32), 256, QKV_SMEM>>>();

    // 2. fp16 flash attention (3-stage KV, one sync/tile, 2 CTAs/SM)
    cudaFuncSetAttribute(flash_tc_kernel, cudaFuncAttributeMaxDynamicSharedMemorySize,
                         FLASH_SMEM);
    flash_tc_kernel<<<dim3(SS / FQ, NH, BB), FTHREADS, FLASH_SMEM>>>();

    // 3. Output projection
    cudaFuncSetAttribute(out_gemm_kernel, cudaFuncAttributeMaxDynamicSharedMemorySize,
                         GEMM_SMEM);
    out_gemm_kernel<<<dim3(16, 32), 256, GEMM_SMEM>>>(out);
}

// round 16
// speedup vs baseline: 11.2616x; 1.0187x over previous
#include <cuda_runtime.h>
#include <cuda_fp16.h>
#include <math.h>
#include <stdint.h>

// Problem constants
#define BB 2
#define SS 2048
#define HH 2048
#define NH 16
#define NKV 4
#define HD 128
#define GROUPS (NH / NKV)        // 4
#define M_TOT (BB * SS)          // 4096
#define QDIM (NH * HD)           // 2048
#define KVDIM (NKV * HD)         // 512
#define KDIM 2048                // GEMM reduction dim

// 1/sqrt(HD) * log2(e): folded into Q at the QKV epilogue
#define SCALE2F (0.08838834764831845f * 1.4426950408889634f)

__device__ float g_cos[SS * 64];
__device__ float g_sin[SS * 64];

// fp16 buffers
__device__ __align__(16) __half g_Xh[M_TOT * KDIM];
__device__ __align__(16) __half g_Wqh[QDIM * KDIM];
__device__ __align__(16) __half g_Wkh[KVDIM * KDIM];
__device__ __align__(16) __half g_Wvh[KVDIM * KDIM];
__device__ __align__(16) __half g_Woh[HH * KDIM];
__device__ __align__(16) __half g_Ah[M_TOT * KDIM];     // flash out (rounded)

// fp16 head-major buffers for flash: [b, h, s, d]
__device__ __align__(16) __half g_Qb[M_TOT * QDIM];     // pre-scaled by SCALE2F
__device__ __align__(16) __half g_Kb[M_TOT * KVDIM];
__device__ __align__(16) __half g_Vb[M_TOT * KVDIM];

// ---------------------------------------------------------------------------
// Helpers
// ---------------------------------------------------------------------------
__device__ __forceinline__ uint32_t pack_f2h2(float a, float b) {
    __half2 t(__float2half_rn(a), __float2half_rn(b));
    return *(uint32_t*)&t;
}
__device__ __forceinline__ void cp16(uint32_t saddr, const void* gaddr) {
    asm volatile("cp.async.cg.shared.global [%0], [%1], 16;\n" ::"r"(saddr), "l"(gaddr));
}
__device__ __forceinline__ void ldsm4(uint32_t* r, uint32_t addr) {
    asm volatile("ldmatrix.sync.aligned.m8n8.x4.shared.b16 {%0,%1,%2,%3}, [%4];\n"
                 : "=r"(r[0]), "=r"(r[1]), "=r"(r[2]), "=r"(r[3]) : "r"(addr));
}
__device__ __forceinline__ void ldsm4t(uint32_t* r, uint32_t addr) {
    asm volatile("ldmatrix.sync.aligned.m8n8.x4.trans.shared.b16 {%0,%1,%2,%3}, [%4];\n"
                 : "=r"(r[0]), "=r"(r[1]), "=r"(r[2]), "=r"(r[3]) : "r"(addr));
}
__device__ __forceinline__ void mma16816h(float* c, const uint32_t* a, uint32_t b0, uint32_t b1) {
    asm volatile("mma.sync.aligned.m16n8k16.row.col.f32.f16.f16.f32 "
                 "{%0,%1,%2,%3}, {%4,%5,%6,%7}, {%8,%9}, {%0,%1,%2,%3};\n"
                 : "+f"(c[0]), "+f"(c[1]), "+f"(c[2]), "+f"(c[3])
                 : "r"(a[0]), "r"(a[1]), "r"(a[2]), "r"(a[3]), "r"(b0), "r"(b1));
}

// ---------------------------------------------------------------------------
// Input split: fp32 -> fp16, 16 floats/thread (4 independent float4 chains)
// + RoPE table tail.
// ---------------------------------------------------------------------------
#define N16_X  ((M_TOT * KDIM) / 16)
#define N16_WQ ((QDIM * KDIM) / 16)
#define N16_WKV ((KVDIM * KDIM) / 16)
#define N16_WO ((HH * KDIM) / 16)
#define N16_TOTAL (N16_X + N16_WQ + 2 * N16_WKV + N16_WO)
#define NT_ROPE (SS * 64)
#define SPLIT_TOTAL (N16_TOTAL + NT_ROPE)

__global__ void split_inputs_kernel(const float* __restrict__ X,
                                    const float* __restrict__ Wq,
                                    const float* __restrict__ Wk,
                                    const float* __restrict__ Wv,
                                    const float* __restrict__ Wo) {
    int i = blockIdx.x * blockDim.x + threadIdx.x;
    if (i >= SPLIT_TOTAL) return;
    if (i >= N16_TOTAL) {
        int idx = i - N16_TOTAL;          // rope table entry
        int pos = idx >> 6;
        int d = idx & 63;
        double inv = pow(10000.0, -(double)d / 64.0);
        double ang = (double)pos * inv;
        double sd, cd;
        sincos(ang, &sd, &cd);
        g_cos[idx] = (float)cd;
        g_sin[idx] = (float)sd;
        return;
    }
    const float* src;
    __half* dst;
    int off;
    if (i < N16_X) {
        src = X; dst = g_Xh; off = i;
    } else if (i < N16_X + N16_WQ) {
        src = Wq; dst = g_Wqh; off = i - N16_X;
    } else if (i < N16_X + N16_WQ + N16_WKV) {
        src = Wk; dst = g_Wkh; off = i - N16_X - N16_WQ;
    } else if (i < N16_X + N16_WQ + 2 * N16_WKV) {
        src = Wv; dst = g_Wvh; off = i - N16_X - N16_WQ - N16_WKV;
    } else {
        src = Wo; dst = g_Woh; off = i - N16_X - N16_WQ - 2 * N16_WKV;
    }
    const float4* s4 = (const float4*)(src + (size_t)off * 16);
    float4 v0 = s4[0];
    float4 v1 = s4[1];
    float4 v2 = s4[2];
    float4 v3 = s4[3];
    uint4 o0, o1;
    o0.x = pack_f2h2(v0.x, v0.y);
    o0.y = pack_f2h2(v0.z, v0.w);
    o0.z = pack_f2h2(v1.x, v1.y);
    o0.w = pack_f2h2(v1.z, v1.w);
    o1.x = pack_f2h2(v2.x, v2.y);
    o1.y = pack_f2h2(v2.z, v2.w);
    o1.z = pack_f2h2(v3.x, v3.y);
    o1.w = pack_f2h2(v3.z, v3.w);
    uint4* d4 = (uint4*)(dst + (size_t)off * 16);
    d4[0] = o0;
    d4[1] = o1;
}

// ---------------------------------------------------------------------------
// GEMM: K-chunk 64, 3-stage pipeline. Stage: A 16K | B 16K = 32K.
// ---------------------------------------------------------------------------
__device__ __forceinline__ uint32_t sw128b(int row, int chunk) {
    return (uint32_t)(row * 128 + ((chunk ^ (row & 7)) << 4));
}

#define STAGE64 32768
#define GEMM_SMEM (3 * STAGE64)          // 96 KB
#define KT64 (KDIM / 64)                 // 32

__device__ __forceinline__ void load_stage64(uint32_t S, int buf,
                                             const __half* __restrict__ A,
                                             const __half* __restrict__ B,
                                             int m0, int n0, int k0, int tid) {
    uint32_t st = S + buf * STAGE64;
#pragma unroll
    for (int l = 0; l < 4; l++) {
        int idx = tid + l * 256;          // 0..1023 = 128 rows x 8 chunks
        int row = idx >> 3;
        int c = idx & 7;
        uint32_t spos = sw128b(row, c);
        cp16(st + spos, A + (size_t)(m0 + row) * KDIM + k0 + c * 8);
        cp16(st + 16384 + spos, B + (size_t)(n0 + row) * KDIM + k0 + c * 8);
    }
    asm volatile("cp.async.commit_group;\n");
}

// Core 128x128x2048 mainloop (K-chunk 64), rotating buffer counters.
#define GEMM_MAINLOOP(A, B, m0, n0)                                                   \
    float acc[4][4][4];                                                               \
    _Pragma("unroll") for (int i = 0; i < 4; i++)                                     \
        _Pragma("unroll") for (int j = 0; j < 4; j++)                                 \
            _Pragma("unroll") for (int r = 0; r < 4; r++) acc[i][j][r] = 0.f;         \
    load_stage64(S, 0, A, B, m0, n0, 0, tid);                                         \
    load_stage64(S, 1, A, B, m0, n0, 64, tid);                                        \
    {                                                                                 \
        int cur = 0, pf = 2;                                                          \
        for (int kt = 0; kt < KT64; kt++) {                                           \
            if (kt < KT64 - 1)                                                        \
                asm volatile("cp.async.wait_group 1;\n");                             \
            else                                                                      \
                asm volatile("cp.async.wait_group 0;\n");                             \
            __syncthreads();                                                          \
            if (kt + 2 < KT64)                                                        \
                load_stage64(S, pf, A, B, m0, n0, (kt + 2) * 64, tid);                \
            uint32_t aB = S + cur * STAGE64;                                          \
            uint32_t bB = aB + 16384;                                                 \
            _Pragma("unroll") for (int kk = 0; kk < 4; kk++) {                        \
                uint32_t ah[4][4];                                                    \
                _Pragma("unroll") for (int i = 0; i < 4; i++) {                       \
                    int m_l = wm * 64 + i * 16 + (mid & 1) * 8 + rin;                 \
                    int chnk = kk * 2 + (mid >> 1);                                   \
                    ldsm4(ah[i], aB + sw128b(m_l, chnk));                             \
                }                                                                     \
                _Pragma("unroll") for (int j2 = 0; j2 < 2; j2++) {                    \
                    uint32_t bh[4];                                                   \
                    int n_l = wn * 32 + (j2 * 2 + (mid >> 1)) * 8 + rin;              \
                    int chnk = kk * 2 + (mid & 1);                                    \
                    ldsm4(bh, bB + sw128b(n_l, chnk));                                \
                    _Pragma("unroll") for (int jj = 0; jj < 2; jj++) {                \
                        int j = j2 * 2 + jj;                                          \
                        _Pragma("unroll") for (int i = 0; i < 4; i++)                 \
                            mma16816h(acc[i][j], ah[i], bh[jj * 2], bh[jj * 2 + 1]);  \
                    }                                                                 \
                }                                                                     \
            }                                                                         \
            cur = (cur == 2) ? 0 : cur + 1;                                           \
            pf = (pf == 2) ? 0 : pf + 1;                                              \
        }                                                                             \
    }

// ---------------------------------------------------------------------------
// QKV GEMM with fused RoPE + fp16 head-major epilogue (Q pre-scaled).
// ---------------------------------------------------------------------------
#define QKV_SMEM GEMM_SMEM    // 96K (epilogue tile 66K fits inside)

__global__ __launch_bounds__(256, 2) void qkv_gemm_kernel() {
    extern __shared__ char smem_raw[];
    uint32_t S = (uint32_t)__cvta_generic_to_shared(smem_raw);
    int tid = threadIdx.x;
    int lane = tid & 31, wid = tid >> 5;
    int wm = wid & 1, wn = wid >> 1;
    int mid = lane >> 3, rin = lane & 7;

    int bx = blockIdx.x;
    int m0 = blockIdx.y * 128;

    const __half* A = g_Xh;
    const __half* B;
    __half* dstH;
    int head, nhd;
    bool do_rope;
    float outmul;
    if (bx < 16) {
        B = g_Wqh; dstH = g_Qb; head = bx; nhd = NH; do_rope = true; outmul = SCALE2F;
    } else if (bx < 20) {
        B = g_Wkh; dstH = g_Kb; head = bx - 16; nhd = NKV; do_rope = true; outmul = 1.f;
    } else {
        B = g_Wvh; dstH = g_Vb; head = bx - 20; nhd = NKV; do_rope = false; outmul = 1.f;
    }
    int n0 = head * HD;

    GEMM_MAINLOOP(A, B, m0, n0)

    // ---- fused epilogue: stage fp32 tile in smem, rope pairs, fp16 out ----
    __syncthreads();
    float* tile = (float*)smem_raw;
#pragma unroll
    for (int i = 0; i < 4; i++) {
#pragma unroll
        for (int j = 0; j < 4; j++) {
            int r0 = wm * 64 + i * 16 + (lane >> 2);
            int cc = wn * 32 + j * 8 + (lane & 3) * 2;
            *(float2*)&tile[r0 * 132 + cc] = make_float2(acc[i][j][0], acc[i][j][1]);
            *(float2*)&tile[(r0 + 8) * 132 + cc] = make_float2(acc[i][j][2], acc[i][j][3]);
        }
    }
    __syncthreads();

    for (int it = tid; it < 128 * 64; it += 256) {
        int row = it >> 6, d = it & 63;
        int m = m0 + row;
        int s = m & (SS - 1), b = m >> 11;
        float x1 = tile[row * 132 + d];
        float x2 = tile[row * 132 + d + 64];
        float y1 = x1, y2 = x2;
        if (do_rope) {
            float c = g_cos[s * 64 + d], sn = g_sin[s * 64 + d];
            y1 = x1 * c - x2 * sn;
            y2 = x2 * c + x1 * sn;
        }
        y1 *= outmul;
        y2 *= outmul;
        size_t dst = ((size_t)(b * nhd + head) * SS + s) * HD + d;
        dstH[dst] = __float2half_rn(y1);
        dstH[dst + 64] = __float2half_rn(y2);
    }
}

// ---------------------------------------------------------------------------
// Output projection (1-term, fp32 out)
// ---------------------------------------------------------------------------
__global__ __launch_bounds__(256, 2) void out_gemm_kernel(float* __restrict__ out) {
    extern __shared__ char smem_raw[];
    uint32_t S = (uint32_t)__cvta_generic_to_shared(smem_raw);
    int tid = threadIdx.x;
    int lane = tid & 31, wid = tid >> 5;
    int wm = wid & 1, wn = wid >> 1;
    int mid = lane >> 3, rin = lane & 7;
    int m0 = blockIdx.y * 128, n0 = blockIdx.x * 128;

    GEMM_MAINLOOP(g_Ah, g_Woh, m0, n0)

#pragma unroll
    for (int i = 0; i < 4; i++) {
#pragma unroll
        for (int j = 0; j < 4; j++) {
            int r0 = m0 + wm * 64 + i * 16 + (lane >> 2);
            int cc = n0 + wn * 32 + j * 8 + (lane & 3) * 2;
            *(float2*)&out[(size_t)r0 * HH + cc] = make_float2(acc[i][j][0], acc[i][j][1]);
            *(float2*)&out[(size_t)(r0 + 8) * HH + cc] = make_float2(acc[i][j][2], acc[i][j][3]);
        }
    }
}

// ---------------------------------------------------------------------------
// fp16 flash attention (causal), 1-term operands, Q pre-scaled (log2 domain).
// BQ=64, 4 warps, 2 CTAs/SM. Q in registers; exp2 softmax.
// 3-stage KV pipeline, ONE sync per tile. smem: 3 x (K 16K | V 16K) = 96 KB
// ---------------------------------------------------------------------------
#define FQ 64
#define FK 64
#define FTHREADS 128
#define FLASH_SMEM (3 * 32768)

__device__ __forceinline__ uint32_t sw256(int row, int chunk) {
    return (uint32_t)(row * 256 + ((chunk ^ (row & 7)) << 4));
}

__device__ __forceinline__ void flash_load_kv(uint32_t sb, int t, int st,
                                              const __half* Kh, const __half* Vh, int tid) {
    uint32_t base = sb + st * 32768;
    size_t g0 = (size_t)t * FK * HD;
#pragma unroll
    for (int l = 0; l < 8; l++) {
        int idx = tid + l * FTHREADS;    // 0..1023 = 64 rows x 16 chunks
        int row = idx >> 4;
        int c = idx & 15;
        uint32_t off = sw256(row, c);
        size_t go = g0 + (size_t)row * HD + c * 8;
        cp16(base + off, Kh + go);
        cp16(base + 16384 + off, Vh + go);
    }
    asm volatile("cp.async.commit_group;\n");
}

__global__ __launch_bounds__(FTHREADS, 2) void flash_tc_kernel() {
    extern __shared__ char smem_raw[];
    uint32_t sb = (uint32_t)__cvta_generic_to_shared(smem_raw);

    int qt = (int)(gridDim.x - 1 - blockIdx.x);   // big tiles first
    int h = blockIdx.y, b = blockIdx.z;
    int q0 = qt * FQ;
    int kh = h / GROUPS;

    int tid = threadIdx.x, lane = tid & 31, wid = tid >> 5;  // wid 0..3
    int mid = lane >> 3, rin = lane & 7;

    const __half* Qg = g_Qb + ((size_t)(b * NH + h) * SS + q0) * HD;
    const __half* Khg = g_Kb + (size_t)(b * NKV + kh) * SS * HD;
    const __half* Vhg = g_Vb + (size_t)(b * NKV + kh) * SS * HD;

    // ---- Stage Q transiently in buf2; preload KV0, KV1 ----
    uint32_t Qstage = sb + 2 * 32768;
#pragma unroll
    for (int l = 0; l < 8; l++) {
        int idx = tid + l * FTHREADS;
        int row = idx >> 4;
        int c = idx & 15;
        cp16(Qstage + sw256(row, c), Qg + (size_t)row * HD + c * 8);
    }
    asm volatile("cp.async.commit_group;\n");
    const int ntile = qt + 1;
    flash_load_kv(sb, 0, 0, Khg, Vhg, tid);
    if (ntile > 1) {
        flash_load_kv(sb, 1, 1, Khg, Vhg, tid);
        asm volatile("cp.async.wait_group 2;\n");   // pending {Q,KV0,KV1}: Q done
    } else {
        asm volatile("cp.async.wait_group 1;\n");   // pending {Q,KV0}: Q done
    }
    __syncthreads();                              // ALL threads' Q copies visible
    uint32_t qreg[8][4];
#pragma unroll
    for (int kk = 0; kk < 8; kk++) {
        int m_l = wid * 16 + (mid & 1) * 8 + rin;
        int chnk = kk * 2 + (mid >> 1);
        ldsm4(qreg[kk], Qstage + sw256(m_l, chnk));
    }
    // Loop's first barrier (iteration 0) orders all Q ldsm before the tile-2
    // prefetch that overwrites buf2.

    float m_lo = -1e30f, m_hi = -1e30f, l_lo = 0.f, l_hi = 0.f;
    float oacc[16][4];
#pragma unroll
    for (int v = 0; v < 16; v++)
#pragma unroll
        for (int r = 0; r < 4; r++) oacc[v][r] = 0.f;

    const int rlo = q0 + wid * 16 + (lane >> 2);
    const int rhi = rlo + 8;

    for (int t = 0; t < ntile; t++) {
        if (t + 1 < ntile)
            asm volatile("cp.async.wait_group 1;\n");   // tile t ready, t+1 in flight
        else
            asm volatile("cp.async.wait_group 0;\n");
        __syncthreads();   // single barrier per tile: data ready + prev reads done

        if (t + 2 < ntile)
            flash_load_kv(sb, t + 2, (t + 2) % 3, Khg, Vhg, tid);

        uint32_t kb = sb + (t % 3) * 32768;
        uint32_t vb = kb + 16384;

        float sacc[8][4];
#pragma unroll
        for (int n = 0; n < 8; n++)
#pragma unroll
            for (int r = 0; r < 4; r++) sacc[n][r] = 0.f;

#pragma unroll
        for (int kk = 0; kk < 8; kk++) {
#pragma unroll
            for (int j2 = 0; j2 < 4; j2++) {
                uint32_t bh[4];
                int n_l = (j2 * 2 + (mid >> 1)) * 8 + rin;
                int chnk = kk * 2 + (mid & 1);
                ldsm4(bh, kb + sw256(n_l, chnk));
#pragma unroll
                for (int jj = 0; jj < 2; jj++) {
                    int j = j2 * 2 + jj;
                    mma16816h(sacc[j], qreg[kk], bh[jj * 2], bh[jj * 2 + 1]);
                }
            }
        }

        // scores already in exp2 domain (Q pre-scaled); mask only on diag tile
        if (t == ntile - 1) {
            int k0 = t * FK;
#pragma unroll
            for (int n = 0; n < 8; n++) {
                int c0 = k0 + n * 8 + (lane & 3) * 2;
                if (c0 > rlo) sacc[n][0] = -1e30f;
                if (c0 + 1 > rlo) sacc[n][1] = -1e30f;
                if (c0 > rhi) sacc[n][2] = -1e30f;
                if (c0 + 1 > rhi) sacc[n][3] = -1e30f;
            }
        }

        float mx0 = -1e30f, mx1 = -1e30f;
#pragma unroll
        for (int n = 0; n < 8; n++) {
            mx0 = fmaxf(mx0, fmaxf(sacc[n][0], sacc[n][1]));
            mx1 = fmaxf(mx1, fmaxf(sacc[n][2], sacc[n][3]));
        }
        mx0 = fmaxf(mx0, __shfl_xor_sync(0xffffffffu, mx0, 1));
        mx0 = fmaxf(mx0, __shfl_xor_sync(0xffffffffu, mx0, 2));
        mx1 = fmaxf(mx1, __shfl_xor_sync(0xffffffffu, mx1, 1));
        mx1 = fmaxf(mx1, __shfl_xor_sync(0xffffffffu, mx1, 2));
        float newm0 = fmaxf(m_lo, mx0);
        float newm1 = fmaxf(m_hi, mx1);
        float corr0 = exp2f(m_lo - newm0);
        float corr1 = exp2f(m_hi - newm1);
        m_lo = newm0;
        m_hi = newm1;

        float ls0 = 0.f, ls1 = 0.f;
#pragma unroll
        for (int n = 0; n < 8; n++) {
            sacc[n][0] = exp2f(sacc[n][0] - newm0);
            sacc[n][1] = exp2f(sacc[n][1] - newm0);
            sacc[n][2] = exp2f(sacc[n][2] - newm1);
            sacc[n][3] = exp2f(sacc[n][3] - newm1);
            ls0 += sacc[n][0] + sacc[n][1];
            ls1 += sacc[n][2] + sacc[n][3];
        }
        ls0 += __shfl_xor_sync(0xffffffffu, ls0, 1);
        ls0 += __shfl_xor_sync(0xffffffffu, ls0, 2);
        ls1 += __shfl_xor_sync(0xffffffffu, ls1, 1);
        ls1 += __shfl_xor_sync(0xffffffffu, ls1, 2);
        l_lo = l_lo * corr0 + ls0;
        l_hi = l_hi * corr1 + ls1;

#pragma unroll
        for (int v = 0; v < 16; v++) {
            oacc[v][0] *= corr0;
            oacc[v][1] *= corr0;
            oacc[v][2] *= corr1;
            oacc[v][3] *= corr1;
        }

        // ---- O += P V  (P rounded, V 1-term) ----
#pragma unroll
        for (int kk = 0; kk < 4; kk++) {
            uint32_t aph[4];
            aph[0] = pack_f2h2(sacc[2 * kk][0], sacc[2 * kk][1]);
            aph[1] = pack_f2h2(sacc[2 * kk][2], sacc[2 * kk][3]);
            aph[2] = pack_f2h2(sacc[2 * kk + 1][0], sacc[2 * kk + 1][1]);
            aph[3] = pack_f2h2(sacc[2 * kk + 1][2], sacc[2 * kk + 1][3]);
#pragma unroll
            for (int v2 = 0; v2 < 8; v2++) {
                int g = lane >> 3;
                int row = kk * 16 + (g & 1) * 8 + rin;
                int chnk = v2 * 2 + (g >> 1);
                uint32_t vh[4];
                ldsm4t(vh, vb + sw256(row, chnk));
#pragma unroll
                for (int gg = 0; gg < 2; gg++) {
                    int vnt = v2 * 2 + gg;
                    mma16816h(oacc[vnt], aph, vh[gg * 2], vh[gg * 2 + 1]);
                }
            }
        }
        // no trailing sync: next iteration's barrier protects buffer reuse
    }

    // epilogue: normalize, write rounded fp16 for the out-proj
    float inv0 = 1.f / l_lo;
    float inv1 = 1.f / l_hi;
    int row0 = b * SS + q0 + wid * 16 + (lane >> 2);
    int row1 = row0 + 8;
#pragma unroll
    for (int v = 0; v < 16; v++) {
        int col = h * HD + v * 8 + (lane & 3) * 2;
        *(uint32_t*)(g_Ah + (size_t)row0 * KDIM + col) =
            pack_f2h2(oacc[v][0] * inv0, oacc[v][1] * inv0);
        *(uint32_t*)(g_Ah + (size_t)row1 * KDIM + col) =
            pack_f2h2(oacc[v][2] * inv1, oacc[v][3] * inv1);
    }
}

// ---------------------------------------------------------------------------
extern "C" void kernel_launch(void* const* d_in, const int* in_sizes, int n_in,
                              void* d_out, int out_size) {
    const float* X = (const float*)d_in[0];
    const float* Wq = (const float*)d_in[1];
    const float* Wk = (const float*)d_in[2];
    const float* Wv = (const float*)d_in[3];
    const float* Wo = (const float*)d_in[4];
    float* out = (float*)d_out;

    // 0. Round inputs to fp16 + RoPE table (fused)
    split_inputs_kernel<<<(SPLIT_TOTAL + 255) / 256, 256>>>(X, Wq, Wk, Wv, Wo);

    // 1. QKV projections with fused RoPE + head-major fp16 epilogue
    cudaFuncSetAttribute(qkv_gemm_kernel, cudaFuncAttributeMaxDynamicSharedMemorySize,
                         QKV_SMEM);
    qkv_gemm_kernel<<<dim3(24, 32), 256, QKV_SMEM>>>();

    // 2. fp16 flash attention (3-stage KV, one sync/tile, 2 CTAs/SM)
    cudaFuncSetAttribute(flash_tc_kernel, cudaFuncAttributeMaxDynamicSharedMemorySize,
                         FLASH_SMEM);
    flash_tc_kernel<<<dim3(SS / FQ, NH, BB), FTHREADS, FLASH_SMEM>>>();

    // 3. Output projection
    cudaFuncSetAttribute(out_gemm_kernel, cudaFuncAttributeMaxDynamicSharedMemorySize,
                         GEMM_SMEM);
    out_gemm_kernel<<<dim3(16, 32), 256, GEMM_SMEM>>>(out);
}

// round 17
// speedup vs baseline: 11.2826x; 1.0019x over previous
#include <cuda_runtime.h>
#include <cuda_fp16.h>
#include <math.h>
#include <stdint.h>

// Problem constants
#define BB 2
#define SS 2048
#define HH 2048
#define NH 16
#define NKV 4
#define HD 128
#define GROUPS (NH / NKV)        // 4
#define M_TOT (BB * SS)          // 4096
#define QDIM (NH * HD)           // 2048
#define KVDIM (NKV * HD)         // 512
#define KDIM 2048                // GEMM reduction dim

// 1/sqrt(HD) * log2(e): folded into Q at the QKV epilogue
#define SCALE2F (0.08838834764831845f * 1.4426950408889634f)

__device__ float g_cos[SS * 64];
__device__ float g_sin[SS * 64];

// fp16 buffers
__device__ __align__(16) __half g_Xh[M_TOT * KDIM];
__device__ __align__(16) __half g_Wqh[QDIM * KDIM];
__device__ __align__(16) __half g_Wkh[KVDIM * KDIM];
__device__ __align__(16) __half g_Wvh[KVDIM * KDIM];
__device__ __align__(16) __half g_Woh[HH * KDIM];
__device__ __align__(16) __half g_Ah[M_TOT * KDIM];     // flash out (rounded)

// fp16 head-major buffers for flash: [b, h, s, d]
__device__ __align__(16) __half g_Qb[M_TOT * QDIM];     // pre-scaled by SCALE2F
__device__ __align__(16) __half g_Kb[M_TOT * KVDIM];
__device__ __align__(16) __half g_Vb[M_TOT * KVDIM];

// ---------------------------------------------------------------------------
// Helpers
// ---------------------------------------------------------------------------
__device__ __forceinline__ uint32_t pack_f2h2(float a, float b) {
    __half2 t(__float2half_rn(a), __float2half_rn(b));
    return *(uint32_t*)&t;
}
__device__ __forceinline__ void cp16(uint32_t saddr, const void* gaddr) {
    asm volatile("cp.async.cg.shared.global [%0], [%1], 16;\n" ::"r"(saddr), "l"(gaddr));
}
__device__ __forceinline__ void ldsm4(uint32_t* r, uint32_t addr) {
    asm volatile("ldmatrix.sync.aligned.m8n8.x4.shared.b16 {%0,%1,%2,%3}, [%4];\n"
                 : "=r"(r[0]), "=r"(r[1]), "=r"(r[2]), "=r"(r[3]) : "r"(addr));
}
__device__ __forceinline__ void ldsm4t(uint32_t* r, uint32_t addr) {
    asm volatile("ldmatrix.sync.aligned.m8n8.x4.trans.shared.b16 {%0,%1,%2,%3}, [%4];\n"
                 : "=r"(r[0]), "=r"(r[1]), "=r"(r[2]), "=r"(r[3]) : "r"(addr));
}
__device__ __forceinline__ void mma16816h(float* c, const uint32_t* a, uint32_t b0, uint32_t b1) {
    asm volatile("mma.sync.aligned.m16n8k16.row.col.f32.f16.f16.f32 "
                 "{%0,%1,%2,%3}, {%4,%5,%6,%7}, {%8,%9}, {%0,%1,%2,%3};\n"
                 : "+f"(c[0]), "+f"(c[1]), "+f"(c[2]), "+f"(c[3])
                 : "r"(a[0]), "r"(a[1]), "r"(a[2]), "r"(a[3]), "r"(b0), "r"(b1));
}

// ---------------------------------------------------------------------------
// Input split: fp32 -> fp16, 16 floats/thread + RoPE table tail.
// ---------------------------------------------------------------------------
#define N16_X  ((M_TOT * KDIM) / 16)
#define N16_WQ ((QDIM * KDIM) / 16)
#define N16_WKV ((KVDIM * KDIM) / 16)
#define N16_WO ((HH * KDIM) / 16)
#define N16_TOTAL (N16_X + N16_WQ + 2 * N16_WKV + N16_WO)
#define NT_ROPE (SS * 64)
#define SPLIT_TOTAL (N16_TOTAL + NT_ROPE)

__global__ void split_inputs_kernel(const float* __restrict__ X,
                                    const float* __restrict__ Wq,
                                    const float* __restrict__ Wk,
                                    const float* __restrict__ Wv,
                                    const float* __restrict__ Wo) {
    int i = blockIdx.x * blockDim.x + threadIdx.x;
    if (i >= SPLIT_TOTAL) return;
    if (i >= N16_TOTAL) {
        int idx = i - N16_TOTAL;          // rope table entry
        int pos = idx >> 6;
        int d = idx & 63;
        double inv = pow(10000.0, -(double)d / 64.0);
        double ang = (double)pos * inv;
        double sd, cd;
        sincos(ang, &sd, &cd);
        g_cos[idx] = (float)cd;
        g_sin[idx] = (float)sd;
        return;
    }
    const float* src;
    __half* dst;
    int off;
    if (i < N16_X) {
        src = X; dst = g_Xh; off = i;
    } else if (i < N16_X + N16_WQ) {
        src = Wq; dst = g_Wqh; off = i - N16_X;
    } else if (i < N16_X + N16_WQ + N16_WKV) {
        src = Wk; dst = g_Wkh; off = i - N16_X - N16_WQ;
    } else if (i < N16_X + N16_WQ + 2 * N16_WKV) {
        src = Wv; dst = g_Wvh; off = i - N16_X - N16_WQ - N16_WKV;
    } else {
        src = Wo; dst = g_Woh; off = i - N16_X - N16_WQ - 2 * N16_WKV;
    }
    const float4* s4 = (const float4*)(src + (size_t)off * 16);
    float4 v0 = s4[0];
    float4 v1 = s4[1];
    float4 v2 = s4[2];
    float4 v3 = s4[3];
    uint4 o0, o1;
    o0.x = pack_f2h2(v0.x, v0.y);
    o0.y = pack_f2h2(v0.z, v0.w);
    o0.z = pack_f2h2(v1.x, v1.y);
    o0.w = pack_f2h2(v1.z, v1.w);
    o1.x = pack_f2h2(v2.x, v2.y);
    o1.y = pack_f2h2(v2.z, v2.w);
    o1.z = pack_f2h2(v3.x, v3.y);
    o1.w = pack_f2h2(v3.z, v3.w);
    uint4* d4 = (uint4*)(dst + (size_t)off * 16);
    d4[0] = o0;
    d4[1] = o1;
}

// ---------------------------------------------------------------------------
// QKV GEMM: 128x128 tile, K-chunk 64, 3-stage (2 CTAs/SM) — unchanged.
// ---------------------------------------------------------------------------
__device__ __forceinline__ uint32_t sw128b(int row, int chunk) {
    return (uint32_t)(row * 128 + ((chunk ^ (row & 7)) << 4));
}

#define STAGE64 32768
#define QKV_SMEM (3 * STAGE64)           // 96 KB
#define KT64 (KDIM / 64)                 // 32

__device__ __forceinline__ void load_stage64(uint32_t S, int buf,
                                             const __half* __restrict__ A,
                                             const __half* __restrict__ B,
                                             int m0, int n0, int k0, int tid) {
    uint32_t st = S + buf * STAGE64;
#pragma unroll
    for (int l = 0; l < 4; l++) {
        int idx = tid + l * 256;          // 0..1023 = 128 rows x 8 chunks
        int row = idx >> 3;
        int c = idx & 7;
        uint32_t spos = sw128b(row, c);
        cp16(st + spos, A + (size_t)(m0 + row) * KDIM + k0 + c * 8);
        cp16(st + 16384 + spos, B + (size_t)(n0 + row) * KDIM + k0 + c * 8);
    }
    asm volatile("cp.async.commit_group;\n");
}

__global__ __launch_bounds__(256, 2) void qkv_gemm_kernel() {
    extern __shared__ char smem_raw[];
    uint32_t S = (uint32_t)__cvta_generic_to_shared(smem_raw);
    int tid = threadIdx.x;
    int lane = tid & 31, wid = tid >> 5;
    int wm = wid & 1, wn = wid >> 1;
    int mid = lane >> 3, rin = lane & 7;

    int bx = blockIdx.x;
    int m0 = blockIdx.y * 128;

    const __half* A = g_Xh;
    const __half* B;
    __half* dstH;
    int head, nhd;
    bool do_rope;
    float outmul;
    if (bx < 16) {
        B = g_Wqh; dstH = g_Qb; head = bx; nhd = NH; do_rope = true; outmul = SCALE2F;
    } else if (bx < 20) {
        B = g_Wkh; dstH = g_Kb; head = bx - 16; nhd = NKV; do_rope = true; outmul = 1.f;
    } else {
        B = g_Wvh; dstH = g_Vb; head = bx - 20; nhd = NKV; do_rope = false; outmul = 1.f;
    }
    int n0 = head * HD;

    float acc[4][4][4];
#pragma unroll
    for (int i = 0; i < 4; i++)
#pragma unroll
        for (int j = 0; j < 4; j++)
#pragma unroll
            for (int r = 0; r < 4; r++) acc[i][j][r] = 0.f;

    load_stage64(S, 0, A, B, m0, n0, 0, tid);
    load_stage64(S, 1, A, B, m0, n0, 64, tid);
    {
        int cur = 0, pf = 2;
        for (int kt = 0; kt < KT64; kt++) {
            if (kt < KT64 - 1)
                asm volatile("cp.async.wait_group 1;\n");
            else
                asm volatile("cp.async.wait_group 0;\n");
            __syncthreads();
            if (kt + 2 < KT64)
                load_stage64(S, pf, A, B, m0, n0, (kt + 2) * 64, tid);
            uint32_t aB = S + cur * STAGE64;
            uint32_t bB = aB + 16384;
#pragma unroll
            for (int kk = 0; kk < 4; kk++) {
                uint32_t ah[4][4];
#pragma unroll
                for (int i = 0; i < 4; i++) {
                    int m_l = wm * 64 + i * 16 + (mid & 1) * 8 + rin;
                    int chnk = kk * 2 + (mid >> 1);
                    ldsm4(ah[i], aB + sw128b(m_l, chnk));
                }
#pragma unroll
                for (int j2 = 0; j2 < 2; j2++) {
                    uint32_t bh[4];
                    int n_l = wn * 32 + (j2 * 2 + (mid >> 1)) * 8 + rin;
                    int chnk = kk * 2 + (mid & 1);
                    ldsm4(bh, bB + sw128b(n_l, chnk));
#pragma unroll
                    for (int jj = 0; jj < 2; jj++) {
                        int j = j2 * 2 + jj;
#pragma unroll
                        for (int i = 0; i < 4; i++)
                            mma16816h(acc[i][j], ah[i], bh[jj * 2], bh[jj * 2 + 1]);
                    }
                }
            }
            cur = (cur == 2) ? 0 : cur + 1;
            pf = (pf == 2) ? 0 : pf + 1;
        }
    }

    // ---- fused epilogue: stage fp32 tile in smem, rope pairs, fp16 out ----
    __syncthreads();
    float* tile = (float*)smem_raw;
#pragma unroll
    for (int i = 0; i < 4; i++) {
#pragma unroll
        for (int j = 0; j < 4; j++) {
            int r0 = wm * 64 + i * 16 + (lane >> 2);
            int cc = wn * 32 + j * 8 + (lane & 3) * 2;
            *(float2*)&tile[r0 * 132 + cc] = make_float2(acc[i][j][0], acc[i][j][1]);
            *(float2*)&tile[(r0 + 8) * 132 + cc] = make_float2(acc[i][j][2], acc[i][j][3]);
        }
    }
    __syncthreads();

    for (int it = tid; it < 128 * 64; it += 256) {
        int row = it >> 6, d = it & 63;
        int m = m0 + row;
        int s = m & (SS - 1), b = m >> 11;
        float x1 = tile[row * 132 + d];
        float x2 = tile[row * 132 + d + 64];
        float y1 = x1, y2 = x2;
        if (do_rope) {
            float c = g_cos[s * 64 + d], sn = g_sin[s * 64 + d];
            y1 = x1 * c - x2 * sn;
            y2 = x2 * c + x1 * sn;
        }
        y1 *= outmul;
        y2 *= outmul;
        size_t dst = ((size_t)(b * nhd + head) * SS + s) * HD + d;
        dstH[dst] = __float2half_rn(y1);
        dstH[dst + 64] = __float2half_rn(y2);
    }
}

// ---------------------------------------------------------------------------
// Output projection: 64x128 tile, K-chunk 64, 3-stage, 3 CTAs/SM.
// Stage: A 8K | B 16K = 24K; 3 stages = 72K.
// 8 warps: wm 0-1 (32 rows), wn 0-3 (32 cols). acc[2][4][4] = 32 regs.
// ---------------------------------------------------------------------------
#define OSTAGE 24576
#define OUT_SMEM (3 * OSTAGE)            // 72 KB

__device__ __forceinline__ void load_stage_out(uint32_t S, int buf,
                                               int m0, int n0, int k0, int tid) {
    uint32_t st = S + buf * OSTAGE;
#pragma unroll
    for (int l = 0; l < 2; l++) {        // A: 64 rows x 8 chunks = 512
        int idx = tid + l * 256;
        int row = idx >> 3;
        int c = idx & 7;
        cp16(st + sw128b(row, c), g_Ah + (size_t)(m0 + row) * KDIM + k0 + c * 8);
    }
#pragma unroll
    for (int l = 0; l < 4; l++) {        // B: 128 rows x 8 chunks = 1024
        int idx = tid + l * 256;
        int row = idx >> 3;
        int c = idx & 7;
        cp16(st + 8192 + sw128b(row, c), g_Woh + (size_t)(n0 + row) * KDIM + k0 + c * 8);
    }
    asm volatile("cp.async.commit_group;\n");
}

__global__ __launch_bounds__(256, 3) void out_gemm_kernel(float* __restrict__ out) {
    extern __shared__ char smem_raw[];
    uint32_t S = (uint32_t)__cvta_generic_to_shared(smem_raw);
    int tid = threadIdx.x;
    int lane = tid & 31, wid = tid >> 5;
    int wm = wid & 1, wn = wid >> 1;
    int mid = lane >> 3, rin = lane & 7;
    int m0 = blockIdx.y * 64, n0 = blockIdx.x * 128;

    float acc[2][4][4];
#pragma unroll
    for (int i = 0; i < 2; i++)
#pragma unroll
        for (int j = 0; j < 4; j++)
#pragma unroll
            for (int r = 0; r < 4; r++) acc[i][j][r] = 0.f;

    load_stage_out(S, 0, m0, n0, 0, tid);
    load_stage_out(S, 1, m0, n0, 64, tid);
    {
        int cur = 0, pf = 2;
        for (int kt = 0; kt < KT64; kt++) {
            if (kt < KT64 - 1)
                asm volatile("cp.async.wait_group 1;\n");
            else
                asm volatile("cp.async.wait_group 0;\n");
            __syncthreads();
            if (kt + 2 < KT64)
                load_stage_out(S, pf, m0, n0, (kt + 2) * 64, tid);
            uint32_t aB = S + cur * OSTAGE;
            uint32_t bB = aB + 8192;
#pragma unroll
            for (int kk = 0; kk < 4; kk++) {
                uint32_t ah[2][4];
#pragma unroll
                for (int i = 0; i < 2; i++) {
                    int m_l = wm * 32 + i * 16 + (mid & 1) * 8 + rin;
                    int chnk = kk * 2 + (mid >> 1);
                    ldsm4(ah[i], aB + sw128b(m_l, chnk));
                }
#pragma unroll
                for (int j2 = 0; j2 < 2; j2++) {
                    uint32_t bh[4];
                    int n_l = wn * 32 + (j2 * 2 + (mid >> 1)) * 8 + rin;
                    int chnk = kk * 2 + (mid & 1);
                    ldsm4(bh, bB + sw128b(n_l, chnk));
#pragma unroll
                    for (int jj = 0; jj < 2; jj++) {
                        int j = j2 * 2 + jj;
#pragma unroll
                        for (int i = 0; i < 2; i++)
                            mma16816h(acc[i][j], ah[i], bh[jj * 2], bh[jj * 2 + 1]);
                    }
                }
            }
            cur = (cur == 2) ? 0 : cur + 1;
            pf = (pf == 2) ? 0 : pf + 1;
        }
    }

#pragma unroll
    for (int i = 0; i < 2; i++) {
#pragma unroll
        for (int j = 0; j < 4; j++) {
            int r0 = m0 + wm * 32 + i * 16 + (lane >> 2);
            int cc = n0 + wn * 32 + j * 8 + (lane & 3) * 2;
            *(float2*)&out[(size_t)r0 * HH + cc] = make_float2(acc[i][j][0], acc[i][j][1]);
            *(float2*)&out[(size_t)(r0 + 8) * HH + cc] = make_float2(acc[i][j][2], acc[i][j][3]);
        }
    }
}

// ---------------------------------------------------------------------------
// fp16 flash attention (causal), 1-term operands, Q pre-scaled (log2 domain).
// BQ=64, 4 warps, 2 CTAs/SM. Q in registers; exp2 softmax.
// 3-stage KV pipeline, ONE sync per tile. smem: 3 x (K 16K | V 16K) = 96 KB
// ---------------------------------------------------------------------------
#define FQ 64
#define FK 64
#define FTHREADS 128
#define FLASH_SMEM (3 * 32768)

__device__ __forceinline__ uint32_t sw256(int row, int chunk) {
    return (uint32_t)(row * 256 + ((chunk ^ (row & 7)) << 4));
}

__device__ __forceinline__ void flash_load_kv(uint32_t sb, int t, int st,
                                              const __half* Kh, const __half* Vh, int tid) {
    uint32_t base = sb + st * 32768;
    size_t g0 = (size_t)t * FK * HD;
#pragma unroll
    for (int l = 0; l < 8; l++) {
        int idx = tid + l * FTHREADS;    // 0..1023 = 64 rows x 16 chunks
        int row = idx >> 4;
        int c = idx & 15;
        uint32_t off = sw256(row, c);
        size_t go = g0 + (size_t)row * HD + c * 8;
        cp16(base + off, Kh + go);
        cp16(base + 16384 + off, Vh + go);
    }
    asm volatile("cp.async.commit_group;\n");
}

__global__ __launch_bounds__(FTHREADS, 2) void flash_tc_kernel() {
    extern __shared__ char smem_raw[];
    uint32_t sb = (uint32_t)__cvta_generic_to_shared(smem_raw);

    int qt = (int)(gridDim.x - 1 - blockIdx.x);   // big tiles first
    int h = blockIdx.y, b = blockIdx.z;
    int q0 = qt * FQ;
    int kh = h / GROUPS;

    int tid = threadIdx.x, lane = tid & 31, wid = tid >> 5;  // wid 0..3
    int mid = lane >> 3, rin = lane & 7;

    const __half* Qg = g_Qb + ((size_t)(b * NH + h) * SS + q0) * HD;
    const __half* Khg = g_Kb + (size_t)(b * NKV + kh) * SS * HD;
    const __half* Vhg = g_Vb + (size_t)(b * NKV + kh) * SS * HD;

    // ---- Stage Q transiently in buf2; preload KV0, KV1 ----
    uint32_t Qstage = sb + 2 * 32768;
#pragma unroll
    for (int l = 0; l < 8; l++) {
        int idx = tid + l * FTHREADS;
        int row = idx >> 4;
        int c = idx & 15;
        cp16(Qstage + sw256(row, c), Qg + (size_t)row * HD + c * 8);
    }
    asm volatile("cp.async.commit_group;\n");
    const int ntile = qt + 1;
    flash_load_kv(sb, 0, 0, Khg, Vhg, tid);
    if (ntile > 1) {
        flash_load_kv(sb, 1, 1, Khg, Vhg, tid);
        asm volatile("cp.async.wait_group 2;\n");   // pending {Q,KV0,KV1}: Q done
    } else {
        asm volatile("cp.async.wait_group 1;\n");   // pending {Q,KV0}: Q done
    }
    __syncthreads();                              // ALL threads' Q copies visible
    uint32_t qreg[8][4];
#pragma unroll
    for (int kk = 0; kk < 8; kk++) {
        int m_l = wid * 16 + (mid & 1) * 8 + rin;
        int chnk = kk * 2 + (mid >> 1);
        ldsm4(qreg[kk], Qstage + sw256(m_l, chnk));
    }
    // Loop's first barrier (iteration 0) orders all Q ldsm before the tile-2
    // prefetch that overwrites buf2.

    float m_lo = -1e30f, m_hi = -1e30f, l_lo = 0.f, l_hi = 0.f;
    float oacc[16][4];
#pragma unroll
    for (int v = 0; v < 16; v++)
#pragma unroll
        for (int r = 0; r < 4; r++) oacc[v][r] = 0.f;

    const int rlo = q0 + wid * 16 + (lane >> 2);
    const int rhi = rlo + 8;

    for (int t = 0; t < ntile; t++) {
        if (t + 1 < ntile)
            asm volatile("cp.async.wait_group 1;\n");   // tile t ready, t+1 in flight
        else
            asm volatile("cp.async.wait_group 0;\n");
        __syncthreads();   // single barrier per tile: data ready + prev reads done

        if (t + 2 < ntile)
            flash_load_kv(sb, t + 2, (t + 2) % 3, Khg, Vhg, tid);

        uint32_t kb = sb + (t % 3) * 32768;
        uint32_t vb = kb + 16384;

        float sacc[8][4];
#pragma unroll
        for (int n = 0; n < 8; n++)
#pragma unroll
            for (int r = 0; r < 4; r++) sacc[n][r] = 0.f;

#pragma unroll
        for (int kk = 0; kk < 8; kk++) {
#pragma unroll
            for (int j2 = 0; j2 < 4; j2++) {
                uint32_t bh[4];
                int n_l = (j2 * 2 + (mid >> 1)) * 8 + rin;
                int chnk = kk * 2 + (mid & 1);
                ldsm4(bh, kb + sw256(n_l, chnk));
#pragma unroll
                for (int jj = 0; jj < 2; jj++) {
                    int j = j2 * 2 + jj;
                    mma16816h(sacc[j], qreg[kk], bh[jj * 2], bh[jj * 2 + 1]);
                }
            }
        }

        // scores already in exp2 domain (Q pre-scaled); mask only on diag tile
        if (t == ntile - 1) {
            int k0 = t * FK;
#pragma unroll
            for (int n = 0; n < 8; n++) {
                int c0 = k0 + n * 8 + (lane & 3) * 2;
                if (c0 > rlo) sacc[n][0] = -1e30f;
                if (c0 + 1 > rlo) sacc[n][1] = -1e30f;
                if (c0 > rhi) sacc[n][2] = -1e30f;
                if (c0 + 1 > rhi) sacc[n][3] = -1e30f;
            }
        }

        float mx0 = -1e30f, mx1 = -1e30f;
#pragma unroll
        for (int n = 0; n < 8; n++) {
            mx0 = fmaxf(mx0, fmaxf(sacc[n][0], sacc[n][1]));
            mx1 = fmaxf(mx1, fmaxf(sacc[n][2], sacc[n][3]));
        }
        mx0 = fmaxf(mx0, __shfl_xor_sync(0xffffffffu, mx0, 1));
        mx0 = fmaxf(mx0, __shfl_xor_sync(0xffffffffu, mx0, 2));
        mx1 = fmaxf(mx1, __shfl_xor_sync(0xffffffffu, mx1, 1));
        mx1 = fmaxf(mx1, __shfl_xor_sync(0xffffffffu, mx1, 2));
        float newm0 = fmaxf(m_lo, mx0);
        float newm1 = fmaxf(m_hi, mx1);
        float corr0 = exp2f(m_lo - newm0);
        float corr1 = exp2f(m_hi - newm1);
        m_lo = newm0;
        m_hi = newm1;

        float ls0 = 0.f, ls1 = 0.f;
#pragma unroll
        for (int n = 0; n < 8; n++) {
            sacc[n][0] = exp2f(sacc[n][0] - newm0);
            sacc[n][1] = exp2f(sacc[n][1] - newm0);
            sacc[n][2] = exp2f(sacc[n][2] - newm1);
            sacc[n][3] = exp2f(sacc[n][3] - newm1);
            ls0 += sacc[n][0] + sacc[n][1];
            ls1 += sacc[n][2] + sacc[n][3];
        }
        ls0 += __shfl_xor_sync(0xffffffffu, ls0, 1);
        ls0 += __shfl_xor_sync(0xffffffffu, ls0, 2);
        ls1 += __shfl_xor_sync(0xffffffffu, ls1, 1);
        ls1 += __shfl_xor_sync(0xffffffffu, ls1, 2);
        l_lo = l_lo * corr0 + ls0;
        l_hi = l_hi * corr1 + ls1;

#pragma unroll
        for (int v = 0; v < 16; v++) {
            oacc[v][0] *= corr0;
            oacc[v][1] *= corr0;
            oacc[v][2] *= corr1;
            oacc[v][3] *= corr1;
        }

        // ---- O += P V  (P rounded, V 1-term) ----
#pragma unroll
        for (int kk = 0; kk < 4; kk++) {
            uint32_t aph[4];
            aph[0] = pack_f2h2(sacc[2 * kk][0], sacc[2 * kk][1]);
            aph[1] = pack_f2h2(sacc[2 * kk][2], sacc[2 * kk][3]);
            aph[2] = pack_f2h2(sacc[2 * kk + 1][0], sacc[2 * kk + 1][1]);
            aph[3] = pack_f2h2(sacc[2 * kk + 1][2], sacc[2 * kk + 1][3]);
#pragma unroll
            for (int v2 = 0; v2 < 8; v2++) {
                int g = lane >> 3;
                int row = kk * 16 + (g & 1) * 8 + rin;
                int chnk = v2 * 2 + (g >> 1);
                uint32_t vh[4];
                ldsm4t(vh, vb + sw256(row, chnk));
#pragma unroll
                for (int gg = 0; gg < 2; gg++) {
                    int vnt = v2 * 2 + gg;
                    mma16816h(oacc[vnt], aph, vh[gg * 2], vh[gg * 2 + 1]);
                }
            }
        }
        // no trailing sync: next iteration's barrier protects buffer reuse
    }

    // epilogue: normalize, write rounded fp16 for the out-proj
    float inv0 = 1.f / l_lo;
    float inv1 = 1.f / l_hi;
    int row0 = b * SS + q0 + wid * 16 + (lane >> 2);
    int row1 = row0 + 8;
#pragma unroll
    for (int v = 0; v < 16; v++) {
        int col = h * HD + v * 8 + (lane & 3) * 2;
        *(uint32_t*)(g_Ah + (size_t)row0 * KDIM + col) =
            pack_f2h2(oacc[v][0] * inv0, oacc[v][1] * inv0);
        *(uint32_t*)(g_Ah + (size_t)row1 * KDIM + col) =
            pack_f2h2(oacc[v][2] * inv1, oacc[v][3] * inv1);
    }
}

// ---------------------------------------------------------------------------
extern "C" void kernel_launch(void* const* d_in, const int* in_sizes, int n_in,
                              void* d_out, int out_size) {
    const float* X = (const float*)d_in[0];
    const float* Wq = (const float*)d_in[1];
    const float* Wk = (const float*)d_in[2];
    const float* Wv = (const float*)d_in[3];
    const float* Wo = (const float*)d_in[4];
    float* out = (float*)d_out;

    // 0. Round inputs to fp16 + RoPE table (fused)
    split_inputs_kernel<<<(SPLIT_TOTAL + 255) / 256, 256>>>(X, Wq, Wk, Wv, Wo);

    // 1. QKV projections with fused RoPE + head-major fp16 epilogue
    cudaFuncSetAttribute(qkv_gemm_kernel, cudaFuncAttributeMaxDynamicSharedMemorySize,
                         QKV_SMEM);
    qkv_gemm_kernel<<<dim3(24, 32), 256, QKV_SMEM>>>();

    // 2. fp16 flash attention (3-stage KV, one sync/tile, 2 CTAs/SM)
    cudaFuncSetAttribute(flash_tc_kernel, cudaFuncAttributeMaxDynamicSharedMemorySize,
                         FLASH_SMEM);
    flash_tc_kernel<<<dim3(SS / FQ, NH, BB), FTHREADS, FLASH_SMEM>>>();

    // 3. Output projection (64x128 tiles, 3 CTAs/SM)
    cudaFuncSetAttribute(out_gemm_kernel, cudaFuncAttributeMaxDynamicSharedMemorySize,
                         OUT_SMEM);
    out_gemm_kernel<<<dim3(16, 64), 256, OUT_SMEM>>>(out);
}